// round 1
// baseline (speedup 1.0000x reference)
#include <cuda_runtime.h>
#include <math.h>

// Problem constants
#define BB 2
#define TT 2048
#define EE 768
#define NH 12
#define HD 64
#define FFD 3072
#define MROWS (BB * TT)   // 4096
#define LN_EPS 1e-5f

// ---------------------------------------------------------------------------
// Scratch (no allocation allowed -> __device__ globals)
// ---------------------------------------------------------------------------
__device__ float g_q[MROWS * EE];
__device__ float g_k[MROWS * EE];
__device__ float g_v[MROWS * EE];
__device__ float g_attn[MROWS * EE];
__device__ float g_tmp[MROWS * EE];
__device__ float g_x1[MROWS * EE];
__device__ float g_h[MROWS * FFD];

// ---------------------------------------------------------------------------
// SGEMM: C[M,N] = A[M,K] @ B[N,K]^T (+bias, +relu)
// A row-major [M,K], B row-major [N,K] (torch Linear weight layout).
// BM=BN=128, BK=16, 256 threads, 8x8 per thread.
// Requires M%128==0, N%128==0, K%16==0 (true for all shapes here).
// ---------------------------------------------------------------------------
template <bool HAS_BIAS, bool RELU>
__global__ __launch_bounds__(256)
void sgemm_kernel(const float* __restrict__ A, const float* __restrict__ B,
                  const float* __restrict__ bias, float* __restrict__ C,
                  int M, int N, int K) {
    __shared__ float As[16][129];
    __shared__ float Bs[16][129];

    const int tid = threadIdx.x;
    const int tm  = tid >> 4;          // 0..15
    const int tn  = tid & 15;          // 0..15
    const int brow = blockIdx.y * 128; // M offset
    const int bcol = blockIdx.x * 128; // N offset

    float acc[8][8];
#pragma unroll
    for (int i = 0; i < 8; i++)
#pragma unroll
        for (int j = 0; j < 8; j++) acc[i][j] = 0.0f;

    const int nkt = K >> 4;
    for (int kt = 0; kt < nkt; kt++) {
        // Load A tile 128x16 and B tile 128x16 (each 512 float4, 2 per thread)
#pragma unroll
        for (int i = 0; i < 2; i++) {
            int idx = tid + i * 256;          // 0..511
            int row = idx >> 2;               // 0..127
            int kc  = (idx & 3) << 2;         // 0,4,8,12
            float4 va = *reinterpret_cast<const float4*>(
                A + (size_t)(brow + row) * K + kt * 16 + kc);
            As[kc + 0][row] = va.x;
            As[kc + 1][row] = va.y;
            As[kc + 2][row] = va.z;
            As[kc + 3][row] = va.w;
            float4 vb = *reinterpret_cast<const float4*>(
                B + (size_t)(bcol + row) * K + kt * 16 + kc);
            Bs[kc + 0][row] = vb.x;
            Bs[kc + 1][row] = vb.y;
            Bs[kc + 2][row] = vb.z;
            Bs[kc + 3][row] = vb.w;
        }
        __syncthreads();

#pragma unroll
        for (int k = 0; k < 16; k++) {
            float a[8], b[8];
#pragma unroll
            for (int i = 0; i < 8; i++) a[i] = As[k][tm * 8 + i];
#pragma unroll
            for (int j = 0; j < 8; j++) b[j] = Bs[k][tn * 8 + j];
#pragma unroll
            for (int i = 0; i < 8; i++)
#pragma unroll
                for (int j = 0; j < 8; j++) acc[i][j] = fmaf(a[i], b[j], acc[i][j]);
        }
        __syncthreads();
    }

    // Epilogue
#pragma unroll
    for (int i = 0; i < 8; i++) {
        int r = brow + tm * 8 + i;
        float* crow = C + (size_t)r * N + bcol + tn * 8;
#pragma unroll
        for (int j = 0; j < 8; j++) {
            float vv = acc[i][j];
            if (HAS_BIAS) vv += bias[bcol + tn * 8 + j];
            if (RELU) vv = fmaxf(vv, 0.0f);
            crow[j] = vv;
        }
    }
}

// ---------------------------------------------------------------------------
// Fused causal flash attention.
// q/k/v: [B,T,H,HD] row-major as [(b*T+t)*E + h*HD + d]. o: same layout.
// Grid: (T/64, B*H). 128 threads.
// Q tile = 64 rows, K/V tiles = 32 keys, online softmax.
// Thread tiling: tm = tid/8 (16), tn = tid%8 (8).
//   GEMM1 (S=Q K^T, 64x32): thread owns rows tm*4+0..3, cols tn*4+0..3.
//   GEMM2 (O+=P V, 64x64): thread owns rows tm*4+0..3, cols tn*8+0..7.
// ---------------------------------------------------------------------------
__global__ __launch_bounds__(128)
void attn_kernel(const float* __restrict__ q, const float* __restrict__ k,
                 const float* __restrict__ v, float* __restrict__ o) {
    __shared__ float Qs[64][65];
    __shared__ float Ks[32][65];
    __shared__ float Vs[32][65];
    __shared__ float Ps[64][33];

    const int qt = blockIdx.x;            // query tile
    const int bh = blockIdx.y;            // b*H + h
    const int b  = bh / NH;
    const int h  = bh % NH;
    const int tid = threadIdx.x;
    const int tm = tid >> 3;              // 0..15
    const int tn = tid & 7;               // 0..7

    // Load Q tile 64x64 (1024 float4, 8 per thread)
#pragma unroll
    for (int i = 0; i < 8; i++) {
        int idx = tid + i * 128;          // 0..1023
        int row = idx >> 4;               // 0..63
        int dc  = (idx & 15) << 2;        // 0..60
        float4 vq = *reinterpret_cast<const float4*>(
            q + ((size_t)(b * TT + qt * 64 + row) * EE + h * HD + dc));
        Qs[row][dc + 0] = vq.x;
        Qs[row][dc + 1] = vq.y;
        Qs[row][dc + 2] = vq.z;
        Qs[row][dc + 3] = vq.w;
    }

    float o_acc[4][8];
#pragma unroll
    for (int i = 0; i < 4; i++)
#pragma unroll
        for (int j = 0; j < 8; j++) o_acc[i][j] = 0.0f;
    float m_i[4], l_i[4];
#pragma unroll
    for (int i = 0; i < 4; i++) { m_i[i] = -1e30f; l_i[i] = 0.0f; }

    const float scale = 0.125f;           // 1/sqrt(64)
    const int nkt = 2 * qt + 2;           // key tiles of 32 up to (qt+1)*64

    for (int kt = 0; kt < nkt; kt++) {
        const int s0 = kt * 32;
        // Load K,V tiles 32x64 (512 float4 each, 4 per thread each)
        __syncthreads();
#pragma unroll
        for (int i = 0; i < 4; i++) {
            int idx = tid + i * 128;      // 0..511
            int row = idx >> 4;           // 0..31
            int dc  = (idx & 15) << 2;
            size_t gk = ((size_t)(b * TT + s0 + row) * EE + h * HD + dc);
            float4 vk = *reinterpret_cast<const float4*>(k + gk);
            Ks[row][dc + 0] = vk.x; Ks[row][dc + 1] = vk.y;
            Ks[row][dc + 2] = vk.z; Ks[row][dc + 3] = vk.w;
            float4 vv = *reinterpret_cast<const float4*>(v + gk);
            Vs[row][dc + 0] = vv.x; Vs[row][dc + 1] = vv.y;
            Vs[row][dc + 2] = vv.z; Vs[row][dc + 3] = vv.w;
        }
        __syncthreads();

        // S = Q K^T, 64x32, thread computes 4x4
        float s[4][4];
#pragma unroll
        for (int i = 0; i < 4; i++)
#pragma unroll
            for (int j = 0; j < 4; j++) s[i][j] = 0.0f;
#pragma unroll 4
        for (int kd = 0; kd < 64; kd++) {
            float a[4], bb[4];
#pragma unroll
            for (int i = 0; i < 4; i++) a[i] = Qs[tm * 4 + i][kd];
#pragma unroll
            for (int j = 0; j < 4; j++) bb[j] = Ks[tn * 4 + j][kd];
#pragma unroll
            for (int i = 0; i < 4; i++)
#pragma unroll
                for (int j = 0; j < 4; j++) s[i][j] = fmaf(a[i], bb[j], s[i][j]);
        }

        // scale + causal mask (only the last two tiles can be masked)
        const bool domask = (kt >= 2 * qt);
#pragma unroll
        for (int i = 0; i < 4; i++) {
            int qr = qt * 64 + tm * 4 + i;
#pragma unroll
            for (int j = 0; j < 4; j++) {
                int kc = s0 + tn * 4 + j;
                float vv = s[i][j] * scale;
                if (domask && kc > qr) vv = -1e30f;
                s[i][j] = vv;
            }
        }

        // online softmax: row stats over 8 threads (tn in low 3 bits of lane)
        float alpha[4];
#pragma unroll
        for (int i = 0; i < 4; i++) {
            float mx = s[i][0];
#pragma unroll
            for (int j = 1; j < 4; j++) mx = fmaxf(mx, s[i][j]);
            mx = fmaxf(mx, __shfl_xor_sync(0xffffffffu, mx, 1));
            mx = fmaxf(mx, __shfl_xor_sync(0xffffffffu, mx, 2));
            mx = fmaxf(mx, __shfl_xor_sync(0xffffffffu, mx, 4));
            float m_new = fmaxf(m_i[i], mx);
            float rs = 0.0f;
#pragma unroll
            for (int j = 0; j < 4; j++) {
                float p = __expf(s[i][j] - m_new);
                Ps[tm * 4 + i][tn * 4 + j] = p;
                rs += p;
            }
            rs += __shfl_xor_sync(0xffffffffu, rs, 1);
            rs += __shfl_xor_sync(0xffffffffu, rs, 2);
            rs += __shfl_xor_sync(0xffffffffu, rs, 4);
            alpha[i] = __expf(m_i[i] - m_new);
            l_i[i] = l_i[i] * alpha[i] + rs;
            m_i[i] = m_new;
        }
#pragma unroll
        for (int i = 0; i < 4; i++)
#pragma unroll
            for (int j = 0; j < 8; j++) o_acc[i][j] *= alpha[i];
        __syncthreads();

        // O += P @ V, 64x64x32, thread computes 4x8
#pragma unroll 4
        for (int kc = 0; kc < 32; kc++) {
            float a[4], bb[8];
#pragma unroll
            for (int i = 0; i < 4; i++) a[i] = Ps[tm * 4 + i][kc];
#pragma unroll
            for (int j = 0; j < 8; j++) bb[j] = Vs[kc][tn * 8 + j];
#pragma unroll
            for (int i = 0; i < 4; i++)
#pragma unroll
                for (int j = 0; j < 8; j++)
                    o_acc[i][j] = fmaf(a[i], bb[j], o_acc[i][j]);
        }
    }

    // write out O / l
#pragma unroll
    for (int i = 0; i < 4; i++) {
        int qr = qt * 64 + tm * 4 + i;
        float inv_l = 1.0f / l_i[i];
        float* orow = o + ((size_t)(b * TT + qr) * EE + h * HD + tn * 8);
#pragma unroll
        for (int j = 0; j < 8; j++) orow[j] = o_acc[i][j] * inv_l;
    }
}

// ---------------------------------------------------------------------------
// Fused residual-add + LayerNorm over E=768. One block per row, 256 threads.
// out = LN(a + res) * g + b
// ---------------------------------------------------------------------------
__global__ __launch_bounds__(256)
void ln_kernel(const float* __restrict__ a, const float* __restrict__ res,
               const float* __restrict__ g, const float* __restrict__ bt,
               float* __restrict__ out) {
    const int row = blockIdx.x;
    const float* pa = a + (size_t)row * EE;
    const float* pr = res + (size_t)row * EE;
    float vloc[3];
    float s = 0.0f, ss = 0.0f;
#pragma unroll
    for (int i = 0; i < 3; i++) {
        int c = threadIdx.x + i * 256;
        float vv = pa[c] + pr[c];
        vloc[i] = vv;
        s += vv;
        ss += vv * vv;
    }
#pragma unroll
    for (int off = 16; off > 0; off >>= 1) {
        s  += __shfl_xor_sync(0xffffffffu, s, off);
        ss += __shfl_xor_sync(0xffffffffu, ss, off);
    }
    __shared__ float sred[16];
    __shared__ float smu, srstd;
    int w = threadIdx.x >> 5, lane = threadIdx.x & 31;
    if (lane == 0) { sred[w] = s; sred[8 + w] = ss; }
    __syncthreads();
    if (threadIdx.x == 0) {
        float S = 0.0f, SS = 0.0f;
#pragma unroll
        for (int i = 0; i < 8; i++) { S += sred[i]; SS += sred[8 + i]; }
        float mu = S * (1.0f / EE);
        float var = SS * (1.0f / EE) - mu * mu;
        smu = mu;
        srstd = rsqrtf(var + LN_EPS);
    }
    __syncthreads();
    float mu = smu, rstd = srstd;
    float* po = out + (size_t)row * EE;
#pragma unroll
    for (int i = 0; i < 3; i++) {
        int c = threadIdx.x + i * 256;
        po[c] = (vloc[i] - mu) * rstd * g[c] + bt[c];
    }
}

// ---------------------------------------------------------------------------
// Launch
// ---------------------------------------------------------------------------
extern "C" void kernel_launch(void* const* d_in, const int* in_sizes, int n_in,
                              void* d_out, int out_size) {
    const float* x      = (const float*)d_in[0];
    const float* Wq     = (const float*)d_in[1];
    const float* Wk     = (const float*)d_in[2];
    const float* Wv     = (const float*)d_in[3];
    const float* proj_w = (const float*)d_in[4];
    const float* proj_b = (const float*)d_in[5];
    const float* ln1_g  = (const float*)d_in[6];
    const float* ln1_b  = (const float*)d_in[7];
    const float* w1     = (const float*)d_in[8];
    const float* b1     = (const float*)d_in[9];
    const float* w2     = (const float*)d_in[10];
    const float* b2     = (const float*)d_in[11];
    const float* ln2_g  = (const float*)d_in[12];
    const float* ln2_b  = (const float*)d_in[13];
    float* out = (float*)d_out;

    float *q, *k, *v, *attn, *tmp, *x1, *hbuf;
    cudaGetSymbolAddress((void**)&q,    g_q);
    cudaGetSymbolAddress((void**)&k,    g_k);
    cudaGetSymbolAddress((void**)&v,    g_v);
    cudaGetSymbolAddress((void**)&attn, g_attn);
    cudaGetSymbolAddress((void**)&tmp,  g_tmp);
    cudaGetSymbolAddress((void**)&x1,   g_x1);
    cudaGetSymbolAddress((void**)&hbuf, g_h);

    dim3 gE(EE / 128, MROWS / 128);     // (6, 32)
    dim3 gF(FFD / 128, MROWS / 128);    // (24, 32)

    // QKV projections (no bias in reference)
    sgemm_kernel<false, false><<<gE, 256>>>(x, Wq, nullptr, q, MROWS, EE, EE);
    sgemm_kernel<false, false><<<gE, 256>>>(x, Wk, nullptr, k, MROWS, EE, EE);
    sgemm_kernel<false, false><<<gE, 256>>>(x, Wv, nullptr, v, MROWS, EE, EE);

    // Causal attention
    attn_kernel<<<dim3(TT / 64, BB * NH), 128>>>(q, k, v, attn);

    // Output projection + bias
    sgemm_kernel<true, false><<<gE, 256>>>(attn, proj_w, proj_b, tmp, MROWS, EE, EE);
    // x1 = LN(tmp + x)
    ln_kernel<<<MROWS, 256>>>(tmp, x, ln1_g, ln1_b, x1);

    // FFN
    sgemm_kernel<true, true><<<gF, 256>>>(x1, w1, b1, hbuf, MROWS, FFD, EE);
    sgemm_kernel<true, false><<<gE, 256>>>(hbuf, w2, b2, tmp, MROWS, EE, FFD);
    // out = LN(tmp + x1)
    ln_kernel<<<MROWS, 256>>>(tmp, x1, ln2_g, ln2_b, out);
}

// round 2
// speedup vs baseline: 2.2608x; 2.2608x over previous
#include <cuda_runtime.h>
#include <math.h>

// Problem constants
#define BB 2
#define TT 2048
#define EE 768
#define NH 12
#define HD 64
#define FFD 3072
#define MROWS (BB * TT)   // 4096
#define LN_EPS 1e-5f

// ---------------------------------------------------------------------------
// Scratch (no allocation allowed -> __device__ globals)
// ---------------------------------------------------------------------------
__device__ float g_q[MROWS * EE];
__device__ float g_k[MROWS * EE];
__device__ float g_v[MROWS * EE];
__device__ float g_attn[MROWS * EE];
__device__ float g_tmp[MROWS * EE];
__device__ float g_x1[MROWS * EE];
__device__ float g_h[MROWS * FFD];

// ---------------------------------------------------------------------------
// Helpers: tf32 convert, mma, cp.async
// ---------------------------------------------------------------------------
__device__ __forceinline__ unsigned f2tf32(float f) {
    unsigned u;
    asm("cvt.rna.tf32.f32 %0, %1;" : "=r"(u) : "f"(f));
    return u;
}

__device__ __forceinline__ void mma_tf32(float* c, const unsigned* a, const unsigned* b) {
    asm volatile(
        "mma.sync.aligned.m16n8k8.row.col.f32.tf32.tf32.f32 "
        "{%0,%1,%2,%3}, {%4,%5,%6,%7}, {%8,%9}, {%0,%1,%2,%3};\n"
        : "+f"(c[0]), "+f"(c[1]), "+f"(c[2]), "+f"(c[3])
        : "r"(a[0]), "r"(a[1]), "r"(a[2]), "r"(a[3]), "r"(b[0]), "r"(b[1]));
}

__device__ __forceinline__ void cp16(void* s, const void* g) {
    unsigned sa = (unsigned)__cvta_generic_to_shared(s);
    asm volatile("cp.async.cg.shared.global [%0], [%1], 16;\n" :: "r"(sa), "l"(g));
}
__device__ __forceinline__ void cp_commit() {
    asm volatile("cp.async.commit_group;\n");
}
__device__ __forceinline__ void cp_wait1() {
    asm volatile("cp.async.wait_group 1;\n");
}

// ---------------------------------------------------------------------------
// TF32 tensor-core GEMM: C[M,N] = A[M,K] @ B[N,K]^T (+bias, +relu)
// BM=BN=128, BK=16, 256 threads (8 warps as 4x2, 32x64 per warp).
// cp.async double-buffered SMEM, pad-20 rows (conflict-free fragment reads).
// NZ=3: blockIdx.z selects among (B0,C0)/(B1,C1)/(B2,C2)  [fused QKV]
// ---------------------------------------------------------------------------
#define PAD 20
#define TILE_F (128 * PAD)

template <bool HAS_BIAS, bool RELU, int NZ>
__global__ __launch_bounds__(256)
void tgemm_kernel(const float* __restrict__ A,
                  const float* __restrict__ B0, const float* __restrict__ B1,
                  const float* __restrict__ B2,
                  const float* __restrict__ bias,
                  float* __restrict__ C0, float* __restrict__ C1, float* __restrict__ C2,
                  int M, int N, int K) {
    const float* B = B0;
    float* C = C0;
    if (NZ == 3) {
        if (blockIdx.z == 1) { B = B1; C = C1; }
        else if (blockIdx.z == 2) { B = B2; C = C2; }
    }

    __shared__ float As[2][TILE_F];
    __shared__ float Bs[2][TILE_F];

    const int tid  = threadIdx.x;
    const int lane = tid & 31;
    const int warp = tid >> 5;
    const int wm   = warp >> 1;         // 0..3
    const int wn   = warp & 1;          // 0..1
    const int ln4  = lane >> 2;         // 0..7
    const int lm4  = lane & 3;          // 0..3
    const int brow = blockIdx.y * 128;
    const int bcol = blockIdx.x * 128;

    // load mapping: thread handles rows r0 and r0+64, fixed 16B k-chunk
    const int r0 = tid >> 2;            // 0..63
    const int kc = (tid & 3) << 2;      // 0,4,8,12

    float acc[2][8][4];
#pragma unroll
    for (int mt = 0; mt < 2; mt++)
#pragma unroll
        for (int nt = 0; nt < 8; nt++)
#pragma unroll
            for (int i = 0; i < 4; i++) acc[mt][nt][i] = 0.0f;

    const int nkt = K >> 4;

    // prologue: stage 0
    {
        const float* ga = A + (size_t)(brow + r0) * K + kc;
        cp16(&As[0][r0 * PAD + kc], ga);
        cp16(&As[0][(r0 + 64) * PAD + kc], ga + (size_t)64 * K);
        const float* gb = B + (size_t)(bcol + r0) * K + kc;
        cp16(&Bs[0][r0 * PAD + kc], gb);
        cp16(&Bs[0][(r0 + 64) * PAD + kc], gb + (size_t)64 * K);
        cp_commit();
    }

    for (int kt = 0; kt < nkt; kt++) {
        const int st = kt & 1;
        if (kt + 1 < nkt) {
            const int st2 = st ^ 1;
            const float* ga = A + (size_t)(brow + r0) * K + (kt + 1) * 16 + kc;
            cp16(&As[st2][r0 * PAD + kc], ga);
            cp16(&As[st2][(r0 + 64) * PAD + kc], ga + (size_t)64 * K);
            const float* gb = B + (size_t)(bcol + r0) * K + (kt + 1) * 16 + kc;
            cp16(&Bs[st2][r0 * PAD + kc], gb);
            cp16(&Bs[st2][(r0 + 64) * PAD + kc], gb + (size_t)64 * K);
        }
        cp_commit();
        cp_wait1();
        __syncthreads();

        const float* as = As[st];
        const float* bs = Bs[st];
#pragma unroll
        for (int ks = 0; ks < 2; ks++) {
            const int k0 = ks * 8;
            unsigned af[2][4], bf[8][2];
#pragma unroll
            for (int mt = 0; mt < 2; mt++) {
                const int rb = wm * 32 + mt * 16;
                af[mt][0] = f2tf32(as[(rb + ln4) * PAD + k0 + lm4]);
                af[mt][1] = f2tf32(as[(rb + ln4 + 8) * PAD + k0 + lm4]);
                af[mt][2] = f2tf32(as[(rb + ln4) * PAD + k0 + lm4 + 4]);
                af[mt][3] = f2tf32(as[(rb + ln4 + 8) * PAD + k0 + lm4 + 4]);
            }
#pragma unroll
            for (int nt = 0; nt < 8; nt++) {
                const int cb = wn * 64 + nt * 8;
                bf[nt][0] = f2tf32(bs[(cb + ln4) * PAD + k0 + lm4]);
                bf[nt][1] = f2tf32(bs[(cb + ln4) * PAD + k0 + lm4 + 4]);
            }
#pragma unroll
            for (int mt = 0; mt < 2; mt++)
#pragma unroll
                for (int nt = 0; nt < 8; nt++)
                    mma_tf32(acc[mt][nt], af[mt], bf[nt]);
        }
        __syncthreads();
    }

    // epilogue
#pragma unroll
    for (int mt = 0; mt < 2; mt++) {
        const int r = brow + wm * 32 + mt * 16 + ln4;
#pragma unroll
        for (int nt = 0; nt < 8; nt++) {
            const int col = bcol + wn * 64 + nt * 8 + lm4 * 2;
            float2 v0 = make_float2(acc[mt][nt][0], acc[mt][nt][1]);
            float2 v1 = make_float2(acc[mt][nt][2], acc[mt][nt][3]);
            if (HAS_BIAS) {
                float bx = bias[col], by = bias[col + 1];
                v0.x += bx; v0.y += by;
                v1.x += bx; v1.y += by;
            }
            if (RELU) {
                v0.x = fmaxf(v0.x, 0.0f); v0.y = fmaxf(v0.y, 0.0f);
                v1.x = fmaxf(v1.x, 0.0f); v1.y = fmaxf(v1.y, 0.0f);
            }
            *reinterpret_cast<float2*>(C + (size_t)r * N + col) = v0;
            *reinterpret_cast<float2*>(C + (size_t)(r + 8) * N + col) = v1;
        }
    }
}

// ---------------------------------------------------------------------------
// Fused causal flash attention (unchanged from R1).
// ---------------------------------------------------------------------------
__global__ __launch_bounds__(128)
void attn_kernel(const float* __restrict__ q, const float* __restrict__ k,
                 const float* __restrict__ v, float* __restrict__ o) {
    __shared__ float Qs[64][65];
    __shared__ float Ks[32][65];
    __shared__ float Vs[32][65];
    __shared__ float Ps[64][33];

    const int qt = blockIdx.x;
    const int bh = blockIdx.y;
    const int b  = bh / NH;
    const int h  = bh % NH;
    const int tid = threadIdx.x;
    const int tm = tid >> 3;
    const int tn = tid & 7;

#pragma unroll
    for (int i = 0; i < 8; i++) {
        int idx = tid + i * 128;
        int row = idx >> 4;
        int dc  = (idx & 15) << 2;
        float4 vq = *reinterpret_cast<const float4*>(
            q + ((size_t)(b * TT + qt * 64 + row) * EE + h * HD + dc));
        Qs[row][dc + 0] = vq.x;
        Qs[row][dc + 1] = vq.y;
        Qs[row][dc + 2] = vq.z;
        Qs[row][dc + 3] = vq.w;
    }

    float o_acc[4][8];
#pragma unroll
    for (int i = 0; i < 4; i++)
#pragma unroll
        for (int j = 0; j < 8; j++) o_acc[i][j] = 0.0f;
    float m_i[4], l_i[4];
#pragma unroll
    for (int i = 0; i < 4; i++) { m_i[i] = -1e30f; l_i[i] = 0.0f; }

    const float scale = 0.125f;
    const int nkt = 2 * qt + 2;

    for (int kt = 0; kt < nkt; kt++) {
        const int s0 = kt * 32;
        __syncthreads();
#pragma unroll
        for (int i = 0; i < 4; i++) {
            int idx = tid + i * 128;
            int row = idx >> 4;
            int dc  = (idx & 15) << 2;
            size_t gk = ((size_t)(b * TT + s0 + row) * EE + h * HD + dc);
            float4 vk = *reinterpret_cast<const float4*>(k + gk);
            Ks[row][dc + 0] = vk.x; Ks[row][dc + 1] = vk.y;
            Ks[row][dc + 2] = vk.z; Ks[row][dc + 3] = vk.w;
            float4 vv = *reinterpret_cast<const float4*>(v + gk);
            Vs[row][dc + 0] = vv.x; Vs[row][dc + 1] = vv.y;
            Vs[row][dc + 2] = vv.z; Vs[row][dc + 3] = vv.w;
        }
        __syncthreads();

        float s[4][4];
#pragma unroll
        for (int i = 0; i < 4; i++)
#pragma unroll
            for (int j = 0; j < 4; j++) s[i][j] = 0.0f;
#pragma unroll 4
        for (int kd = 0; kd < 64; kd++) {
            float a[4], bb[4];
#pragma unroll
            for (int i = 0; i < 4; i++) a[i] = Qs[tm * 4 + i][kd];
#pragma unroll
            for (int j = 0; j < 4; j++) bb[j] = Ks[tn * 4 + j][kd];
#pragma unroll
            for (int i = 0; i < 4; i++)
#pragma unroll
                for (int j = 0; j < 4; j++) s[i][j] = fmaf(a[i], bb[j], s[i][j]);
        }

        const bool domask = (kt >= 2 * qt);
#pragma unroll
        for (int i = 0; i < 4; i++) {
            int qr = qt * 64 + tm * 4 + i;
#pragma unroll
            for (int j = 0; j < 4; j++) {
                int kc = s0 + tn * 4 + j;
                float vv = s[i][j] * scale;
                if (domask && kc > qr) vv = -1e30f;
                s[i][j] = vv;
            }
        }

        float alpha[4];
#pragma unroll
        for (int i = 0; i < 4; i++) {
            float mx = s[i][0];
#pragma unroll
            for (int j = 1; j < 4; j++) mx = fmaxf(mx, s[i][j]);
            mx = fmaxf(mx, __shfl_xor_sync(0xffffffffu, mx, 1));
            mx = fmaxf(mx, __shfl_xor_sync(0xffffffffu, mx, 2));
            mx = fmaxf(mx, __shfl_xor_sync(0xffffffffu, mx, 4));
            float m_new = fmaxf(m_i[i], mx);
            float rs = 0.0f;
#pragma unroll
            for (int j = 0; j < 4; j++) {
                float p = __expf(s[i][j] - m_new);
                Ps[tm * 4 + i][tn * 4 + j] = p;
                rs += p;
            }
            rs += __shfl_xor_sync(0xffffffffu, rs, 1);
            rs += __shfl_xor_sync(0xffffffffu, rs, 2);
            rs += __shfl_xor_sync(0xffffffffu, rs, 4);
            alpha[i] = __expf(m_i[i] - m_new);
            l_i[i] = l_i[i] * alpha[i] + rs;
            m_i[i] = m_new;
        }
#pragma unroll
        for (int i = 0; i < 4; i++)
#pragma unroll
            for (int j = 0; j < 8; j++) o_acc[i][j] *= alpha[i];
        __syncthreads();

#pragma unroll 4
        for (int kc = 0; kc < 32; kc++) {
            float a[4], bb[8];
#pragma unroll
            for (int i = 0; i < 4; i++) a[i] = Ps[tm * 4 + i][kc];
#pragma unroll
            for (int j = 0; j < 8; j++) bb[j] = Vs[kc][tn * 8 + j];
#pragma unroll
            for (int i = 0; i < 4; i++)
#pragma unroll
                for (int j = 0; j < 8; j++)
                    o_acc[i][j] = fmaf(a[i], bb[j], o_acc[i][j]);
        }
    }

#pragma unroll
    for (int i = 0; i < 4; i++) {
        int qr = qt * 64 + tm * 4 + i;
        float inv_l = 1.0f / l_i[i];
        float* orow = o + ((size_t)(b * TT + qr) * EE + h * HD + tn * 8);
#pragma unroll
        for (int j = 0; j < 8; j++) orow[j] = o_acc[i][j] * inv_l;
    }
}

// ---------------------------------------------------------------------------
// Fused residual-add + LayerNorm over E=768. One block per row, 256 threads.
// ---------------------------------------------------------------------------
__global__ __launch_bounds__(256)
void ln_kernel(const float* __restrict__ a, const float* __restrict__ res,
               const float* __restrict__ g, const float* __restrict__ bt,
               float* __restrict__ out) {
    const int row = blockIdx.x;
    const float* pa = a + (size_t)row * EE;
    const float* pr = res + (size_t)row * EE;
    float vloc[3];
    float s = 0.0f, ss = 0.0f;
#pragma unroll
    for (int i = 0; i < 3; i++) {
        int c = threadIdx.x + i * 256;
        float vv = pa[c] + pr[c];
        vloc[i] = vv;
        s += vv;
        ss += vv * vv;
    }
#pragma unroll
    for (int off = 16; off > 0; off >>= 1) {
        s  += __shfl_xor_sync(0xffffffffu, s, off);
        ss += __shfl_xor_sync(0xffffffffu, ss, off);
    }
    __shared__ float sred[16];
    __shared__ float smu, srstd;
    int w = threadIdx.x >> 5, lane = threadIdx.x & 31;
    if (lane == 0) { sred[w] = s; sred[8 + w] = ss; }
    __syncthreads();
    if (threadIdx.x == 0) {
        float S = 0.0f, SS = 0.0f;
#pragma unroll
        for (int i = 0; i < 8; i++) { S += sred[i]; SS += sred[8 + i]; }
        float mu = S * (1.0f / EE);
        float var = SS * (1.0f / EE) - mu * mu;
        smu = mu;
        srstd = rsqrtf(var + LN_EPS);
    }
    __syncthreads();
    float mu = smu, rstd = srstd;
    float* po = out + (size_t)row * EE;
#pragma unroll
    for (int i = 0; i < 3; i++) {
        int c = threadIdx.x + i * 256;
        po[c] = (vloc[i] - mu) * rstd * g[c] + bt[c];
    }
}

// ---------------------------------------------------------------------------
// Launch
// ---------------------------------------------------------------------------
extern "C" void kernel_launch(void* const* d_in, const int* in_sizes, int n_in,
                              void* d_out, int out_size) {
    const float* x      = (const float*)d_in[0];
    const float* Wq     = (const float*)d_in[1];
    const float* Wk     = (const float*)d_in[2];
    const float* Wv     = (const float*)d_in[3];
    const float* proj_w = (const float*)d_in[4];
    const float* proj_b = (const float*)d_in[5];
    const float* ln1_g  = (const float*)d_in[6];
    const float* ln1_b  = (const float*)d_in[7];
    const float* w1     = (const float*)d_in[8];
    const float* b1     = (const float*)d_in[9];
    const float* w2     = (const float*)d_in[10];
    const float* b2     = (const float*)d_in[11];
    const float* ln2_g  = (const float*)d_in[12];
    const float* ln2_b  = (const float*)d_in[13];
    float* out = (float*)d_out;

    float *q, *k, *v, *attn, *tmp, *x1, *hbuf;
    cudaGetSymbolAddress((void**)&q,    g_q);
    cudaGetSymbolAddress((void**)&k,    g_k);
    cudaGetSymbolAddress((void**)&v,    g_v);
    cudaGetSymbolAddress((void**)&attn, g_attn);
    cudaGetSymbolAddress((void**)&tmp,  g_tmp);
    cudaGetSymbolAddress((void**)&x1,   g_x1);
    cudaGetSymbolAddress((void**)&hbuf, g_h);

    dim3 gQKV(EE / 128, MROWS / 128, 3);  // (6, 32, 3)
    dim3 gE(EE / 128, MROWS / 128, 1);    // (6, 32)
    dim3 gF(FFD / 128, MROWS / 128, 1);   // (24, 32)

    // Fused QKV projections (tensor cores, tf32)
    tgemm_kernel<false, false, 3><<<gQKV, 256>>>(x, Wq, Wk, Wv, nullptr,
                                                 q, k, v, MROWS, EE, EE);

    // Causal attention
    attn_kernel<<<dim3(TT / 64, BB * NH), 128>>>(q, k, v, attn);

    // Output projection + bias
    tgemm_kernel<true, false, 1><<<gE, 256>>>(attn, proj_w, proj_w, proj_w, proj_b,
                                              tmp, tmp, tmp, MROWS, EE, EE);
    ln_kernel<<<MROWS, 256>>>(tmp, x, ln1_g, ln1_b, x1);

    // FFN
    tgemm_kernel<true, true, 1><<<gF, 256>>>(x1, w1, w1, w1, b1,
                                             hbuf, hbuf, hbuf, MROWS, FFD, EE);
    tgemm_kernel<true, false, 1><<<gE, 256>>>(hbuf, w2, w2, w2, b2,
                                              tmp, tmp, tmp, MROWS, EE, FFD);
    ln_kernel<<<MROWS, 256>>>(tmp, x1, ln2_g, ln2_b, out);
}

// round 3
// speedup vs baseline: 3.5219x; 1.5578x over previous
#include <cuda_runtime.h>
#include <math.h>

// Problem constants
#define BB 2
#define TT 2048
#define EE 768
#define NH 12
#define HD 64
#define FFD 3072
#define MROWS (BB * TT)   // 4096
#define LN_EPS 1e-5f

// ---------------------------------------------------------------------------
// Scratch (no allocation allowed -> __device__ globals)
// ---------------------------------------------------------------------------
__device__ float g_q[MROWS * EE];
__device__ float g_k[MROWS * EE];
__device__ float g_v[MROWS * EE];
__device__ float g_attn[MROWS * EE];
__device__ float g_tmp[MROWS * EE];
__device__ float g_x1[MROWS * EE];
__device__ float g_h[MROWS * FFD];

// ---------------------------------------------------------------------------
// Helpers: tf32 convert, mma, cp.async
// ---------------------------------------------------------------------------
__device__ __forceinline__ unsigned f2tf32(float f) {
    unsigned u;
    asm("cvt.rna.tf32.f32 %0, %1;" : "=r"(u) : "f"(f));
    return u;
}

__device__ __forceinline__ void mma_tf32(float* c, const unsigned* a, const unsigned* b) {
    asm volatile(
        "mma.sync.aligned.m16n8k8.row.col.f32.tf32.tf32.f32 "
        "{%0,%1,%2,%3}, {%4,%5,%6,%7}, {%8,%9}, {%0,%1,%2,%3};\n"
        : "+f"(c[0]), "+f"(c[1]), "+f"(c[2]), "+f"(c[3])
        : "r"(a[0]), "r"(a[1]), "r"(a[2]), "r"(a[3]), "r"(b[0]), "r"(b[1]));
}

__device__ __forceinline__ void cp16(void* s, const void* g) {
    unsigned sa = (unsigned)__cvta_generic_to_shared(s);
    asm volatile("cp.async.cg.shared.global [%0], [%1], 16;\n" :: "r"(sa), "l"(g));
}
__device__ __forceinline__ void cp_commit() {
    asm volatile("cp.async.commit_group;\n");
}
__device__ __forceinline__ void cp_wait1() {
    asm volatile("cp.async.wait_group 1;\n");
}

// ---------------------------------------------------------------------------
// TF32 tensor-core GEMM: C[M,N] = A[M,K] @ B[N,K]^T (+bias, +relu)
// BM=BN=128, BK=16, 256 threads (8 warps as 4x2, 32x64 per warp).
// ---------------------------------------------------------------------------
#define PAD 20
#define TILE_F (128 * PAD)

template <bool HAS_BIAS, bool RELU, int NZ>
__global__ __launch_bounds__(256)
void tgemm_kernel(const float* __restrict__ A,
                  const float* __restrict__ B0, const float* __restrict__ B1,
                  const float* __restrict__ B2,
                  const float* __restrict__ bias,
                  float* __restrict__ C0, float* __restrict__ C1, float* __restrict__ C2,
                  int M, int N, int K) {
    const float* B = B0;
    float* C = C0;
    if (NZ == 3) {
        if (blockIdx.z == 1) { B = B1; C = C1; }
        else if (blockIdx.z == 2) { B = B2; C = C2; }
    }

    __shared__ float As[2][TILE_F];
    __shared__ float Bs[2][TILE_F];

    const int tid  = threadIdx.x;
    const int lane = tid & 31;
    const int warp = tid >> 5;
    const int wm   = warp >> 1;
    const int wn   = warp & 1;
    const int ln4  = lane >> 2;
    const int lm4  = lane & 3;
    const int brow = blockIdx.y * 128;
    const int bcol = blockIdx.x * 128;

    const int r0 = tid >> 2;
    const int kc = (tid & 3) << 2;

    float acc[2][8][4];
#pragma unroll
    for (int mt = 0; mt < 2; mt++)
#pragma unroll
        for (int nt = 0; nt < 8; nt++)
#pragma unroll
            for (int i = 0; i < 4; i++) acc[mt][nt][i] = 0.0f;

    const int nkt = K >> 4;

    {
        const float* ga = A + (size_t)(brow + r0) * K + kc;
        cp16(&As[0][r0 * PAD + kc], ga);
        cp16(&As[0][(r0 + 64) * PAD + kc], ga + (size_t)64 * K);
        const float* gb = B + (size_t)(bcol + r0) * K + kc;
        cp16(&Bs[0][r0 * PAD + kc], gb);
        cp16(&Bs[0][(r0 + 64) * PAD + kc], gb + (size_t)64 * K);
        cp_commit();
    }

    for (int kt = 0; kt < nkt; kt++) {
        const int st = kt & 1;
        if (kt + 1 < nkt) {
            const int st2 = st ^ 1;
            const float* ga = A + (size_t)(brow + r0) * K + (kt + 1) * 16 + kc;
            cp16(&As[st2][r0 * PAD + kc], ga);
            cp16(&As[st2][(r0 + 64) * PAD + kc], ga + (size_t)64 * K);
            const float* gb = B + (size_t)(bcol + r0) * K + (kt + 1) * 16 + kc;
            cp16(&Bs[st2][r0 * PAD + kc], gb);
            cp16(&Bs[st2][(r0 + 64) * PAD + kc], gb + (size_t)64 * K);
        }
        cp_commit();
        cp_wait1();
        __syncthreads();

        const float* as = As[st];
        const float* bs = Bs[st];
#pragma unroll
        for (int ks = 0; ks < 2; ks++) {
            const int k0 = ks * 8;
            unsigned af[2][4], bf[8][2];
#pragma unroll
            for (int mt = 0; mt < 2; mt++) {
                const int rb = wm * 32 + mt * 16;
                af[mt][0] = f2tf32(as[(rb + ln4) * PAD + k0 + lm4]);
                af[mt][1] = f2tf32(as[(rb + ln4 + 8) * PAD + k0 + lm4]);
                af[mt][2] = f2tf32(as[(rb + ln4) * PAD + k0 + lm4 + 4]);
                af[mt][3] = f2tf32(as[(rb + ln4 + 8) * PAD + k0 + lm4 + 4]);
            }
#pragma unroll
            for (int nt = 0; nt < 8; nt++) {
                const int cb = wn * 64 + nt * 8;
                bf[nt][0] = f2tf32(bs[(cb + ln4) * PAD + k0 + lm4]);
                bf[nt][1] = f2tf32(bs[(cb + ln4) * PAD + k0 + lm4 + 4]);
            }
#pragma unroll
            for (int mt = 0; mt < 2; mt++)
#pragma unroll
                for (int nt = 0; nt < 8; nt++)
                    mma_tf32(acc[mt][nt], af[mt], bf[nt]);
        }
        __syncthreads();
    }

#pragma unroll
    for (int mt = 0; mt < 2; mt++) {
        const int r = brow + wm * 32 + mt * 16 + ln4;
#pragma unroll
        for (int nt = 0; nt < 8; nt++) {
            const int col = bcol + wn * 64 + nt * 8 + lm4 * 2;
            float2 v0 = make_float2(acc[mt][nt][0], acc[mt][nt][1]);
            float2 v1 = make_float2(acc[mt][nt][2], acc[mt][nt][3]);
            if (HAS_BIAS) {
                float bx = bias[col], by = bias[col + 1];
                v0.x += bx; v0.y += by;
                v1.x += bx; v1.y += by;
            }
            if (RELU) {
                v0.x = fmaxf(v0.x, 0.0f); v0.y = fmaxf(v0.y, 0.0f);
                v1.x = fmaxf(v1.x, 0.0f); v1.y = fmaxf(v1.y, 0.0f);
            }
            *reinterpret_cast<float2*>(C + (size_t)r * N + col) = v0;
            *reinterpret_cast<float2*>(C + (size_t)(r + 8) * N + col) = v1;
        }
    }
}

// ---------------------------------------------------------------------------
// Tensor-core causal flash attention (tf32 mma.m16n8k8).
// Grid (T/64, B*NH), 128 threads (4 warps). Warp w owns query rows w*16..+15.
// K/V tiles of 64 keys. Q held as register a-fragments for the whole kernel.
// SMEM (dynamic, 52224B): Ks[64][68], Vs[64][68] (tf32 bits), QP[64][68]
// (Q at start, then per-warp P fragments).
// ---------------------------------------------------------------------------
#define ASTR 68
#define AREG (64 * ASTR)
#define ATTN_SMEM (3 * AREG * 4)

__global__ __launch_bounds__(128)
void attn_tc_kernel(const float* __restrict__ qp, const float* __restrict__ kp,
                    const float* __restrict__ vp, float* __restrict__ op) {
    extern __shared__ unsigned smem[];
    unsigned* Ks = smem;
    unsigned* Vs = smem + AREG;
    unsigned* QP = smem + 2 * AREG;

    const int qt  = blockIdx.x;
    const int bh  = blockIdx.y;
    const int b   = bh / NH;
    const int h   = bh % NH;
    const int tid = threadIdx.x;
    const int lane = tid & 31;
    const int w    = tid >> 5;
    const int ln4  = lane >> 2;      // 0..7
    const int lm4  = lane & 3;       // 0..3
    const int rb   = w * 16;         // warp's query row base within tile

    // ---- Load Q tile (64x64) as tf32 bits ----
#pragma unroll
    for (int i = 0; i < 8; i++) {
        int idx = tid + i * 128;             // 0..1023 float4 slots
        int row = idx >> 4;
        int dc  = (idx & 15) << 2;
        float4 vq = *reinterpret_cast<const float4*>(
            qp + ((size_t)(b * TT + qt * 64 + row) * EE + h * HD + dc));
        unsigned* d = &QP[row * ASTR + dc];
        d[0] = f2tf32(vq.x); d[1] = f2tf32(vq.y);
        d[2] = f2tf32(vq.z); d[3] = f2tf32(vq.w);
    }
    __syncthreads();

    // ---- Q a-fragments (held in registers) ----
    unsigned qa[8][4];
#pragma unroll
    for (int ks = 0; ks < 8; ks++) {
        qa[ks][0] = QP[(rb + ln4) * ASTR + ks * 8 + lm4];
        qa[ks][1] = QP[(rb + ln4 + 8) * ASTR + ks * 8 + lm4];
        qa[ks][2] = QP[(rb + ln4) * ASTR + ks * 8 + lm4 + 4];
        qa[ks][3] = QP[(rb + ln4 + 8) * ASTR + ks * 8 + lm4 + 4];
    }

    float o_acc[8][4];
#pragma unroll
    for (int nb = 0; nb < 8; nb++)
#pragma unroll
        for (int i = 0; i < 4; i++) o_acc[nb][i] = 0.0f;
    float m0 = -1e30f, m1 = -1e30f, l0 = 0.0f, l1 = 0.0f;
    const float scale = 0.125f;          // 1/sqrt(64)
    const int row0g = qt * 64 + rb + ln4;
    const int row1g = row0g + 8;

    for (int kt = 0; kt <= qt; kt++) {
        __syncthreads();   // prior tile compute done (also covers Q-frag reads, iter 0)
        // ---- Load K/V tiles (64x64 each) as tf32 bits ----
#pragma unroll
        for (int i = 0; i < 8; i++) {
            int idx = tid + i * 128;
            int row = idx >> 4;
            int dc  = (idx & 15) << 2;
            size_t g = ((size_t)(b * TT + kt * 64 + row) * EE + h * HD + dc);
            float4 vk = *reinterpret_cast<const float4*>(kp + g);
            unsigned* dk = &Ks[row * ASTR + dc];
            dk[0] = f2tf32(vk.x); dk[1] = f2tf32(vk.y);
            dk[2] = f2tf32(vk.z); dk[3] = f2tf32(vk.w);
            float4 vv = *reinterpret_cast<const float4*>(vp + g);
            unsigned* dv = &Vs[row * ASTR + dc];
            dv[0] = f2tf32(vv.x); dv[1] = f2tf32(vv.y);
            dv[2] = f2tf32(vv.z); dv[3] = f2tf32(vv.w);
        }
        __syncthreads();

        // ---- S = Q K^T : warp computes 16x64, c-frag layout ----
        float s[8][4];
#pragma unroll
        for (int nb = 0; nb < 8; nb++)
#pragma unroll
            for (int i = 0; i < 4; i++) s[nb][i] = 0.0f;
#pragma unroll
        for (int nb = 0; nb < 8; nb++) {
#pragma unroll
            for (int ks = 0; ks < 8; ks++) {
                unsigned bf[2];
                bf[0] = Ks[(nb * 8 + ln4) * ASTR + ks * 8 + lm4];
                bf[1] = Ks[(nb * 8 + ln4) * ASTR + ks * 8 + lm4 + 4];
                mma_tf32(s[nb], qa[ks], bf);
            }
        }

        // ---- scale + causal mask (diagonal tile only) ----
        if (kt == qt) {
#pragma unroll
            for (int nb = 0; nb < 8; nb++) {
                int c0 = kt * 64 + nb * 8 + lm4 * 2;
                s[nb][0] = (c0     > row0g) ? -1e30f : s[nb][0] * scale;
                s[nb][1] = (c0 + 1 > row0g) ? -1e30f : s[nb][1] * scale;
                s[nb][2] = (c0     > row1g) ? -1e30f : s[nb][2] * scale;
                s[nb][3] = (c0 + 1 > row1g) ? -1e30f : s[nb][3] * scale;
            }
        } else {
#pragma unroll
            for (int nb = 0; nb < 8; nb++)
#pragma unroll
                for (int i = 0; i < 4; i++) s[nb][i] *= scale;
        }

        // ---- online softmax (rows ln4 / ln4+8; 4 lanes per row) ----
        float mx0 = -1e30f, mx1 = -1e30f;
#pragma unroll
        for (int nb = 0; nb < 8; nb++) {
            mx0 = fmaxf(mx0, fmaxf(s[nb][0], s[nb][1]));
            mx1 = fmaxf(mx1, fmaxf(s[nb][2], s[nb][3]));
        }
        mx0 = fmaxf(mx0, __shfl_xor_sync(0xffffffffu, mx0, 1));
        mx0 = fmaxf(mx0, __shfl_xor_sync(0xffffffffu, mx0, 2));
        mx1 = fmaxf(mx1, __shfl_xor_sync(0xffffffffu, mx1, 1));
        mx1 = fmaxf(mx1, __shfl_xor_sync(0xffffffffu, mx1, 2));
        float mn0 = fmaxf(m0, mx0), mn1 = fmaxf(m1, mx1);
        float alpha0 = __expf(m0 - mn0), alpha1 = __expf(m1 - mn1);
        float sum0 = 0.0f, sum1 = 0.0f;
#pragma unroll
        for (int nb = 0; nb < 8; nb++) {
            float p00 = __expf(s[nb][0] - mn0);
            float p01 = __expf(s[nb][1] - mn0);
            float p10 = __expf(s[nb][2] - mn1);
            float p11 = __expf(s[nb][3] - mn1);
            sum0 += p00 + p01;
            sum1 += p10 + p11;
            unsigned* pr0 = &QP[(rb + ln4) * ASTR + nb * 8 + lm4 * 2];
            pr0[0] = f2tf32(p00); pr0[1] = f2tf32(p01);
            unsigned* pr1 = &QP[(rb + ln4 + 8) * ASTR + nb * 8 + lm4 * 2];
            pr1[0] = f2tf32(p10); pr1[1] = f2tf32(p11);
        }
        sum0 += __shfl_xor_sync(0xffffffffu, sum0, 1);
        sum0 += __shfl_xor_sync(0xffffffffu, sum0, 2);
        sum1 += __shfl_xor_sync(0xffffffffu, sum1, 1);
        sum1 += __shfl_xor_sync(0xffffffffu, sum1, 2);
        l0 = l0 * alpha0 + sum0;
        l1 = l1 * alpha1 + sum1;
        m0 = mn0; m1 = mn1;
#pragma unroll
        for (int nb = 0; nb < 8; nb++) {
            o_acc[nb][0] *= alpha0; o_acc[nb][1] *= alpha0;
            o_acc[nb][2] *= alpha1; o_acc[nb][3] *= alpha1;
        }
        __syncwarp();

        // ---- O += P V : 16x64 += 16x64_k * 64x64 ----
#pragma unroll
        for (int ks = 0; ks < 8; ks++) {
            unsigned pa[4];
            pa[0] = QP[(rb + ln4) * ASTR + ks * 8 + lm4];
            pa[1] = QP[(rb + ln4 + 8) * ASTR + ks * 8 + lm4];
            pa[2] = QP[(rb + ln4) * ASTR + ks * 8 + lm4 + 4];
            pa[3] = QP[(rb + ln4 + 8) * ASTR + ks * 8 + lm4 + 4];
#pragma unroll
            for (int nb = 0; nb < 8; nb++) {
                unsigned vb[2];
                vb[0] = Vs[(ks * 8 + lm4) * ASTR + nb * 8 + ln4];
                vb[1] = Vs[(ks * 8 + lm4 + 4) * ASTR + nb * 8 + ln4];
                mma_tf32(o_acc[nb], pa, vb);
            }
        }
    }

    // ---- write O ----
    float inv0 = 1.0f / l0, inv1 = 1.0f / l1;
#pragma unroll
    for (int nb = 0; nb < 8; nb++) {
        int col = h * HD + nb * 8 + lm4 * 2;
        float2 v0 = make_float2(o_acc[nb][0] * inv0, o_acc[nb][1] * inv0);
        float2 v1 = make_float2(o_acc[nb][2] * inv1, o_acc[nb][3] * inv1);
        *reinterpret_cast<float2*>(op + (size_t)(b * TT + row0g) * EE + col) = v0;
        *reinterpret_cast<float2*>(op + (size_t)(b * TT + row1g) * EE + col) = v1;
    }
}

// ---------------------------------------------------------------------------
// Fused residual-add + LayerNorm over E=768. One block per row, 256 threads.
// ---------------------------------------------------------------------------
__global__ __launch_bounds__(256)
void ln_kernel(const float* __restrict__ a, const float* __restrict__ res,
               const float* __restrict__ g, const float* __restrict__ bt,
               float* __restrict__ out) {
    const int row = blockIdx.x;
    const float* pa = a + (size_t)row * EE;
    const float* pr = res + (size_t)row * EE;
    float vloc[3];
    float s = 0.0f, ss = 0.0f;
#pragma unroll
    for (int i = 0; i < 3; i++) {
        int c = threadIdx.x + i * 256;
        float vv = pa[c] + pr[c];
        vloc[i] = vv;
        s += vv;
        ss += vv * vv;
    }
#pragma unroll
    for (int off = 16; off > 0; off >>= 1) {
        s  += __shfl_xor_sync(0xffffffffu, s, off);
        ss += __shfl_xor_sync(0xffffffffu, ss, off);
    }
    __shared__ float sred[16];
    __shared__ float smu, srstd;
    int w = threadIdx.x >> 5, lane = threadIdx.x & 31;
    if (lane == 0) { sred[w] = s; sred[8 + w] = ss; }
    __syncthreads();
    if (threadIdx.x == 0) {
        float S = 0.0f, SS = 0.0f;
#pragma unroll
        for (int i = 0; i < 8; i++) { S += sred[i]; SS += sred[8 + i]; }
        float mu = S * (1.0f / EE);
        float var = SS * (1.0f / EE) - mu * mu;
        smu = mu;
        srstd = rsqrtf(var + LN_EPS);
    }
    __syncthreads();
    float mu = smu, rstd = srstd;
    float* po = out + (size_t)row * EE;
#pragma unroll
    for (int i = 0; i < 3; i++) {
        int c = threadIdx.x + i * 256;
        po[c] = (vloc[i] - mu) * rstd * g[c] + bt[c];
    }
}

// ---------------------------------------------------------------------------
// Launch
// ---------------------------------------------------------------------------
extern "C" void kernel_launch(void* const* d_in, const int* in_sizes, int n_in,
                              void* d_out, int out_size) {
    const float* x      = (const float*)d_in[0];
    const float* Wq     = (const float*)d_in[1];
    const float* Wk     = (const float*)d_in[2];
    const float* Wv     = (const float*)d_in[3];
    const float* proj_w = (const float*)d_in[4];
    const float* proj_b = (const float*)d_in[5];
    const float* ln1_g  = (const float*)d_in[6];
    const float* ln1_b  = (const float*)d_in[7];
    const float* w1     = (const float*)d_in[8];
    const float* b1     = (const float*)d_in[9];
    const float* w2     = (const float*)d_in[10];
    const float* b2     = (const float*)d_in[11];
    const float* ln2_g  = (const float*)d_in[12];
    const float* ln2_b  = (const float*)d_in[13];
    float* out = (float*)d_out;

    float *q, *k, *v, *attn, *tmp, *x1, *hbuf;
    cudaGetSymbolAddress((void**)&q,    g_q);
    cudaGetSymbolAddress((void**)&k,    g_k);
    cudaGetSymbolAddress((void**)&v,    g_v);
    cudaGetSymbolAddress((void**)&attn, g_attn);
    cudaGetSymbolAddress((void**)&tmp,  g_tmp);
    cudaGetSymbolAddress((void**)&x1,   g_x1);
    cudaGetSymbolAddress((void**)&hbuf, g_h);

    static bool attr_done = false;
    if (!attr_done) {
        cudaFuncSetAttribute((const void*)attn_tc_kernel,
                             cudaFuncAttributeMaxDynamicSharedMemorySize, ATTN_SMEM);
        attr_done = true;
    }

    dim3 gQKV(EE / 128, MROWS / 128, 3);
    dim3 gE(EE / 128, MROWS / 128, 1);
    dim3 gF(FFD / 128, MROWS / 128, 1);

    // Fused QKV projections (tensor cores, tf32)
    tgemm_kernel<false, false, 3><<<gQKV, 256>>>(x, Wq, Wk, Wv, nullptr,
                                                 q, k, v, MROWS, EE, EE);

    // Causal attention (tensor cores, tf32)
    attn_tc_kernel<<<dim3(TT / 64, BB * NH), 128, ATTN_SMEM>>>(q, k, v, attn);

    // Output projection + bias
    tgemm_kernel<true, false, 1><<<gE, 256>>>(attn, proj_w, proj_w, proj_w, proj_b,
                                              tmp, tmp, tmp, MROWS, EE, EE);
    ln_kernel<<<MROWS, 256>>>(tmp, x, ln1_g, ln1_b, x1);

    // FFN
    tgemm_kernel<true, true, 1><<<gF, 256>>>(x1, w1, w1, w1, b1,
                                             hbuf, hbuf, hbuf, MROWS, FFD, EE);
    tgemm_kernel<true, false, 1><<<gE, 256>>>(hbuf, w2, w2, w2, b2,
                                              tmp, tmp, tmp, MROWS, EE, FFD);
    ln_kernel<<<MROWS, 256>>>(tmp, x1, ln2_g, ln2_b, out);
}

// round 4
// speedup vs baseline: 3.7631x; 1.0685x over previous
#include <cuda_runtime.h>
#include <math.h>

// Problem constants
#define BB 2
#define TT 2048
#define EE 768
#define NH 12
#define HD 64
#define FFD 3072
#define MROWS (BB * TT)   // 4096
#define LN_EPS 1e-5f

// ---------------------------------------------------------------------------
// Scratch (no allocation allowed -> __device__ globals)
// ---------------------------------------------------------------------------
__device__ float g_q[MROWS * EE];
__device__ float g_k[MROWS * EE];
__device__ float g_v[MROWS * EE];
__device__ float g_attn[MROWS * EE];
__device__ float g_tmp[MROWS * EE];
__device__ float g_x1[MROWS * EE];
__device__ float g_x1r[MROWS * EE];
__device__ float g_xr[MROWS * EE];
__device__ float g_h[MROWS * FFD];
__device__ float g_wqr[NH * HD * EE];
__device__ float g_wkr[NH * HD * EE];
__device__ float g_wvr[NH * HD * EE];
__device__ float g_projr[EE * EE];
__device__ float g_w1r[FFD * EE];
__device__ float g_w2r[EE * FFD];

// ---------------------------------------------------------------------------
// Helpers
// ---------------------------------------------------------------------------
__device__ __forceinline__ unsigned f2tf32(float f) {
    unsigned u;
    asm("cvt.rna.tf32.f32 %0, %1;" : "=r"(u) : "f"(f));
    return u;
}
__device__ __forceinline__ float roundtf(float f) {
    return __uint_as_float(f2tf32(f));
}

__device__ __forceinline__ void mma_tf32(float* c, const unsigned* a, const unsigned* b) {
    asm volatile(
        "mma.sync.aligned.m16n8k8.row.col.f32.tf32.tf32.f32 "
        "{%0,%1,%2,%3}, {%4,%5,%6,%7}, {%8,%9}, {%0,%1,%2,%3};\n"
        : "+f"(c[0]), "+f"(c[1]), "+f"(c[2]), "+f"(c[3])
        : "r"(a[0]), "r"(a[1]), "r"(a[2]), "r"(a[3]), "r"(b[0]), "r"(b[1]));
}

__device__ __forceinline__ void cp16(void* s, const void* g) {
    unsigned sa = (unsigned)__cvta_generic_to_shared(s);
    asm volatile("cp.async.cg.shared.global [%0], [%1], 16;\n" :: "r"(sa), "l"(g));
}
__device__ __forceinline__ void cp_commit() {
    asm volatile("cp.async.commit_group;\n");
}
__device__ __forceinline__ void cp_wait1() {
    asm volatile("cp.async.wait_group 1;\n");
}

// ---------------------------------------------------------------------------
// Elementwise tf32 pre-rounding: out[i] = tf32(in[i])
// ---------------------------------------------------------------------------
__global__ __launch_bounds__(256)
void round_kernel(const float* __restrict__ in, float* __restrict__ out, int n4) {
    int i = blockIdx.x * 256 + threadIdx.x;
    if (i < n4) {
        float4 v = reinterpret_cast<const float4*>(in)[i];
        v.x = roundtf(v.x); v.y = roundtf(v.y);
        v.z = roundtf(v.z); v.w = roundtf(v.w);
        reinterpret_cast<float4*>(out)[i] = v;
    }
}

// ---------------------------------------------------------------------------
// TF32 tensor-core GEMM: C[M,N] = A[M,K] @ B[N,K]^T (+bias, +relu, +round)
// Inputs MUST be pre-rounded to tf32 (no cvt in the inner loop).
// BM=BN=128, BK=32, 256 threads (8 warps as 4x2, 32x64 per warp).
// Dynamic SMEM 73728B, 2-stage cp.async pipeline, pad-36 rows.
// ---------------------------------------------------------------------------
#define GPAD 36
#define GTILE (128 * GPAD)                 // floats per stage per operand
#define GSMEM (4 * GTILE * 4)              // bytes

template <bool HAS_BIAS, bool RELU, int NZ, bool ROUND_OUT>
__global__ __launch_bounds__(256)
void tgemm_kernel(const float* __restrict__ A,
                  const float* __restrict__ B0, const float* __restrict__ B1,
                  const float* __restrict__ B2,
                  const float* __restrict__ bias,
                  float* __restrict__ C0, float* __restrict__ C1, float* __restrict__ C2,
                  int M, int N, int K) {
    const float* B = B0;
    float* C = C0;
    if (NZ == 3) {
        if (blockIdx.z == 1) { B = B1; C = C1; }
        else if (blockIdx.z == 2) { B = B2; C = C2; }
    }

    extern __shared__ float sm[];
    float* Asm = sm;                 // 2 stages of 128x36
    float* Bsm = sm + 2 * GTILE;

    const int tid  = threadIdx.x;
    const int lane = tid & 31;
    const int warp = tid >> 5;
    const int wm   = warp >> 1;          // 0..3
    const int wn   = warp & 1;           // 0..1
    const int ln4  = lane >> 2;          // 0..7
    const int lm4  = lane & 3;           // 0..3
    const int brow = blockIdx.y * 128;
    const int bcol = blockIdx.x * 128;

    float acc[2][8][4];
#pragma unroll
    for (int mt = 0; mt < 2; mt++)
#pragma unroll
        for (int nt = 0; nt < 8; nt++)
#pragma unroll
            for (int i = 0; i < 4; i++) acc[mt][nt][i] = 0.0f;

    const int nkt = K >> 5;

    // prologue: stage 0 (128x32 of A and B: 4 float4 per thread each)
    {
#pragma unroll
        for (int i = 0; i < 4; i++) {
            int idx = tid + i * 256;         // 0..1023
            int row = idx >> 3;              // 0..127
            int kc  = (idx & 7) << 2;        // 0..28
            cp16(&Asm[row * GPAD + kc], A + (size_t)(brow + row) * K + kc);
            cp16(&Bsm[row * GPAD + kc], B + (size_t)(bcol + row) * K + kc);
        }
        cp_commit();
    }

    for (int kt = 0; kt < nkt; kt++) {
        const int st = kt & 1;
        if (kt + 1 < nkt) {
            const int so = (st ^ 1) * GTILE;
            const int kb = (kt + 1) * 32;
#pragma unroll
            for (int i = 0; i < 4; i++) {
                int idx = tid + i * 256;
                int row = idx >> 3;
                int kc  = (idx & 7) << 2;
                cp16(&Asm[so + row * GPAD + kc], A + (size_t)(brow + row) * K + kb + kc);
                cp16(&Bsm[so + row * GPAD + kc], B + (size_t)(bcol + row) * K + kb + kc);
            }
        }
        cp_commit();
        cp_wait1();
        __syncthreads();

        const unsigned* as = reinterpret_cast<const unsigned*>(Asm + st * GTILE);
        const unsigned* bs = reinterpret_cast<const unsigned*>(Bsm + st * GTILE);
#pragma unroll
        for (int ks = 0; ks < 4; ks++) {
            const int k0 = ks * 8;
            unsigned af[2][4], bf[8][2];
#pragma unroll
            for (int mt = 0; mt < 2; mt++) {
                const int rb = wm * 32 + mt * 16;
                af[mt][0] = as[(rb + ln4) * GPAD + k0 + lm4];
                af[mt][1] = as[(rb + ln4 + 8) * GPAD + k0 + lm4];
                af[mt][2] = as[(rb + ln4) * GPAD + k0 + lm4 + 4];
                af[mt][3] = as[(rb + ln4 + 8) * GPAD + k0 + lm4 + 4];
            }
#pragma unroll
            for (int nt = 0; nt < 8; nt++) {
                const int cb = wn * 64 + nt * 8;
                bf[nt][0] = bs[(cb + ln4) * GPAD + k0 + lm4];
                bf[nt][1] = bs[(cb + ln4) * GPAD + k0 + lm4 + 4];
            }
#pragma unroll
            for (int mt = 0; mt < 2; mt++)
#pragma unroll
                for (int nt = 0; nt < 8; nt++)
                    mma_tf32(acc[mt][nt], af[mt], bf[nt]);
        }
        __syncthreads();
    }

    // epilogue
#pragma unroll
    for (int mt = 0; mt < 2; mt++) {
        const int r = brow + wm * 32 + mt * 16 + ln4;
#pragma unroll
        for (int nt = 0; nt < 8; nt++) {
            const int col = bcol + wn * 64 + nt * 8 + lm4 * 2;
            float2 v0 = make_float2(acc[mt][nt][0], acc[mt][nt][1]);
            float2 v1 = make_float2(acc[mt][nt][2], acc[mt][nt][3]);
            if (HAS_BIAS) {
                float bx = bias[col], by = bias[col + 1];
                v0.x += bx; v0.y += by;
                v1.x += bx; v1.y += by;
            }
            if (RELU) {
                v0.x = fmaxf(v0.x, 0.0f); v0.y = fmaxf(v0.y, 0.0f);
                v1.x = fmaxf(v1.x, 0.0f); v1.y = fmaxf(v1.y, 0.0f);
            }
            if (ROUND_OUT) {
                v0.x = roundtf(v0.x); v0.y = roundtf(v0.y);
                v1.x = roundtf(v1.x); v1.y = roundtf(v1.y);
            }
            *reinterpret_cast<float2*>(C + (size_t)r * N + col) = v0;
            *reinterpret_cast<float2*>(C + (size_t)(r + 8) * N + col) = v1;
        }
    }
}

// ---------------------------------------------------------------------------
// Tensor-core causal flash attention (tf32 mma.m16n8k8).
// q/k/v are pre-rounded to tf32 by the QKV GEMM -> loads are raw bit copies.
// Output O is written pre-rounded (feeds the proj GEMM only).
// ---------------------------------------------------------------------------
#define ASTR 68
#define AREG (64 * ASTR)
#define ATTN_SMEM (3 * AREG * 4)

__global__ __launch_bounds__(128)
void attn_tc_kernel(const float* __restrict__ qp, const float* __restrict__ kp,
                    const float* __restrict__ vp, float* __restrict__ op) {
    extern __shared__ unsigned smem[];
    unsigned* Ks = smem;
    unsigned* Vs = smem + AREG;
    unsigned* QP = smem + 2 * AREG;

    const int qt  = blockIdx.x;
    const int bh  = blockIdx.y;
    const int b   = bh / NH;
    const int h   = bh % NH;
    const int tid = threadIdx.x;
    const int lane = tid & 31;
    const int w    = tid >> 5;
    const int ln4  = lane >> 2;
    const int lm4  = lane & 3;
    const int rb   = w * 16;

    // ---- Load Q tile (64x64) ----
#pragma unroll
    for (int i = 0; i < 8; i++) {
        int idx = tid + i * 128;
        int row = idx >> 4;
        int dc  = (idx & 15) << 2;
        float4 vq = *reinterpret_cast<const float4*>(
            qp + ((size_t)(b * TT + qt * 64 + row) * EE + h * HD + dc));
        unsigned* d = &QP[row * ASTR + dc];
        d[0] = __float_as_uint(vq.x); d[1] = __float_as_uint(vq.y);
        d[2] = __float_as_uint(vq.z); d[3] = __float_as_uint(vq.w);
    }
    __syncthreads();

    unsigned qa[8][4];
#pragma unroll
    for (int ks = 0; ks < 8; ks++) {
        qa[ks][0] = QP[(rb + ln4) * ASTR + ks * 8 + lm4];
        qa[ks][1] = QP[(rb + ln4 + 8) * ASTR + ks * 8 + lm4];
        qa[ks][2] = QP[(rb + ln4) * ASTR + ks * 8 + lm4 + 4];
        qa[ks][3] = QP[(rb + ln4 + 8) * ASTR + ks * 8 + lm4 + 4];
    }

    float o_acc[8][4];
#pragma unroll
    for (int nb = 0; nb < 8; nb++)
#pragma unroll
        for (int i = 0; i < 4; i++) o_acc[nb][i] = 0.0f;
    float m0 = -1e30f, m1 = -1e30f, l0 = 0.0f, l1 = 0.0f;
    const float scale = 0.125f;
    const int row0g = qt * 64 + rb + ln4;
    const int row1g = row0g + 8;

    for (int kt = 0; kt <= qt; kt++) {
        __syncthreads();
#pragma unroll
        for (int i = 0; i < 8; i++) {
            int idx = tid + i * 128;
            int row = idx >> 4;
            int dc  = (idx & 15) << 2;
            size_t g = ((size_t)(b * TT + kt * 64 + row) * EE + h * HD + dc);
            float4 vk = *reinterpret_cast<const float4*>(kp + g);
            unsigned* dk = &Ks[row * ASTR + dc];
            dk[0] = __float_as_uint(vk.x); dk[1] = __float_as_uint(vk.y);
            dk[2] = __float_as_uint(vk.z); dk[3] = __float_as_uint(vk.w);
            float4 vv = *reinterpret_cast<const float4*>(vp + g);
            unsigned* dv = &Vs[row * ASTR + dc];
            dv[0] = __float_as_uint(vv.x); dv[1] = __float_as_uint(vv.y);
            dv[2] = __float_as_uint(vv.z); dv[3] = __float_as_uint(vv.w);
        }
        __syncthreads();

        float s[8][4];
#pragma unroll
        for (int nb = 0; nb < 8; nb++)
#pragma unroll
            for (int i = 0; i < 4; i++) s[nb][i] = 0.0f;
#pragma unroll
        for (int nb = 0; nb < 8; nb++) {
#pragma unroll
            for (int ks = 0; ks < 8; ks++) {
                unsigned bf[2];
                bf[0] = Ks[(nb * 8 + ln4) * ASTR + ks * 8 + lm4];
                bf[1] = Ks[(nb * 8 + ln4) * ASTR + ks * 8 + lm4 + 4];
                mma_tf32(s[nb], qa[ks], bf);
            }
        }

        if (kt == qt) {
#pragma unroll
            for (int nb = 0; nb < 8; nb++) {
                int c0 = kt * 64 + nb * 8 + lm4 * 2;
                s[nb][0] = (c0     > row0g) ? -1e30f : s[nb][0] * scale;
                s[nb][1] = (c0 + 1 > row0g) ? -1e30f : s[nb][1] * scale;
                s[nb][2] = (c0     > row1g) ? -1e30f : s[nb][2] * scale;
                s[nb][3] = (c0 + 1 > row1g) ? -1e30f : s[nb][3] * scale;
            }
        } else {
#pragma unroll
            for (int nb = 0; nb < 8; nb++)
#pragma unroll
                for (int i = 0; i < 4; i++) s[nb][i] *= scale;
        }

        float mx0 = -1e30f, mx1 = -1e30f;
#pragma unroll
        for (int nb = 0; nb < 8; nb++) {
            mx0 = fmaxf(mx0, fmaxf(s[nb][0], s[nb][1]));
            mx1 = fmaxf(mx1, fmaxf(s[nb][2], s[nb][3]));
        }
        mx0 = fmaxf(mx0, __shfl_xor_sync(0xffffffffu, mx0, 1));
        mx0 = fmaxf(mx0, __shfl_xor_sync(0xffffffffu, mx0, 2));
        mx1 = fmaxf(mx1, __shfl_xor_sync(0xffffffffu, mx1, 1));
        mx1 = fmaxf(mx1, __shfl_xor_sync(0xffffffffu, mx1, 2));
        float mn0 = fmaxf(m0, mx0), mn1 = fmaxf(m1, mx1);
        float alpha0 = __expf(m0 - mn0), alpha1 = __expf(m1 - mn1);
        float sum0 = 0.0f, sum1 = 0.0f;
#pragma unroll
        for (int nb = 0; nb < 8; nb++) {
            float p00 = __expf(s[nb][0] - mn0);
            float p01 = __expf(s[nb][1] - mn0);
            float p10 = __expf(s[nb][2] - mn1);
            float p11 = __expf(s[nb][3] - mn1);
            sum0 += p00 + p01;
            sum1 += p10 + p11;
            unsigned* pr0 = &QP[(rb + ln4) * ASTR + nb * 8 + lm4 * 2];
            pr0[0] = f2tf32(p00); pr0[1] = f2tf32(p01);
            unsigned* pr1 = &QP[(rb + ln4 + 8) * ASTR + nb * 8 + lm4 * 2];
            pr1[0] = f2tf32(p10); pr1[1] = f2tf32(p11);
        }
        sum0 += __shfl_xor_sync(0xffffffffu, sum0, 1);
        sum0 += __shfl_xor_sync(0xffffffffu, sum0, 2);
        sum1 += __shfl_xor_sync(0xffffffffu, sum1, 1);
        sum1 += __shfl_xor_sync(0xffffffffu, sum1, 2);
        l0 = l0 * alpha0 + sum0;
        l1 = l1 * alpha1 + sum1;
        m0 = mn0; m1 = mn1;
#pragma unroll
        for (int nb = 0; nb < 8; nb++) {
            o_acc[nb][0] *= alpha0; o_acc[nb][1] *= alpha0;
            o_acc[nb][2] *= alpha1; o_acc[nb][3] *= alpha1;
        }
        __syncwarp();

#pragma unroll
        for (int ks = 0; ks < 8; ks++) {
            unsigned pa[4];
            pa[0] = QP[(rb + ln4) * ASTR + ks * 8 + lm4];
            pa[1] = QP[(rb + ln4 + 8) * ASTR + ks * 8 + lm4];
            pa[2] = QP[(rb + ln4) * ASTR + ks * 8 + lm4 + 4];
            pa[3] = QP[(rb + ln4 + 8) * ASTR + ks * 8 + lm4 + 4];
#pragma unroll
            for (int nb = 0; nb < 8; nb++) {
                unsigned vb[2];
                vb[0] = Vs[(ks * 8 + lm4) * ASTR + nb * 8 + ln4];
                vb[1] = Vs[(ks * 8 + lm4 + 4) * ASTR + nb * 8 + ln4];
                mma_tf32(o_acc[nb], pa, vb);
            }
        }
    }

    float inv0 = 1.0f / l0, inv1 = 1.0f / l1;
#pragma unroll
    for (int nb = 0; nb < 8; nb++) {
        int col = h * HD + nb * 8 + lm4 * 2;
        float2 v0 = make_float2(roundtf(o_acc[nb][0] * inv0), roundtf(o_acc[nb][1] * inv0));
        float2 v1 = make_float2(roundtf(o_acc[nb][2] * inv1), roundtf(o_acc[nb][3] * inv1));
        *reinterpret_cast<float2*>(op + (size_t)(b * TT + row0g) * EE + col) = v0;
        *reinterpret_cast<float2*>(op + (size_t)(b * TT + row1g) * EE + col) = v1;
    }
}

// ---------------------------------------------------------------------------
// Fused residual-add + LayerNorm over E=768. One block per row, 256 threads.
// ROUND=true additionally writes a tf32-rounded copy (GEMM input).
// ---------------------------------------------------------------------------
template <bool ROUND>
__global__ __launch_bounds__(256)
void ln_kernel(const float* __restrict__ a, const float* __restrict__ res,
               const float* __restrict__ g, const float* __restrict__ bt,
               float* __restrict__ out, float* __restrict__ outr) {
    const int row = blockIdx.x;
    const float* pa = a + (size_t)row * EE;
    const float* pr = res + (size_t)row * EE;
    float vloc[3];
    float s = 0.0f, ss = 0.0f;
#pragma unroll
    for (int i = 0; i < 3; i++) {
        int c = threadIdx.x + i * 256;
        float vv = pa[c] + pr[c];
        vloc[i] = vv;
        s += vv;
        ss += vv * vv;
    }
#pragma unroll
    for (int off = 16; off > 0; off >>= 1) {
        s  += __shfl_xor_sync(0xffffffffu, s, off);
        ss += __shfl_xor_sync(0xffffffffu, ss, off);
    }
    __shared__ float sred[16];
    __shared__ float smu, srstd;
    int w = threadIdx.x >> 5, lane = threadIdx.x & 31;
    if (lane == 0) { sred[w] = s; sred[8 + w] = ss; }
    __syncthreads();
    if (threadIdx.x == 0) {
        float S = 0.0f, SS = 0.0f;
#pragma unroll
        for (int i = 0; i < 8; i++) { S += sred[i]; SS += sred[8 + i]; }
        float mu = S * (1.0f / EE);
        float var = SS * (1.0f / EE) - mu * mu;
        smu = mu;
        srstd = rsqrtf(var + LN_EPS);
    }
    __syncthreads();
    float mu = smu, rstd = srstd;
    float* po = out + (size_t)row * EE;
    float* pq = ROUND ? (outr + (size_t)row * EE) : nullptr;
#pragma unroll
    for (int i = 0; i < 3; i++) {
        int c = threadIdx.x + i * 256;
        float vv = (vloc[i] - mu) * rstd * g[c] + bt[c];
        po[c] = vv;
        if (ROUND) pq[c] = roundtf(vv);
    }
}

// ---------------------------------------------------------------------------
// Launch
// ---------------------------------------------------------------------------
extern "C" void kernel_launch(void* const* d_in, const int* in_sizes, int n_in,
                              void* d_out, int out_size) {
    const float* x      = (const float*)d_in[0];
    const float* Wq     = (const float*)d_in[1];
    const float* Wk     = (const float*)d_in[2];
    const float* Wv     = (const float*)d_in[3];
    const float* proj_w = (const float*)d_in[4];
    const float* proj_b = (const float*)d_in[5];
    const float* ln1_g  = (const float*)d_in[6];
    const float* ln1_b  = (const float*)d_in[7];
    const float* w1     = (const float*)d_in[8];
    const float* b1     = (const float*)d_in[9];
    const float* w2     = (const float*)d_in[10];
    const float* b2     = (const float*)d_in[11];
    const float* ln2_g  = (const float*)d_in[12];
    const float* ln2_b  = (const float*)d_in[13];
    float* out = (float*)d_out;

    float *q, *k, *v, *attn, *tmp, *x1, *x1r, *xr, *hbuf;
    float *wqr, *wkr, *wvr, *projr, *w1r, *w2r;
    cudaGetSymbolAddress((void**)&q,     g_q);
    cudaGetSymbolAddress((void**)&k,     g_k);
    cudaGetSymbolAddress((void**)&v,     g_v);
    cudaGetSymbolAddress((void**)&attn,  g_attn);
    cudaGetSymbolAddress((void**)&tmp,   g_tmp);
    cudaGetSymbolAddress((void**)&x1,    g_x1);
    cudaGetSymbolAddress((void**)&x1r,   g_x1r);
    cudaGetSymbolAddress((void**)&xr,    g_xr);
    cudaGetSymbolAddress((void**)&hbuf,  g_h);
    cudaGetSymbolAddress((void**)&wqr,   g_wqr);
    cudaGetSymbolAddress((void**)&wkr,   g_wkr);
    cudaGetSymbolAddress((void**)&wvr,   g_wvr);
    cudaGetSymbolAddress((void**)&projr, g_projr);
    cudaGetSymbolAddress((void**)&w1r,   g_w1r);
    cudaGetSymbolAddress((void**)&w2r,   g_w2r);

    static bool attr_done = false;
    if (!attr_done) {
        cudaFuncSetAttribute((const void*)attn_tc_kernel,
                             cudaFuncAttributeMaxDynamicSharedMemorySize, ATTN_SMEM);
        cudaFuncSetAttribute((const void*)tgemm_kernel<false, false, 3, true>,
                             cudaFuncAttributeMaxDynamicSharedMemorySize, GSMEM);
        cudaFuncSetAttribute((const void*)tgemm_kernel<true, false, 1, false>,
                             cudaFuncAttributeMaxDynamicSharedMemorySize, GSMEM);
        cudaFuncSetAttribute((const void*)tgemm_kernel<true, true, 1, true>,
                             cudaFuncAttributeMaxDynamicSharedMemorySize, GSMEM);
        attr_done = true;
    }

    // ---- pre-round GEMM operands to tf32 ----
    {
        int n4x = MROWS * EE / 4;
        round_kernel<<<(n4x + 255) / 256, 256>>>(x, xr, n4x);
        int n4w = NH * HD * EE / 4;
        round_kernel<<<(n4w + 255) / 256, 256>>>(Wq, wqr, n4w);
        round_kernel<<<(n4w + 255) / 256, 256>>>(Wk, wkr, n4w);
        round_kernel<<<(n4w + 255) / 256, 256>>>(Wv, wvr, n4w);
        int n4p = EE * EE / 4;
        round_kernel<<<(n4p + 255) / 256, 256>>>(proj_w, projr, n4p);
        int n4f = FFD * EE / 4;
        round_kernel<<<(n4f + 255) / 256, 256>>>(w1, w1r, n4f);
        round_kernel<<<(n4f + 255) / 256, 256>>>(w2, w2r, n4f);
    }

    dim3 gQKV(EE / 128, MROWS / 128, 3);
    dim3 gE(EE / 128, MROWS / 128, 1);
    dim3 gF(FFD / 128, MROWS / 128, 1);

    // Fused QKV projections (rounded outputs feed attention)
    tgemm_kernel<false, false, 3, true><<<gQKV, 256, GSMEM>>>(
        xr, wqr, wkr, wvr, nullptr, q, k, v, MROWS, EE, EE);

    // Causal attention (rounded output feeds proj GEMM)
    attn_tc_kernel<<<dim3(TT / 64, BB * NH), 128, ATTN_SMEM>>>(q, k, v, attn);

    // Output projection + bias
    tgemm_kernel<true, false, 1, false><<<gE, 256, GSMEM>>>(
        attn, projr, projr, projr, proj_b, tmp, tmp, tmp, MROWS, EE, EE);
    ln_kernel<true><<<MROWS, 256>>>(tmp, x, ln1_g, ln1_b, x1, x1r);

    // FFN
    tgemm_kernel<true, true, 1, true><<<gF, 256, GSMEM>>>(
        x1r, w1r, w1r, w1r, b1, hbuf, hbuf, hbuf, MROWS, FFD, EE);
    tgemm_kernel<true, false, 1, false><<<gE, 256, GSMEM>>>(
        hbuf, w2r, w2r, w2r, b2, tmp, tmp, tmp, MROWS, EE, FFD);
    ln_kernel<false><<<MROWS, 256>>>(tmp, x1, ln2_g, ln2_b, out, nullptr);
}

// round 6
// speedup vs baseline: 5.2052x; 1.3832x over previous
#include <cuda_runtime.h>
#include <cuda_fp16.h>
#include <math.h>
#include <stdint.h>

// Problem constants
#define BB 2
#define TT 2048
#define EE 768
#define NH 12
#define HD 64
#define FFD 3072
#define MROWS (BB * TT)   // 4096
#define LN_EPS 1e-5f

// ---------------------------------------------------------------------------
// Scratch (no allocation allowed -> __device__ globals)
// ---------------------------------------------------------------------------
__device__ __half g_qh[MROWS * EE];
__device__ __half g_kh[MROWS * EE];
__device__ __half g_vh[MROWS * EE];
__device__ __half g_attnh[MROWS * EE];
__device__ __half g_x1h[MROWS * EE];
__device__ __half g_xh[MROWS * EE];
__device__ __half g_hh[MROWS * FFD];
__device__ __half g_wqh[NH * HD * EE];
__device__ __half g_wkh[NH * HD * EE];
__device__ __half g_wvh[NH * HD * EE];
__device__ __half g_projh[EE * EE];
__device__ __half g_w1h[FFD * EE];
__device__ __half g_w2h[EE * FFD];
__device__ float g_tmp[MROWS * EE];
__device__ float g_x1[MROWS * EE];

// ---------------------------------------------------------------------------
// Helpers
// ---------------------------------------------------------------------------
__device__ __forceinline__ void mma_f16(float* c, const unsigned* a, const unsigned* b) {
    asm volatile(
        "mma.sync.aligned.m16n8k16.row.col.f32.f16.f16.f32 "
        "{%0,%1,%2,%3}, {%4,%5,%6,%7}, {%8,%9}, {%0,%1,%2,%3};\n"
        : "+f"(c[0]), "+f"(c[1]), "+f"(c[2]), "+f"(c[3])
        : "r"(a[0]), "r"(a[1]), "r"(a[2]), "r"(a[3]), "r"(b[0]), "r"(b[1]));
}

__device__ __forceinline__ void cp16s(uint32_t s, const void* g) {
    asm volatile("cp.async.cg.shared.global [%0], [%1], 16;\n" :: "r"(s), "l"(g));
}
__device__ __forceinline__ void cp_commit() {
    asm volatile("cp.async.commit_group;\n");
}

__device__ __forceinline__ uint32_t smem_u32(const void* p) {
    return (uint32_t)__cvta_generic_to_shared(p);
}

// ---------------------------------------------------------------------------
// Elementwise float -> half conversion
// ---------------------------------------------------------------------------
__global__ __launch_bounds__(256)
void tohalf_kernel(const float* __restrict__ in, __half* __restrict__ out, int n4) {
    int i = blockIdx.x * 256 + threadIdx.x;
    if (i < n4) {
        float4 v = reinterpret_cast<const float4*>(in)[i];
        __half2 h0 = __floats2half2_rn(v.x, v.y);
        __half2 h1 = __floats2half2_rn(v.z, v.w);
        reinterpret_cast<__half2*>(out)[2 * i]     = h0;
        reinterpret_cast<__half2*>(out)[2 * i + 1] = h1;
    }
}

// ---------------------------------------------------------------------------
// FP16 tensor-core GEMM: C[M,N] = A[M,K] @ B[N,K]^T (+bias, +relu)
// A,B half; C float or half (OUT_HALF). fp32 accumulation.
// BM=BN=128, BK=32, 256 threads (8 warps as 4x2, warp tile 32x64).
// 3-stage cp.async pipeline. SMEM rows padded: 40 halfs (20 words) per 32-half
// row -> fragment LDS bank pattern (20r + l) mod 32 covers 0..31 (conflict-free).
// ---------------------------------------------------------------------------
#define GSTRW 20                       // words per smem row
#define GROWB 80                       // bytes per smem row
#define GSTGB (128 * GROWB)            // 10240 bytes per operand stage
#define GNS 3
#define GSMEM (2 * GNS * GSTGB)        // 61440 bytes

template <bool HAS_BIAS, bool RELU, int NZ, bool OUT_HALF>
__global__ __launch_bounds__(256)
void hgemm_kernel(const __half* __restrict__ A,
                  const __half* __restrict__ B0, const __half* __restrict__ B1,
                  const __half* __restrict__ B2,
                  const float* __restrict__ bias,
                  void* __restrict__ C0v, void* __restrict__ C1v, void* __restrict__ C2v,
                  int M, int N, int K) {
    const __half* B = B0;
    void* Cv = C0v;
    if (NZ == 3) {
        if (blockIdx.z == 1) { B = B1; Cv = C1v; }
        else if (blockIdx.z == 2) { B = B2; Cv = C2v; }
    }

    extern __shared__ char smraw[];
    const uint32_t smb = smem_u32(smraw);
    const int tid  = threadIdx.x;
    const int lane = tid & 31;
    const int warp = tid >> 5;
    const int wm   = warp >> 1;          // 0..3
    const int wn   = warp & 1;           // 0..1
    const int ln4  = lane >> 2;          // 0..7
    const int lm4  = lane & 3;           // 0..3
    const int brow = blockIdx.y * 128;
    const int bcol = blockIdx.x * 128;

    float acc[2][8][4];
#pragma unroll
    for (int mt = 0; mt < 2; mt++)
#pragma unroll
        for (int nt = 0; nt < 8; nt++)
#pragma unroll
            for (int i = 0; i < 4; i++) acc[mt][nt][i] = 0.0f;

    const int nk = K >> 5;               // BK = 32 halfs

    // load mapping: 2 threads per row; each thread 2x16B chunks per operand
    const int lr  = tid >> 1;            // 0..127
    const int lj0 = (tid & 1) * 2;       // chunk base 0 or 2

#define GLOAD(c) do {                                                        \
    const int st_ = (c) % GNS;                                               \
    const uint32_t sa_ = smb + st_ * GSTGB;                                  \
    const uint32_t sb_ = smb + (GNS + st_) * GSTGB;                          \
    const int kb_ = (c) * 32;                                                \
    const __half* gA_ = A + (size_t)(brow + lr) * K + kb_ + lj0 * 8;         \
    const __half* gB_ = B + (size_t)(bcol + lr) * K + kb_ + lj0 * 8;         \
    _Pragma("unroll")                                                        \
    for (int jj = 0; jj < 2; jj++) {                                         \
        cp16s(sa_ + lr * GROWB + (lj0 + jj) * 16, gA_ + jj * 8);             \
        cp16s(sb_ + lr * GROWB + (lj0 + jj) * 16, gB_ + jj * 8);             \
    }                                                                        \
    cp_commit();                                                             \
} while (0)

    // prologue: chunks 0..GNS-2
#pragma unroll
    for (int c = 0; c < GNS - 1; c++) GLOAD(c);

    for (int s = 0; s < nk; s++) {
        const int t = s + GNS - 1;
        if (t < nk) GLOAD(t);
        else cp_commit();                 // empty group keeps accounting uniform
        asm volatile("cp.async.wait_group %0;\n" :: "n"(GNS - 1));
        __syncthreads();

        const int st = s % GNS;
        const unsigned* as = reinterpret_cast<const unsigned*>(smraw + st * GSTGB);
        const unsigned* bs = reinterpret_cast<const unsigned*>(smraw + (GNS + st) * GSTGB);
#pragma unroll
        for (int ks = 0; ks < 2; ks++) {  // two k16 chunks per BK32
            const int k0 = ks * 8;        // word offset
            unsigned af[2][4], bf[8][2];
#pragma unroll
            for (int mt = 0; mt < 2; mt++) {
                const int rb = wm * 32 + mt * 16;
                af[mt][0] = as[(rb + ln4) * GSTRW + k0 + lm4];
                af[mt][1] = as[(rb + ln4 + 8) * GSTRW + k0 + lm4];
                af[mt][2] = as[(rb + ln4) * GSTRW + k0 + lm4 + 4];
                af[mt][3] = as[(rb + ln4 + 8) * GSTRW + k0 + lm4 + 4];
            }
#pragma unroll
            for (int nt = 0; nt < 8; nt++) {
                const int cb = wn * 64 + nt * 8;
                bf[nt][0] = bs[(cb + ln4) * GSTRW + k0 + lm4];
                bf[nt][1] = bs[(cb + ln4) * GSTRW + k0 + lm4 + 4];
            }
#pragma unroll
            for (int mt = 0; mt < 2; mt++)
#pragma unroll
                for (int nt = 0; nt < 8; nt++)
                    mma_f16(acc[mt][nt], af[mt], bf[nt]);
        }
        __syncthreads();
    }

    // epilogue
#pragma unroll
    for (int mt = 0; mt < 2; mt++) {
        const int r = brow + wm * 32 + mt * 16 + ln4;
#pragma unroll
        for (int nt = 0; nt < 8; nt++) {
            const int col = bcol + wn * 64 + nt * 8 + lm4 * 2;
            float2 v0 = make_float2(acc[mt][nt][0], acc[mt][nt][1]);
            float2 v1 = make_float2(acc[mt][nt][2], acc[mt][nt][3]);
            if (HAS_BIAS) {
                float bx = bias[col], by = bias[col + 1];
                v0.x += bx; v0.y += by;
                v1.x += bx; v1.y += by;
            }
            if (RELU) {
                v0.x = fmaxf(v0.x, 0.0f); v0.y = fmaxf(v0.y, 0.0f);
                v1.x = fmaxf(v1.x, 0.0f); v1.y = fmaxf(v1.y, 0.0f);
            }
            if (OUT_HALF) {
                __half* C = (__half*)Cv;
                *reinterpret_cast<__half2*>(C + (size_t)r * N + col) =
                    __floats2half2_rn(v0.x, v0.y);
                *reinterpret_cast<__half2*>(C + (size_t)(r + 8) * N + col) =
                    __floats2half2_rn(v1.x, v1.y);
            } else {
                float* C = (float*)Cv;
                *reinterpret_cast<float2*>(C + (size_t)r * N + col) = v0;
                *reinterpret_cast<float2*>(C + (size_t)(r + 8) * N + col) = v1;
            }
        }
    }
}

// ---------------------------------------------------------------------------
// FP16 tensor-core causal flash attention (mma.m16n8k16, fp32 accum/softmax).
// Grid (T/64, B*NH), 128 threads (4 warps). Warp w owns query rows w*16..+15.
// K/V tiles of 64 keys. Q held as register a-fragments.
// SMEM (static): Qs/P, Ks row-major [row][64 halfs] stride 36 words;
// Vt transposed [d][key] stride 36 words.
// ---------------------------------------------------------------------------
#define ASTRW 36
#define AROWW (64 * ASTRW)

__global__ __launch_bounds__(128)
void attn_h_kernel(const __half* __restrict__ qp, const __half* __restrict__ kp,
                   const __half* __restrict__ vp, __half* __restrict__ op) {
    __shared__ unsigned Qs[AROWW];   // Q then P (per-warp private rows)
    __shared__ unsigned Ks[AROWW];
    __shared__ unsigned Vt[AROWW];   // transposed V: row = d, cols = keys

    const int qt  = blockIdx.x;
    const int bh  = blockIdx.y;
    const int b   = bh / NH;
    const int h   = bh % NH;
    const int tid = threadIdx.x;
    const int lane = tid & 31;
    const int w    = tid >> 5;
    const int ln4  = lane >> 2;      // 0..7
    const int lm4  = lane & 3;       // 0..3
    const int rb   = w * 16;

    // ---- Load Q tile (64 rows x 64 halfs) ----
#pragma unroll
    for (int i = 0; i < 4; i++) {
        int idx = tid + i * 128;          // 0..511 (16B chunks)
        int row = idx >> 3;               // 0..63
        int c   = idx & 7;                // 0..7
        uint4 vq = *reinterpret_cast<const uint4*>(
            qp + ((size_t)(b * TT + qt * 64 + row) * EE + h * HD + c * 8));
        *reinterpret_cast<uint4*>(&Qs[row * ASTRW + c * 4]) = vq;
    }
    __syncthreads();

    // ---- Q a-fragments (4 k16 chunks x 4 regs) ----
    unsigned qa[4][4];
#pragma unroll
    for (int ks = 0; ks < 4; ks++) {
        qa[ks][0] = Qs[(rb + ln4) * ASTRW + ks * 8 + lm4];
        qa[ks][1] = Qs[(rb + ln4 + 8) * ASTRW + ks * 8 + lm4];
        qa[ks][2] = Qs[(rb + ln4) * ASTRW + ks * 8 + lm4 + 4];
        qa[ks][3] = Qs[(rb + ln4 + 8) * ASTRW + ks * 8 + lm4 + 4];
    }

    float o_acc[8][4];
#pragma unroll
    for (int nb = 0; nb < 8; nb++)
#pragma unroll
        for (int i = 0; i < 4; i++) o_acc[nb][i] = 0.0f;
    float m0 = -1e30f, m1 = -1e30f, l0 = 0.0f, l1 = 0.0f;
    const float scale = 0.125f;
    const int row0g = qt * 64 + rb + ln4;
    const int row1g = row0g + 8;

    for (int kt = 0; kt <= qt; kt++) {
        __syncthreads();
        // ---- Load K tile; load+transpose V tile ----
#pragma unroll
        for (int i = 0; i < 4; i++) {
            int idx = tid + i * 128;
            int row = idx >> 3;
            int c   = idx & 7;
            size_t g = ((size_t)(b * TT + kt * 64 + row) * EE + h * HD + c * 8);
            uint4 kv = *reinterpret_cast<const uint4*>(kp + g);
            *reinterpret_cast<uint4*>(&Ks[row * ASTRW + c * 4]) = kv;
            union { uint4 u; __half hh[8]; } vv;
            vv.u = *reinterpret_cast<const uint4*>(vp + g);
            __half* vt = reinterpret_cast<__half*>(Vt);
#pragma unroll
            for (int j = 0; j < 8; j++)
                vt[(c * 8 + j) * (2 * ASTRW) + row] = vv.hh[j];
        }
        __syncthreads();

        // ---- S = Q K^T : warp computes 16x64 ----
        float s[8][4];
#pragma unroll
        for (int nb = 0; nb < 8; nb++)
#pragma unroll
            for (int i = 0; i < 4; i++) s[nb][i] = 0.0f;
#pragma unroll
        for (int nb = 0; nb < 8; nb++) {
#pragma unroll
            for (int ks = 0; ks < 4; ks++) {
                unsigned bf[2];
                bf[0] = Ks[(nb * 8 + ln4) * ASTRW + ks * 8 + lm4];
                bf[1] = Ks[(nb * 8 + ln4) * ASTRW + ks * 8 + lm4 + 4];
                mma_f16(s[nb], qa[ks], bf);
            }
        }

        // ---- scale + causal mask (diagonal tile only) ----
        if (kt == qt) {
#pragma unroll
            for (int nb = 0; nb < 8; nb++) {
                int c0 = kt * 64 + nb * 8 + lm4 * 2;
                s[nb][0] = (c0     > row0g) ? -1e30f : s[nb][0] * scale;
                s[nb][1] = (c0 + 1 > row0g) ? -1e30f : s[nb][1] * scale;
                s[nb][2] = (c0     > row1g) ? -1e30f : s[nb][2] * scale;
                s[nb][3] = (c0 + 1 > row1g) ? -1e30f : s[nb][3] * scale;
            }
        } else {
#pragma unroll
            for (int nb = 0; nb < 8; nb++)
#pragma unroll
                for (int i = 0; i < 4; i++) s[nb][i] *= scale;
        }

        // ---- online softmax (fp32) ----
        float mx0 = -1e30f, mx1 = -1e30f;
#pragma unroll
        for (int nb = 0; nb < 8; nb++) {
            mx0 = fmaxf(mx0, fmaxf(s[nb][0], s[nb][1]));
            mx1 = fmaxf(mx1, fmaxf(s[nb][2], s[nb][3]));
        }
        mx0 = fmaxf(mx0, __shfl_xor_sync(0xffffffffu, mx0, 1));
        mx0 = fmaxf(mx0, __shfl_xor_sync(0xffffffffu, mx0, 2));
        mx1 = fmaxf(mx1, __shfl_xor_sync(0xffffffffu, mx1, 1));
        mx1 = fmaxf(mx1, __shfl_xor_sync(0xffffffffu, mx1, 2));
        float mn0 = fmaxf(m0, mx0), mn1 = fmaxf(m1, mx1);
        float alpha0 = __expf(m0 - mn0), alpha1 = __expf(m1 - mn1);
        float sum0 = 0.0f, sum1 = 0.0f;
#pragma unroll
        for (int nb = 0; nb < 8; nb++) {
            float p00 = __expf(s[nb][0] - mn0);
            float p01 = __expf(s[nb][1] - mn0);
            float p10 = __expf(s[nb][2] - mn1);
            float p11 = __expf(s[nb][3] - mn1);
            sum0 += p00 + p01;
            sum1 += p10 + p11;
            // store P as half2 (keys nb*8+2*lm4, +1 contiguous)
            __half2 hp0 = __floats2half2_rn(p00, p01);
            __half2 hp1 = __floats2half2_rn(p10, p11);
            Qs[(rb + ln4) * ASTRW + nb * 4 + lm4]     = *reinterpret_cast<unsigned*>(&hp0);
            Qs[(rb + ln4 + 8) * ASTRW + nb * 4 + lm4] = *reinterpret_cast<unsigned*>(&hp1);
        }
        sum0 += __shfl_xor_sync(0xffffffffu, sum0, 1);
        sum0 += __shfl_xor_sync(0xffffffffu, sum0, 2);
        sum1 += __shfl_xor_sync(0xffffffffu, sum1, 1);
        sum1 += __shfl_xor_sync(0xffffffffu, sum1, 2);
        l0 = l0 * alpha0 + sum0;
        l1 = l1 * alpha1 + sum1;
        m0 = mn0; m1 = mn1;
#pragma unroll
        for (int nb = 0; nb < 8; nb++) {
            o_acc[nb][0] *= alpha0; o_acc[nb][1] *= alpha0;
            o_acc[nb][2] *= alpha1; o_acc[nb][3] *= alpha1;
        }
        __syncwarp();

        // ---- O += P V : A = P (16 x 64 keys), B = Vt ----
#pragma unroll
        for (int ks = 0; ks < 4; ks++) {
            unsigned pa[4];
            pa[0] = Qs[(rb + ln4) * ASTRW + ks * 8 + lm4];
            pa[1] = Qs[(rb + ln4 + 8) * ASTRW + ks * 8 + lm4];
            pa[2] = Qs[(rb + ln4) * ASTRW + ks * 8 + lm4 + 4];
            pa[3] = Qs[(rb + ln4 + 8) * ASTRW + ks * 8 + lm4 + 4];
#pragma unroll
            for (int nb = 0; nb < 8; nb++) {
                unsigned vb[2];
                vb[0] = Vt[(nb * 8 + ln4) * ASTRW + ks * 8 + lm4];
                vb[1] = Vt[(nb * 8 + ln4) * ASTRW + ks * 8 + lm4 + 4];
                mma_f16(o_acc[nb], pa, vb);
            }
        }
    }

    // ---- write O (half) ----
    float inv0 = 1.0f / l0, inv1 = 1.0f / l1;
#pragma unroll
    for (int nb = 0; nb < 8; nb++) {
        int col = h * HD + nb * 8 + lm4 * 2;
        __half2 v0 = __floats2half2_rn(o_acc[nb][0] * inv0, o_acc[nb][1] * inv0);
        __half2 v1 = __floats2half2_rn(o_acc[nb][2] * inv1, o_acc[nb][3] * inv1);
        *reinterpret_cast<__half2*>(op + (size_t)(b * TT + row0g) * EE + col) = v0;
        *reinterpret_cast<__half2*>(op + (size_t)(b * TT + row1g) * EE + col) = v1;
    }
}

// ---------------------------------------------------------------------------
// Fused residual-add + LayerNorm over E=768. One block per row, 256 threads.
// HALF_OUT=true additionally writes a half copy (GEMM input).
// ---------------------------------------------------------------------------
template <bool HALF_OUT>
__global__ __launch_bounds__(256)
void ln_kernel(const float* __restrict__ a, const float* __restrict__ res,
               const float* __restrict__ g, const float* __restrict__ bt,
               float* __restrict__ out, __half* __restrict__ outh) {
    const int row = blockIdx.x;
    const float* pa = a + (size_t)row * EE;
    const float* pr = res + (size_t)row * EE;
    float vloc[3];
    float s = 0.0f, ss = 0.0f;
#pragma unroll
    for (int i = 0; i < 3; i++) {
        int c = threadIdx.x + i * 256;
        float vv = pa[c] + pr[c];
        vloc[i] = vv;
        s += vv;
        ss += vv * vv;
    }
#pragma unroll
    for (int off = 16; off > 0; off >>= 1) {
        s  += __shfl_xor_sync(0xffffffffu, s, off);
        ss += __shfl_xor_sync(0xffffffffu, ss, off);
    }
    __shared__ float sred[16];
    __shared__ float smu, srstd;
    int w = threadIdx.x >> 5, lane = threadIdx.x & 31;
    if (lane == 0) { sred[w] = s; sred[8 + w] = ss; }
    __syncthreads();
    if (threadIdx.x == 0) {
        float S = 0.0f, SS = 0.0f;
#pragma unroll
        for (int i = 0; i < 8; i++) { S += sred[i]; SS += sred[8 + i]; }
        float mu = S * (1.0f / EE);
        float var = SS * (1.0f / EE) - mu * mu;
        smu = mu;
        srstd = rsqrtf(var + LN_EPS);
    }
    __syncthreads();
    float mu = smu, rstd = srstd;
    float* po = out + (size_t)row * EE;
    __half* ph = HALF_OUT ? (outh + (size_t)row * EE) : nullptr;
#pragma unroll
    for (int i = 0; i < 3; i++) {
        int c = threadIdx.x + i * 256;
        float vv = (vloc[i] - mu) * rstd * g[c] + bt[c];
        po[c] = vv;
        if (HALF_OUT) ph[c] = __float2half_rn(vv);
    }
}

// ---------------------------------------------------------------------------
// Launch
// ---------------------------------------------------------------------------
extern "C" void kernel_launch(void* const* d_in, const int* in_sizes, int n_in,
                              void* d_out, int out_size) {
    const float* x      = (const float*)d_in[0];
    const float* Wq     = (const float*)d_in[1];
    const float* Wk     = (const float*)d_in[2];
    const float* Wv     = (const float*)d_in[3];
    const float* proj_w = (const float*)d_in[4];
    const float* proj_b = (const float*)d_in[5];
    const float* ln1_g  = (const float*)d_in[6];
    const float* ln1_b  = (const float*)d_in[7];
    const float* w1     = (const float*)d_in[8];
    const float* b1     = (const float*)d_in[9];
    const float* w2     = (const float*)d_in[10];
    const float* b2     = (const float*)d_in[11];
    const float* ln2_g  = (const float*)d_in[12];
    const float* ln2_b  = (const float*)d_in[13];
    float* out = (float*)d_out;

    __half *qh, *kh, *vh, *attnh, *x1h, *xh, *hh;
    __half *wqh, *wkh, *wvh, *projh, *w1h, *w2h;
    float *tmp, *x1;
    cudaGetSymbolAddress((void**)&qh,    g_qh);
    cudaGetSymbolAddress((void**)&kh,    g_kh);
    cudaGetSymbolAddress((void**)&vh,    g_vh);
    cudaGetSymbolAddress((void**)&attnh, g_attnh);
    cudaGetSymbolAddress((void**)&x1h,   g_x1h);
    cudaGetSymbolAddress((void**)&xh,    g_xh);
    cudaGetSymbolAddress((void**)&hh,    g_hh);
    cudaGetSymbolAddress((void**)&wqh,   g_wqh);
    cudaGetSymbolAddress((void**)&wkh,   g_wkh);
    cudaGetSymbolAddress((void**)&wvh,   g_wvh);
    cudaGetSymbolAddress((void**)&projh, g_projh);
    cudaGetSymbolAddress((void**)&w1h,   g_w1h);
    cudaGetSymbolAddress((void**)&w2h,   g_w2h);
    cudaGetSymbolAddress((void**)&tmp,   g_tmp);
    cudaGetSymbolAddress((void**)&x1,    g_x1);

    static bool attr_done = false;
    if (!attr_done) {
        cudaFuncSetAttribute((const void*)hgemm_kernel<false, false, 3, true>,
                             cudaFuncAttributeMaxDynamicSharedMemorySize, GSMEM);
        cudaFuncSetAttribute((const void*)hgemm_kernel<true, false, 1, false>,
                             cudaFuncAttributeMaxDynamicSharedMemorySize, GSMEM);
        cudaFuncSetAttribute((const void*)hgemm_kernel<true, true, 1, true>,
                             cudaFuncAttributeMaxDynamicSharedMemorySize, GSMEM);
        attr_done = true;
    }

    // ---- convert GEMM operands to half ----
    {
        int n4x = MROWS * EE / 4;
        tohalf_kernel<<<(n4x + 255) / 256, 256>>>(x, xh, n4x);
        int n4w = NH * HD * EE / 4;
        tohalf_kernel<<<(n4w + 255) / 256, 256>>>(Wq, wqh, n4w);
        tohalf_kernel<<<(n4w + 255) / 256, 256>>>(Wk, wkh, n4w);
        tohalf_kernel<<<(n4w + 255) / 256, 256>>>(Wv, wvh, n4w);
        int n4p = EE * EE / 4;
        tohalf_kernel<<<(n4p + 255) / 256, 256>>>(proj_w, projh, n4p);
        int n4f = FFD * EE / 4;
        tohalf_kernel<<<(n4f + 255) / 256, 256>>>(w1, w1h, n4f);
        tohalf_kernel<<<(n4f + 255) / 256, 256>>>(w2, w2h, n4f);
    }

    dim3 gQKV(EE / 128, MROWS / 128, 3);
    dim3 gE(EE / 128, MROWS / 128, 1);
    dim3 gF(FFD / 128, MROWS / 128, 1);

    // Fused QKV projections (fp16 MMA, half outputs feed attention)
    hgemm_kernel<false, false, 3, true><<<gQKV, 256, GSMEM>>>(
        xh, wqh, wkh, wvh, nullptr, qh, kh, vh, MROWS, EE, EE);

    // Causal attention (fp16 MMA)
    attn_h_kernel<<<dim3(TT / 64, BB * NH), 128>>>(qh, kh, vh, attnh);

    // Output projection + bias (float out -> LN)
    hgemm_kernel<true, false, 1, false><<<gE, 256, GSMEM>>>(
        attnh, projh, projh, projh, proj_b, tmp, tmp, tmp, MROWS, EE, EE);
    ln_kernel<true><<<MROWS, 256>>>(tmp, x, ln1_g, ln1_b, x1, x1h);

    // FFN
    hgemm_kernel<true, true, 1, true><<<gF, 256, GSMEM>>>(
        x1h, w1h, w1h, w1h, b1, hh, hh, hh, MROWS, FFD, EE);
    hgemm_kernel<true, false, 1, false><<<gE, 256, GSMEM>>>(
        hh, w2h, w2h, w2h, b2, tmp, tmp, tmp, MROWS, EE, FFD);
    ln_kernel<false><<<MROWS, 256>>>(tmp, x1, ln2_g, ln2_b, out, nullptr);
}

// round 7
// speedup vs baseline: 5.7392x; 1.1026x over previous
#include <cuda_runtime.h>
#include <cuda_fp16.h>
#include <math.h>
#include <stdint.h>

// Problem constants
#define BB 2
#define TT 2048
#define EE 768
#define NH 12
#define HD 64
#define FFD 3072
#define MROWS (BB * TT)   // 4096
#define LN_EPS 1e-5f

// ---------------------------------------------------------------------------
// Scratch (no allocation allowed -> __device__ globals)
// ---------------------------------------------------------------------------
__device__ __half g_qh[MROWS * EE];
__device__ __half g_kh[MROWS * EE];
__device__ __half g_vh[MROWS * EE];
__device__ __half g_attnh[MROWS * EE];
__device__ __half g_x1h[MROWS * EE];
__device__ __half g_xh[MROWS * EE];
__device__ __half g_hh[MROWS * FFD];
__device__ __half g_wqh[NH * HD * EE];
__device__ __half g_wkh[NH * HD * EE];
__device__ __half g_wvh[NH * HD * EE];
__device__ __half g_projh[EE * EE];
__device__ __half g_w1h[FFD * EE];
__device__ __half g_w2h[EE * FFD];
__device__ float g_tmp[MROWS * EE];
__device__ float g_x1[MROWS * EE];

// ---------------------------------------------------------------------------
// Helpers
// ---------------------------------------------------------------------------
__device__ __forceinline__ void mma_f16(float* c, const unsigned* a,
                                        unsigned b0, unsigned b1) {
    asm volatile(
        "mma.sync.aligned.m16n8k16.row.col.f32.f16.f16.f32 "
        "{%0,%1,%2,%3}, {%4,%5,%6,%7}, {%8,%9}, {%0,%1,%2,%3};\n"
        : "+f"(c[0]), "+f"(c[1]), "+f"(c[2]), "+f"(c[3])
        : "r"(a[0]), "r"(a[1]), "r"(a[2]), "r"(a[3]), "r"(b0), "r"(b1));
}

__device__ __forceinline__ void ldsm4(unsigned* r, uint32_t addr) {
    asm volatile("ldmatrix.sync.aligned.m8n8.x4.shared.b16 {%0,%1,%2,%3}, [%4];"
                 : "=r"(r[0]), "=r"(r[1]), "=r"(r[2]), "=r"(r[3]) : "r"(addr));
}
__device__ __forceinline__ void ldsm4t(unsigned* r, uint32_t addr) {
    asm volatile("ldmatrix.sync.aligned.m8n8.x4.trans.shared.b16 {%0,%1,%2,%3}, [%4];"
                 : "=r"(r[0]), "=r"(r[1]), "=r"(r[2]), "=r"(r[3]) : "r"(addr));
}

__device__ __forceinline__ void cp16s(uint32_t s, const void* g) {
    asm volatile("cp.async.cg.shared.global [%0], [%1], 16;\n" :: "r"(s), "l"(g));
}
__device__ __forceinline__ void cp_commit() {
    asm volatile("cp.async.commit_group;\n");
}

__device__ __forceinline__ uint32_t smem_u32(const void* p) {
    return (uint32_t)__cvta_generic_to_shared(p);
}

// ---------------------------------------------------------------------------
// Elementwise float -> half conversion
// ---------------------------------------------------------------------------
__global__ __launch_bounds__(256)
void tohalf_kernel(const float* __restrict__ in, __half* __restrict__ out, int n4) {
    int i = blockIdx.x * 256 + threadIdx.x;
    if (i < n4) {
        float4 v = reinterpret_cast<const float4*>(in)[i];
        __half2 h0 = __floats2half2_rn(v.x, v.y);
        __half2 h1 = __floats2half2_rn(v.z, v.w);
        reinterpret_cast<__half2*>(out)[2 * i]     = h0;
        reinterpret_cast<__half2*>(out)[2 * i + 1] = h1;
    }
}

// ---------------------------------------------------------------------------
// FP16 tensor-core GEMM with ldmatrix: C[M,N] = A[M,K] @ B[N,K]^T
// BM=BN=128, BK=32, 256 threads (8 warps as 4x2, warp tile 32x64), fp32 accum.
// 3-stage cp.async pipeline. SMEM rows: 32 halfs + 8 pad = 80 bytes
// (bank pattern 20r+c conflict-free for both LDS and ldmatrix).
// ---------------------------------------------------------------------------
#define GROWB 80                       // bytes per smem row
#define GSTGB (128 * GROWB)            // 10240 bytes per operand stage
#define GNS 3
#define GSMEM (2 * GNS * GSTGB)        // 61440 bytes

template <bool HAS_BIAS, bool RELU, int NZ, bool OUT_HALF>
__global__ __launch_bounds__(256)
void hgemm_kernel(const __half* __restrict__ A,
                  const __half* __restrict__ B0, const __half* __restrict__ B1,
                  const __half* __restrict__ B2,
                  const float* __restrict__ bias,
                  void* __restrict__ C0v, void* __restrict__ C1v, void* __restrict__ C2v,
                  int M, int N, int K) {
    const __half* B = B0;
    void* Cv = C0v;
    if (NZ == 3) {
        if (blockIdx.z == 1) { B = B1; Cv = C1v; }
        else if (blockIdx.z == 2) { B = B2; Cv = C2v; }
    }

    extern __shared__ char smraw[];
    const uint32_t smb = smem_u32(smraw);
    const int tid  = threadIdx.x;
    const int lane = tid & 31;
    const int warp = tid >> 5;
    const int wm   = warp >> 1;          // 0..3
    const int wn   = warp & 1;           // 0..1
    const int ln4  = lane >> 2;          // 0..7
    const int lm4  = lane & 3;           // 0..3
    const int brow = blockIdx.y * 128;
    const int bcol = blockIdx.x * 128;

    // ldmatrix per-lane base offsets (bytes): row = base + (lane&15), high-half
    // lanes (>=16) read the second 4-word k chunk.
    const uint32_t lm_off = (uint32_t)(lane & 15) * GROWB + ((lane >> 4) << 4);
    const uint32_t a_lm = (uint32_t)(wm * 32) * GROWB + lm_off;   // + stage base
    const uint32_t b_lm = (uint32_t)(wn * 64) * GROWB + lm_off;

    float acc[2][8][4];
#pragma unroll
    for (int mt = 0; mt < 2; mt++)
#pragma unroll
        for (int nt = 0; nt < 8; nt++)
#pragma unroll
            for (int i = 0; i < 4; i++) acc[mt][nt][i] = 0.0f;

    const int nk = K >> 5;               // BK = 32 halfs

    const int lr  = tid >> 1;            // 0..127
    const int lj0 = (tid & 1) * 2;       // chunk base 0 or 2

#define GLOAD(c) do {                                                        \
    const int st_ = (c) % GNS;                                               \
    const uint32_t sa_ = smb + st_ * GSTGB;                                  \
    const uint32_t sb_ = smb + (GNS + st_) * GSTGB;                          \
    const int kb_ = (c) * 32;                                                \
    const __half* gA_ = A + (size_t)(brow + lr) * K + kb_ + lj0 * 8;         \
    const __half* gB_ = B + (size_t)(bcol + lr) * K + kb_ + lj0 * 8;         \
    _Pragma("unroll")                                                        \
    for (int jj = 0; jj < 2; jj++) {                                         \
        cp16s(sa_ + lr * GROWB + (lj0 + jj) * 16, gA_ + jj * 8);             \
        cp16s(sb_ + lr * GROWB + (lj0 + jj) * 16, gB_ + jj * 8);             \
    }                                                                        \
    cp_commit();                                                             \
} while (0)

#pragma unroll
    for (int c = 0; c < GNS - 1; c++) GLOAD(c);

    for (int s = 0; s < nk; s++) {
        const int t = s + GNS - 1;
        if (t < nk) GLOAD(t);
        else cp_commit();
        asm volatile("cp.async.wait_group %0;\n" :: "n"(GNS - 1));
        __syncthreads();

        const int st = s % GNS;
        const uint32_t sa = smb + st * GSTGB + a_lm;
        const uint32_t sb = smb + (GNS + st) * GSTGB + b_lm;
#pragma unroll
        for (int ks = 0; ks < 2; ks++) {  // two k16 chunks per BK32
            unsigned af[2][4];
            ldsm4(af[0], sa + ks * 32);
            ldsm4(af[1], sa + 16 * GROWB + ks * 32);
#pragma unroll
            for (int p = 0; p < 4; p++) {
                unsigned bq[4];
                ldsm4(bq, sb + p * 16 * GROWB + ks * 32);
                mma_f16(acc[0][2 * p],     af[0], bq[0], bq[2]);
                mma_f16(acc[0][2 * p + 1], af[0], bq[1], bq[3]);
                mma_f16(acc[1][2 * p],     af[1], bq[0], bq[2]);
                mma_f16(acc[1][2 * p + 1], af[1], bq[1], bq[3]);
            }
        }
        __syncthreads();
    }

    // epilogue
#pragma unroll
    for (int mt = 0; mt < 2; mt++) {
        const int r = brow + wm * 32 + mt * 16 + ln4;
#pragma unroll
        for (int nt = 0; nt < 8; nt++) {
            const int col = bcol + wn * 64 + nt * 8 + lm4 * 2;
            float2 v0 = make_float2(acc[mt][nt][0], acc[mt][nt][1]);
            float2 v1 = make_float2(acc[mt][nt][2], acc[mt][nt][3]);
            if (HAS_BIAS) {
                float bx = bias[col], by = bias[col + 1];
                v0.x += bx; v0.y += by;
                v1.x += bx; v1.y += by;
            }
            if (RELU) {
                v0.x = fmaxf(v0.x, 0.0f); v0.y = fmaxf(v0.y, 0.0f);
                v1.x = fmaxf(v1.x, 0.0f); v1.y = fmaxf(v1.y, 0.0f);
            }
            if (OUT_HALF) {
                __half* C = (__half*)Cv;
                *reinterpret_cast<__half2*>(C + (size_t)r * N + col) =
                    __floats2half2_rn(v0.x, v0.y);
                *reinterpret_cast<__half2*>(C + (size_t)(r + 8) * N + col) =
                    __floats2half2_rn(v1.x, v1.y);
            } else {
                float* C = (float*)Cv;
                *reinterpret_cast<float2*>(C + (size_t)r * N + col) = v0;
                *reinterpret_cast<float2*>(C + (size_t)(r + 8) * N + col) = v1;
            }
        }
    }
}

// ---------------------------------------------------------------------------
// FP16 causal flash attention with ldmatrix (mma.m16n8k16, fp32 softmax).
// Grid (T/64, B*NH), 128 threads (4 warps); warp w owns query rows w*16..+15.
// K/V tiles of 64 keys. V stored row-major [key][d], read via ldmatrix.trans.
// SMEM rows: 32 words + 4 pad = 36 words (144B) -> conflict-free (4r+c).
// ---------------------------------------------------------------------------
#define ASTRW 36
#define ASTRB 144
#define AROWW (64 * ASTRW)

__global__ __launch_bounds__(128)
void attn_h_kernel(const __half* __restrict__ qp, const __half* __restrict__ kp,
                   const __half* __restrict__ vp, __half* __restrict__ op) {
    __shared__ unsigned Qs[AROWW];   // Q, then P (per-warp private rows)
    __shared__ unsigned Ks[AROWW];
    __shared__ unsigned Vs[AROWW];   // row-major: [key][d halfs]

    const int qt  = blockIdx.x;
    const int bh  = blockIdx.y;
    const int b   = bh / NH;
    const int h   = bh % NH;
    const int tid = threadIdx.x;
    const int lane = tid & 31;
    const int w    = tid >> 5;
    const int ln4  = lane >> 2;      // 0..7
    const int lm4  = lane & 3;       // 0..3
    const int rb   = w * 16;

    const uint32_t smQ = smem_u32(Qs);
    const uint32_t smK = smem_u32(Ks);
    const uint32_t smV = smem_u32(Vs);

    // ldmatrix base offsets
    const uint32_t lm_off = (uint32_t)(lane & 15) * ASTRB + ((lane >> 4) << 4);
    const uint32_t q_lm = smQ + (uint32_t)rb * ASTRB + lm_off;       // Q / P a-frags
    const uint32_t k_lm = smK + lm_off;                              // K b-frags
    // V trans: k row = (lane&7) + 8*(lane>=16); d word = ((lane>>3)&1)*4
    const uint32_t v_lm = smV + ((uint32_t)((lane & 7) + ((lane >> 4) << 3))) * ASTRB
                              + (((lane >> 3) & 1) << 4);

    // ---- Load Q tile (64 rows x 64 halfs) ----
#pragma unroll
    for (int i = 0; i < 4; i++) {
        int idx = tid + i * 128;          // 0..511 (16B chunks)
        int row = idx >> 3;
        int c   = idx & 7;
        uint4 vq = *reinterpret_cast<const uint4*>(
            qp + ((size_t)(b * TT + qt * 64 + row) * EE + h * HD + c * 8));
        *reinterpret_cast<uint4*>(&Qs[row * ASTRW + c * 4]) = vq;
    }
    __syncthreads();

    // ---- Q a-fragments (4 k16 chunks x 4 regs) ----
    unsigned qa[4][4];
#pragma unroll
    for (int ks = 0; ks < 4; ks++) ldsm4(qa[ks], q_lm + ks * 32);

    float o_acc[8][4];
#pragma unroll
    for (int nb = 0; nb < 8; nb++)
#pragma unroll
        for (int i = 0; i < 4; i++) o_acc[nb][i] = 0.0f;
    float m0 = -1e30f, m1 = -1e30f, l0 = 0.0f, l1 = 0.0f;
    const float scale = 0.125f;
    const int row0g = qt * 64 + rb + ln4;
    const int row1g = row0g + 8;

    for (int kt = 0; kt <= qt; kt++) {
        __syncthreads();
        // ---- Load K and V tiles (both row-major, vectorized) ----
#pragma unroll
        for (int i = 0; i < 4; i++) {
            int idx = tid + i * 128;
            int row = idx >> 3;
            int c   = idx & 7;
            size_t g = ((size_t)(b * TT + kt * 64 + row) * EE + h * HD + c * 8);
            *reinterpret_cast<uint4*>(&Ks[row * ASTRW + c * 4]) =
                *reinterpret_cast<const uint4*>(kp + g);
            *reinterpret_cast<uint4*>(&Vs[row * ASTRW + c * 4]) =
                *reinterpret_cast<const uint4*>(vp + g);
        }
        __syncthreads();

        // ---- S = Q K^T : warp computes 16x64 ----
        float s[8][4];
#pragma unroll
        for (int nb = 0; nb < 8; nb++)
#pragma unroll
            for (int i = 0; i < 4; i++) s[nb][i] = 0.0f;
#pragma unroll
        for (int ks = 0; ks < 4; ks++) {
#pragma unroll
            for (int p = 0; p < 4; p++) {
                unsigned bq[4];
                ldsm4(bq, k_lm + p * 16 * ASTRB + ks * 32);
                mma_f16(s[2 * p],     qa[ks], bq[0], bq[2]);
                mma_f16(s[2 * p + 1], qa[ks], bq[1], bq[3]);
            }
        }

        // ---- scale + causal mask (diagonal tile only) ----
        if (kt == qt) {
#pragma unroll
            for (int nb = 0; nb < 8; nb++) {
                int c0 = kt * 64 + nb * 8 + lm4 * 2;
                s[nb][0] = (c0     > row0g) ? -1e30f : s[nb][0] * scale;
                s[nb][1] = (c0 + 1 > row0g) ? -1e30f : s[nb][1] * scale;
                s[nb][2] = (c0     > row1g) ? -1e30f : s[nb][2] * scale;
                s[nb][3] = (c0 + 1 > row1g) ? -1e30f : s[nb][3] * scale;
            }
        } else {
#pragma unroll
            for (int nb = 0; nb < 8; nb++)
#pragma unroll
                for (int i = 0; i < 4; i++) s[nb][i] *= scale;
        }

        // ---- online softmax (fp32) ----
        float mx0 = -1e30f, mx1 = -1e30f;
#pragma unroll
        for (int nb = 0; nb < 8; nb++) {
            mx0 = fmaxf(mx0, fmaxf(s[nb][0], s[nb][1]));
            mx1 = fmaxf(mx1, fmaxf(s[nb][2], s[nb][3]));
        }
        mx0 = fmaxf(mx0, __shfl_xor_sync(0xffffffffu, mx0, 1));
        mx0 = fmaxf(mx0, __shfl_xor_sync(0xffffffffu, mx0, 2));
        mx1 = fmaxf(mx1, __shfl_xor_sync(0xffffffffu, mx1, 1));
        mx1 = fmaxf(mx1, __shfl_xor_sync(0xffffffffu, mx1, 2));
        float mn0 = fmaxf(m0, mx0), mn1 = fmaxf(m1, mx1);
        float alpha0 = __expf(m0 - mn0), alpha1 = __expf(m1 - mn1);
        float sum0 = 0.0f, sum1 = 0.0f;
#pragma unroll
        for (int nb = 0; nb < 8; nb++) {
            float p00 = __expf(s[nb][0] - mn0);
            float p01 = __expf(s[nb][1] - mn0);
            float p10 = __expf(s[nb][2] - mn1);
            float p11 = __expf(s[nb][3] - mn1);
            sum0 += p00 + p01;
            sum1 += p10 + p11;
            __half2 hp0 = __floats2half2_rn(p00, p01);
            __half2 hp1 = __floats2half2_rn(p10, p11);
            Qs[(rb + ln4) * ASTRW + nb * 4 + lm4]     = *reinterpret_cast<unsigned*>(&hp0);
            Qs[(rb + ln4 + 8) * ASTRW + nb * 4 + lm4] = *reinterpret_cast<unsigned*>(&hp1);
        }
        sum0 += __shfl_xor_sync(0xffffffffu, sum0, 1);
        sum0 += __shfl_xor_sync(0xffffffffu, sum0, 2);
        sum1 += __shfl_xor_sync(0xffffffffu, sum1, 1);
        sum1 += __shfl_xor_sync(0xffffffffu, sum1, 2);
        l0 = l0 * alpha0 + sum0;
        l1 = l1 * alpha1 + sum1;
        m0 = mn0; m1 = mn1;
#pragma unroll
        for (int nb = 0; nb < 8; nb++) {
            o_acc[nb][0] *= alpha0; o_acc[nb][1] *= alpha0;
            o_acc[nb][2] *= alpha1; o_acc[nb][3] *= alpha1;
        }
        __syncwarp();

        // ---- O += P V : P a-frags via ldsm, V b-frags via ldsm.trans ----
#pragma unroll
        for (int ks = 0; ks < 4; ks++) {
            unsigned pa[4];
            ldsm4(pa, q_lm + ks * 32);
#pragma unroll
            for (int p = 0; p < 4; p++) {
                unsigned vq[4];
                ldsm4t(vq, v_lm + ks * 16 * ASTRB + p * 32);
                mma_f16(o_acc[2 * p],     pa, vq[0], vq[2]);
                mma_f16(o_acc[2 * p + 1], pa, vq[1], vq[3]);
            }
        }
    }

    // ---- write O (half) ----
    float inv0 = 1.0f / l0, inv1 = 1.0f / l1;
#pragma unroll
    for (int nb = 0; nb < 8; nb++) {
        int col = h * HD + nb * 8 + lm4 * 2;
        __half2 v0 = __floats2half2_rn(o_acc[nb][0] * inv0, o_acc[nb][1] * inv0);
        __half2 v1 = __floats2half2_rn(o_acc[nb][2] * inv1, o_acc[nb][3] * inv1);
        *reinterpret_cast<__half2*>(op + (size_t)(b * TT + row0g) * EE + col) = v0;
        *reinterpret_cast<__half2*>(op + (size_t)(b * TT + row1g) * EE + col) = v1;
    }
}

// ---------------------------------------------------------------------------
// Fused residual-add + LayerNorm over E=768. One block per row, 256 threads.
// ---------------------------------------------------------------------------
template <bool HALF_OUT>
__global__ __launch_bounds__(256)
void ln_kernel(const float* __restrict__ a, const float* __restrict__ res,
               const float* __restrict__ g, const float* __restrict__ bt,
               float* __restrict__ out, __half* __restrict__ outh) {
    const int row = blockIdx.x;
    const float* pa = a + (size_t)row * EE;
    const float* pr = res + (size_t)row * EE;
    float vloc[3];
    float s = 0.0f, ss = 0.0f;
#pragma unroll
    for (int i = 0; i < 3; i++) {
        int c = threadIdx.x + i * 256;
        float vv = pa[c] + pr[c];
        vloc[i] = vv;
        s += vv;
        ss += vv * vv;
    }
#pragma unroll
    for (int off = 16; off > 0; off >>= 1) {
        s  += __shfl_xor_sync(0xffffffffu, s, off);
        ss += __shfl_xor_sync(0xffffffffu, ss, off);
    }
    __shared__ float sred[16];
    __shared__ float smu, srstd;
    int w = threadIdx.x >> 5, lane = threadIdx.x & 31;
    if (lane == 0) { sred[w] = s; sred[8 + w] = ss; }
    __syncthreads();
    if (threadIdx.x == 0) {
        float S = 0.0f, SS = 0.0f;
#pragma unroll
        for (int i = 0; i < 8; i++) { S += sred[i]; SS += sred[8 + i]; }
        float mu = S * (1.0f / EE);
        float var = SS * (1.0f / EE) - mu * mu;
        smu = mu;
        srstd = rsqrtf(var + LN_EPS);
    }
    __syncthreads();
    float mu = smu, rstd = srstd;
    float* po = out + (size_t)row * EE;
    __half* ph = HALF_OUT ? (outh + (size_t)row * EE) : nullptr;
#pragma unroll
    for (int i = 0; i < 3; i++) {
        int c = threadIdx.x + i * 256;
        float vv = (vloc[i] - mu) * rstd * g[c] + bt[c];
        po[c] = vv;
        if (HALF_OUT) ph[c] = __float2half_rn(vv);
    }
}

// ---------------------------------------------------------------------------
// Launch
// ---------------------------------------------------------------------------
extern "C" void kernel_launch(void* const* d_in, const int* in_sizes, int n_in,
                              void* d_out, int out_size) {
    const float* x      = (const float*)d_in[0];
    const float* Wq     = (const float*)d_in[1];
    const float* Wk     = (const float*)d_in[2];
    const float* Wv     = (const float*)d_in[3];
    const float* proj_w = (const float*)d_in[4];
    const float* proj_b = (const float*)d_in[5];
    const float* ln1_g  = (const float*)d_in[6];
    const float* ln1_b  = (const float*)d_in[7];
    const float* w1     = (const float*)d_in[8];
    const float* b1     = (const float*)d_in[9];
    const float* w2     = (const float*)d_in[10];
    const float* b2     = (const float*)d_in[11];
    const float* ln2_g  = (const float*)d_in[12];
    const float* ln2_b  = (const float*)d_in[13];
    float* out = (float*)d_out;

    __half *qh, *kh, *vh, *attnh, *x1h, *xh, *hh;
    __half *wqh, *wkh, *wvh, *projh, *w1h, *w2h;
    float *tmp, *x1;
    cudaGetSymbolAddress((void**)&qh,    g_qh);
    cudaGetSymbolAddress((void**)&kh,    g_kh);
    cudaGetSymbolAddress((void**)&vh,    g_vh);
    cudaGetSymbolAddress((void**)&attnh, g_attnh);
    cudaGetSymbolAddress((void**)&x1h,   g_x1h);
    cudaGetSymbolAddress((void**)&xh,    g_xh);
    cudaGetSymbolAddress((void**)&hh,    g_hh);
    cudaGetSymbolAddress((void**)&wqh,   g_wqh);
    cudaGetSymbolAddress((void**)&wkh,   g_wkh);
    cudaGetSymbolAddress((void**)&wvh,   g_wvh);
    cudaGetSymbolAddress((void**)&projh, g_projh);
    cudaGetSymbolAddress((void**)&w1h,   g_w1h);
    cudaGetSymbolAddress((void**)&w2h,   g_w2h);
    cudaGetSymbolAddress((void**)&tmp,   g_tmp);
    cudaGetSymbolAddress((void**)&x1,    g_x1);

    static bool attr_done = false;
    if (!attr_done) {
        cudaFuncSetAttribute((const void*)hgemm_kernel<false, false, 3, true>,
                             cudaFuncAttributeMaxDynamicSharedMemorySize, GSMEM);
        cudaFuncSetAttribute((const void*)hgemm_kernel<true, false, 1, false>,
                             cudaFuncAttributeMaxDynamicSharedMemorySize, GSMEM);
        cudaFuncSetAttribute((const void*)hgemm_kernel<true, true, 1, true>,
                             cudaFuncAttributeMaxDynamicSharedMemorySize, GSMEM);
        attr_done = true;
    }

    // ---- convert GEMM operands to half ----
    {
        int n4x = MROWS * EE / 4;
        tohalf_kernel<<<(n4x + 255) / 256, 256>>>(x, xh, n4x);
        int n4w = NH * HD * EE / 4;
        tohalf_kernel<<<(n4w + 255) / 256, 256>>>(Wq, wqh, n4w);
        tohalf_kernel<<<(n4w + 255) / 256, 256>>>(Wk, wkh, n4w);
        tohalf_kernel<<<(n4w + 255) / 256, 256>>>(Wv, wvh, n4w);
        int n4p = EE * EE / 4;
        tohalf_kernel<<<(n4p + 255) / 256, 256>>>(proj_w, projh, n4p);
        int n4f = FFD * EE / 4;
        tohalf_kernel<<<(n4f + 255) / 256, 256>>>(w1, w1h, n4f);
        tohalf_kernel<<<(n4f + 255) / 256, 256>>>(w2, w2h, n4f);
    }

    dim3 gQKV(EE / 128, MROWS / 128, 3);
    dim3 gE(EE / 128, MROWS / 128, 1);
    dim3 gF(FFD / 128, MROWS / 128, 1);

    // Fused QKV projections (fp16 MMA, half outputs feed attention)
    hgemm_kernel<false, false, 3, true><<<gQKV, 256, GSMEM>>>(
        xh, wqh, wkh, wvh, nullptr, qh, kh, vh, MROWS, EE, EE);

    // Causal attention (fp16 MMA + ldmatrix)
    attn_h_kernel<<<dim3(TT / 64, BB * NH), 128>>>(qh, kh, vh, attnh);

    // Output projection + bias (float out -> LN)
    hgemm_kernel<true, false, 1, false><<<gE, 256, GSMEM>>>(
        attnh, projh, projh, projh, proj_b, tmp, tmp, tmp, MROWS, EE, EE);
    ln_kernel<true><<<MROWS, 256>>>(tmp, x, ln1_g, ln1_b, x1, x1h);

    // FFN
    hgemm_kernel<true, true, 1, true><<<gF, 256, GSMEM>>>(
        x1h, w1h, w1h, w1h, b1, hh, hh, hh, MROWS, FFD, EE);
    hgemm_kernel<true, false, 1, false><<<gE, 256, GSMEM>>>(
        hh, w2h, w2h, w2h, b2, tmp, tmp, tmp, MROWS, EE, FFD);
    ln_kernel<false><<<MROWS, 256>>>(tmp, x1, ln2_g, ln2_b, out, nullptr);
}

// round 8
// speedup vs baseline: 6.3582x; 1.1078x over previous
#include <cuda_runtime.h>
#include <cuda_fp16.h>
#include <math.h>
#include <stdint.h>

// Problem constants
#define BB 2
#define TT 2048
#define EE 768
#define NH 12
#define HD 64
#define FFD 3072
#define MROWS (BB * TT)   // 4096
#define LN_EPS 1e-5f

// ---------------------------------------------------------------------------
// Scratch (no allocation allowed -> __device__ globals)
// ---------------------------------------------------------------------------
__device__ __half g_qh[MROWS * EE];
__device__ __half g_kh[MROWS * EE];
__device__ __half g_vh[MROWS * EE];
__device__ __half g_attnh[MROWS * EE];
__device__ __half g_x1h[MROWS * EE];
__device__ __half g_xh[MROWS * EE];
__device__ __half g_hh[MROWS * FFD];
__device__ __half g_wqh[NH * HD * EE];
__device__ __half g_wkh[NH * HD * EE];
__device__ __half g_wvh[NH * HD * EE];
__device__ __half g_projh[EE * EE];
__device__ __half g_w1h[FFD * EE];
__device__ __half g_w2h[EE * FFD];
__device__ float g_tmp[MROWS * EE];
__device__ float g_x1[MROWS * EE];

// ---------------------------------------------------------------------------
// Helpers
// ---------------------------------------------------------------------------
__device__ __forceinline__ void mma_f16(float* c, const unsigned* a,
                                        unsigned b0, unsigned b1) {
    asm volatile(
        "mma.sync.aligned.m16n8k16.row.col.f32.f16.f16.f32 "
        "{%0,%1,%2,%3}, {%4,%5,%6,%7}, {%8,%9}, {%0,%1,%2,%3};\n"
        : "+f"(c[0]), "+f"(c[1]), "+f"(c[2]), "+f"(c[3])
        : "r"(a[0]), "r"(a[1]), "r"(a[2]), "r"(a[3]), "r"(b0), "r"(b1));
}

__device__ __forceinline__ void ldsm4(unsigned* r, uint32_t addr) {
    asm volatile("ldmatrix.sync.aligned.m8n8.x4.shared.b16 {%0,%1,%2,%3}, [%4];"
                 : "=r"(r[0]), "=r"(r[1]), "=r"(r[2]), "=r"(r[3]) : "r"(addr));
}
__device__ __forceinline__ void ldsm4t(unsigned* r, uint32_t addr) {
    asm volatile("ldmatrix.sync.aligned.m8n8.x4.trans.shared.b16 {%0,%1,%2,%3}, [%4];"
                 : "=r"(r[0]), "=r"(r[1]), "=r"(r[2]), "=r"(r[3]) : "r"(addr));
}

__device__ __forceinline__ void cp16s(uint32_t s, const void* g) {
    asm volatile("cp.async.cg.shared.global [%0], [%1], 16;\n" :: "r"(s), "l"(g));
}
__device__ __forceinline__ void cp_commit() {
    asm volatile("cp.async.commit_group;\n");
}

__device__ __forceinline__ uint32_t smem_u32(const void* p) {
    return (uint32_t)__cvta_generic_to_shared(p);
}

// ---------------------------------------------------------------------------
// Fused float -> half conversion for all 7 operand tensors (one launch).
// ---------------------------------------------------------------------------
#define CN0 (MROWS * EE / 4)      // x
#define CN1 (NH * HD * EE / 4)    // Wq / Wk / Wv
#define CN2 (EE * EE / 4)         // proj_w
#define CN3 (FFD * EE / 4)        // w1 / w2
#define CNTOT (CN0 + 3 * CN1 + CN2 + 2 * CN3)

__global__ __launch_bounds__(256)
void tohalf7_kernel(const float* __restrict__ i0, __half* __restrict__ o0,
                    const float* __restrict__ i1, __half* __restrict__ o1,
                    const float* __restrict__ i2, __half* __restrict__ o2,
                    const float* __restrict__ i3, __half* __restrict__ o3,
                    const float* __restrict__ i4, __half* __restrict__ o4,
                    const float* __restrict__ i5, __half* __restrict__ o5,
                    const float* __restrict__ i6, __half* __restrict__ o6) {
    int i = blockIdx.x * 256 + threadIdx.x;
    const float* in;
    __half* out;
    if (i < CN0) { in = i0; out = o0; }
    else if ((i -= CN0) < CN1) { in = i1; out = o1; }
    else if ((i -= CN1) < CN1) { in = i2; out = o2; }
    else if ((i -= CN1) < CN1) { in = i3; out = o3; }
    else if ((i -= CN1) < CN2) { in = i4; out = o4; }
    else if ((i -= CN2) < CN3) { in = i5; out = o5; }
    else if ((i -= CN3) < CN3) { in = i6; out = o6; }
    else return;
    float4 v = reinterpret_cast<const float4*>(in)[i];
    reinterpret_cast<__half2*>(out)[2 * i]     = __floats2half2_rn(v.x, v.y);
    reinterpret_cast<__half2*>(out)[2 * i + 1] = __floats2half2_rn(v.z, v.w);
}

// ---------------------------------------------------------------------------
// FP16 tensor-core GEMM with ldmatrix: C[M,N] = A[M,K] @ B[N,K]^T
// BM=128, BN template (128 or 64), BK=32, 256 threads, 8 warps as 4x2,
// warp tile 32 x (BN/2), fp32 accum, 3-stage cp.async pipeline.
// SMEM rows: 32 halfs + 8 pad = 80 bytes (conflict-free LDS + ldmatrix).
// ---------------------------------------------------------------------------
#define GROWB 80                       // bytes per smem row
#define GNS 3
#define GSMEM_OF(BN) (GNS * (128 + (BN)) * GROWB)

template <bool HAS_BIAS, bool RELU, int NZ, bool OUT_HALF, int BN>
__global__ __launch_bounds__(256)
void hgemm_kernel(const __half* __restrict__ A,
                  const __half* __restrict__ B0, const __half* __restrict__ B1,
                  const __half* __restrict__ B2,
                  const float* __restrict__ bias,
                  void* __restrict__ C0v, void* __restrict__ C1v, void* __restrict__ C2v,
                  int M, int N, int K) {
    constexpr int WN     = BN / 2;      // warp n extent
    constexpr int NGROUP = WN / 16;     // B ldsm groups per warp
    constexpr int ACCN   = WN / 8;      // acc n tiles per warp
    constexpr int GSTGA  = 128 * GROWB;
    constexpr int GSTGB  = BN * GROWB;

    const __half* B = B0;
    void* Cv = C0v;
    if (NZ == 3) {
        if (blockIdx.z == 1) { B = B1; Cv = C1v; }
        else if (blockIdx.z == 2) { B = B2; Cv = C2v; }
    }

    extern __shared__ char smraw[];
    const uint32_t smb = smem_u32(smraw);
    const int tid  = threadIdx.x;
    const int lane = tid & 31;
    const int warp = tid >> 5;
    const int wm   = warp >> 1;          // 0..3
    const int wn   = warp & 1;           // 0..1
    const int ln4  = lane >> 2;          // 0..7
    const int lm4  = lane & 3;           // 0..3
    const int brow = blockIdx.y * 128;
    const int bcol = blockIdx.x * BN;

    const uint32_t lm_off = (uint32_t)(lane & 15) * GROWB + ((lane >> 4) << 4);
    const uint32_t a_lm = (uint32_t)(wm * 32) * GROWB + lm_off;
    const uint32_t b_lm = (uint32_t)(wn * WN) * GROWB + lm_off;

    float acc[2][ACCN][4];
#pragma unroll
    for (int mt = 0; mt < 2; mt++)
#pragma unroll
        for (int nt = 0; nt < ACCN; nt++)
#pragma unroll
            for (int i = 0; i < 4; i++) acc[mt][nt][i] = 0.0f;

    const int nk = K >> 5;               // BK = 32 halfs

    const int lrA = tid >> 1;            // 0..127
    const int ljA = (tid & 1) * 2;       // chunk base 0 or 2
    const int lrB = tid >> 2;            // 0..63 (BN=64 path)
    const int ljB = tid & 3;             // 0..3

    auto gload = [&](int c) {
        const int st = c % GNS;
        const uint32_t sa = smb + st * GSTGA;
        const uint32_t sb = smb + GNS * GSTGA + st * GSTGB;
        const int kb = c * 32;
        const __half* gA = A + (size_t)(brow + lrA) * K + kb + ljA * 8;
        cp16s(sa + lrA * GROWB + ljA * 16, gA);
        cp16s(sa + lrA * GROWB + (ljA + 1) * 16, gA + 8);
        if (BN == 128) {
            const __half* gB = B + (size_t)(bcol + lrA) * K + kb + ljA * 8;
            cp16s(sb + lrA * GROWB + ljA * 16, gB);
            cp16s(sb + lrA * GROWB + (ljA + 1) * 16, gB + 8);
        } else {
            const __half* gB = B + (size_t)(bcol + lrB) * K + kb + ljB * 8;
            cp16s(sb + lrB * GROWB + ljB * 16, gB);
        }
        cp_commit();
    };

#pragma unroll
    for (int c = 0; c < GNS - 1; c++) gload(c);

    for (int s = 0; s < nk; s++) {
        const int t = s + GNS - 1;
        if (t < nk) gload(t);
        else cp_commit();
        asm volatile("cp.async.wait_group %0;\n" :: "n"(GNS - 1));
        __syncthreads();

        const int st = s % GNS;
        const uint32_t sa = smb + st * GSTGA + a_lm;
        const uint32_t sb = smb + GNS * GSTGA + st * GSTGB + b_lm;
#pragma unroll
        for (int ks = 0; ks < 2; ks++) {  // two k16 chunks per BK32
            unsigned af[2][4];
            ldsm4(af[0], sa + ks * 32);
            ldsm4(af[1], sa + 16 * GROWB + ks * 32);
#pragma unroll
            for (int p = 0; p < NGROUP; p++) {
                unsigned bq[4];
                ldsm4(bq, sb + p * 16 * GROWB + ks * 32);
                mma_f16(acc[0][2 * p],     af[0], bq[0], bq[2]);
                mma_f16(acc[0][2 * p + 1], af[0], bq[1], bq[3]);
                mma_f16(acc[1][2 * p],     af[1], bq[0], bq[2]);
                mma_f16(acc[1][2 * p + 1], af[1], bq[1], bq[3]);
            }
        }
        __syncthreads();
    }

    // epilogue
#pragma unroll
    for (int mt = 0; mt < 2; mt++) {
        const int r = brow + wm * 32 + mt * 16 + ln4;
#pragma unroll
        for (int nt = 0; nt < ACCN; nt++) {
            const int col = bcol + wn * WN + nt * 8 + lm4 * 2;
            float2 v0 = make_float2(acc[mt][nt][0], acc[mt][nt][1]);
            float2 v1 = make_float2(acc[mt][nt][2], acc[mt][nt][3]);
            if (HAS_BIAS) {
                float bx = bias[col], by = bias[col + 1];
                v0.x += bx; v0.y += by;
                v1.x += bx; v1.y += by;
            }
            if (RELU) {
                v0.x = fmaxf(v0.x, 0.0f); v0.y = fmaxf(v0.y, 0.0f);
                v1.x = fmaxf(v1.x, 0.0f); v1.y = fmaxf(v1.y, 0.0f);
            }
            if (OUT_HALF) {
                __half* C = (__half*)Cv;
                *reinterpret_cast<__half2*>(C + (size_t)r * N + col) =
                    __floats2half2_rn(v0.x, v0.y);
                *reinterpret_cast<__half2*>(C + (size_t)(r + 8) * N + col) =
                    __floats2half2_rn(v1.x, v1.y);
            } else {
                float* C = (float*)Cv;
                *reinterpret_cast<float2*>(C + (size_t)r * N + col) = v0;
                *reinterpret_cast<float2*>(C + (size_t)(r + 8) * N + col) = v1;
            }
        }
    }
}

// ---------------------------------------------------------------------------
// FP16 causal flash attention with ldmatrix (mma.m16n8k16, fp32 softmax).
// Q tile = 128 rows (8 warps x 16 rows), K/V tiles of 64 keys.
// Grid (T/128, B*NH), 256 threads. qt order REVERSED (heavy CTAs first).
// V row-major, read via ldmatrix.trans. SMEM rows stride 36 words (144B).
// ---------------------------------------------------------------------------
#define ASTRW 36
#define ASTRB 144

__global__ __launch_bounds__(256)
void attn_h_kernel(const __half* __restrict__ qp, const __half* __restrict__ kp,
                   const __half* __restrict__ vp, __half* __restrict__ op) {
    __shared__ unsigned Qs[128 * ASTRW];   // Q, then P (per-warp private rows)
    __shared__ unsigned Ks[64 * ASTRW];
    __shared__ unsigned Vs[64 * ASTRW];    // row-major: [key][d halfs]

    const int qt  = (gridDim.x - 1) - blockIdx.x;   // reversed: heavy first
    const int bh  = blockIdx.y;
    const int b   = bh / NH;
    const int h   = bh % NH;
    const int tid = threadIdx.x;
    const int lane = tid & 31;
    const int w    = tid >> 5;       // 0..7
    const int ln4  = lane >> 2;      // 0..7
    const int lm4  = lane & 3;       // 0..3
    const int rb   = w * 16;         // warp's query-row base (0..112)

    const uint32_t smQ = smem_u32(Qs);
    const uint32_t smK = smem_u32(Ks);
    const uint32_t smV = smem_u32(Vs);

    const uint32_t lm_off = (uint32_t)(lane & 15) * ASTRB + ((lane >> 4) << 4);
    const uint32_t q_lm = smQ + (uint32_t)rb * ASTRB + lm_off;
    const uint32_t k_lm = smK + lm_off;
    const uint32_t v_lm = smV + ((uint32_t)((lane & 7) + ((lane >> 4) << 3))) * ASTRB
                              + (((lane >> 3) & 1) << 4);

    // ---- Load Q tile (128 rows x 64 halfs): 1024 16B chunks ----
#pragma unroll
    for (int i = 0; i < 4; i++) {
        int idx = tid + i * 256;
        int row = idx >> 3;               // 0..127
        int c   = idx & 7;
        uint4 vq = *reinterpret_cast<const uint4*>(
            qp + ((size_t)(b * TT + qt * 128 + row) * EE + h * HD + c * 8));
        *reinterpret_cast<uint4*>(&Qs[row * ASTRW + c * 4]) = vq;
    }
    __syncthreads();

    // ---- Q a-fragments (4 k16 chunks x 4 regs) ----
    unsigned qa[4][4];
#pragma unroll
    for (int ks = 0; ks < 4; ks++) ldsm4(qa[ks], q_lm + ks * 32);

    float o_acc[8][4];
#pragma unroll
    for (int nb = 0; nb < 8; nb++)
#pragma unroll
        for (int i = 0; i < 4; i++) o_acc[nb][i] = 0.0f;
    float m0 = -1e30f, m1 = -1e30f, l0 = 0.0f, l1 = 0.0f;
    const float scale = 0.125f;
    const int row0g = qt * 128 + rb + ln4;
    const int row1g = row0g + 8;
    const int nkt = 2 * qt + 2;           // 64-key tiles

    for (int kt = 0; kt < nkt; kt++) {
        const int s0 = kt * 64;
        __syncthreads();
        // ---- Load K and V tiles (64 rows x 64 halfs each): 1024 chunks ----
#pragma unroll
        for (int i = 0; i < 2; i++) {
            int idx = tid + i * 256;
            int row = idx >> 3;           // 0..63
            int c   = idx & 7;
            size_t g = ((size_t)(b * TT + s0 + row) * EE + h * HD + c * 8);
            *reinterpret_cast<uint4*>(&Ks[row * ASTRW + c * 4]) =
                *reinterpret_cast<const uint4*>(kp + g);
            *reinterpret_cast<uint4*>(&Vs[row * ASTRW + c * 4]) =
                *reinterpret_cast<const uint4*>(vp + g);
        }
        __syncthreads();

        // ---- S = Q K^T : warp computes 16x64 ----
        float s[8][4];
#pragma unroll
        for (int nb = 0; nb < 8; nb++)
#pragma unroll
            for (int i = 0; i < 4; i++) s[nb][i] = 0.0f;
#pragma unroll
        for (int ks = 0; ks < 4; ks++) {
#pragma unroll
            for (int p = 0; p < 4; p++) {
                unsigned bq[4];
                ldsm4(bq, k_lm + p * 16 * ASTRB + ks * 32);
                mma_f16(s[2 * p],     qa[ks], bq[0], bq[2]);
                mma_f16(s[2 * p + 1], qa[ks], bq[1], bq[3]);
            }
        }

        // ---- scale + causal mask (warp-dependent) ----
        if (s0 + 63 > qt * 128 + rb) {
#pragma unroll
            for (int nb = 0; nb < 8; nb++) {
                int c0 = s0 + nb * 8 + lm4 * 2;
                s[nb][0] = (c0     > row0g) ? -1e30f : s[nb][0] * scale;
                s[nb][1] = (c0 + 1 > row0g) ? -1e30f : s[nb][1] * scale;
                s[nb][2] = (c0     > row1g) ? -1e30f : s[nb][2] * scale;
                s[nb][3] = (c0 + 1 > row1g) ? -1e30f : s[nb][3] * scale;
            }
        } else {
#pragma unroll
            for (int nb = 0; nb < 8; nb++)
#pragma unroll
                for (int i = 0; i < 4; i++) s[nb][i] *= scale;
        }

        // ---- online softmax (fp32) ----
        float mx0 = -1e30f, mx1 = -1e30f;
#pragma unroll
        for (int nb = 0; nb < 8; nb++) {
            mx0 = fmaxf(mx0, fmaxf(s[nb][0], s[nb][1]));
            mx1 = fmaxf(mx1, fmaxf(s[nb][2], s[nb][3]));
        }
        mx0 = fmaxf(mx0, __shfl_xor_sync(0xffffffffu, mx0, 1));
        mx0 = fmaxf(mx0, __shfl_xor_sync(0xffffffffu, mx0, 2));
        mx1 = fmaxf(mx1, __shfl_xor_sync(0xffffffffu, mx1, 1));
        mx1 = fmaxf(mx1, __shfl_xor_sync(0xffffffffu, mx1, 2));
        float mn0 = fmaxf(m0, mx0), mn1 = fmaxf(m1, mx1);
        float alpha0 = __expf(m0 - mn0), alpha1 = __expf(m1 - mn1);
        float sum0 = 0.0f, sum1 = 0.0f;
#pragma unroll
        for (int nb = 0; nb < 8; nb++) {
            float p00 = __expf(s[nb][0] - mn0);
            float p01 = __expf(s[nb][1] - mn0);
            float p10 = __expf(s[nb][2] - mn1);
            float p11 = __expf(s[nb][3] - mn1);
            sum0 += p00 + p01;
            sum1 += p10 + p11;
            __half2 hp0 = __floats2half2_rn(p00, p01);
            __half2 hp1 = __floats2half2_rn(p10, p11);
            Qs[(rb + ln4) * ASTRW + nb * 4 + lm4]     = *reinterpret_cast<unsigned*>(&hp0);
            Qs[(rb + ln4 + 8) * ASTRW + nb * 4 + lm4] = *reinterpret_cast<unsigned*>(&hp1);
        }
        sum0 += __shfl_xor_sync(0xffffffffu, sum0, 1);
        sum0 += __shfl_xor_sync(0xffffffffu, sum0, 2);
        sum1 += __shfl_xor_sync(0xffffffffu, sum1, 1);
        sum1 += __shfl_xor_sync(0xffffffffu, sum1, 2);
        l0 = l0 * alpha0 + sum0;
        l1 = l1 * alpha1 + sum1;
        m0 = mn0; m1 = mn1;
#pragma unroll
        for (int nb = 0; nb < 8; nb++) {
            o_acc[nb][0] *= alpha0; o_acc[nb][1] *= alpha0;
            o_acc[nb][2] *= alpha1; o_acc[nb][3] *= alpha1;
        }
        __syncwarp();

        // ---- O += P V : P a-frags via ldsm, V b-frags via ldsm.trans ----
#pragma unroll
        for (int ks = 0; ks < 4; ks++) {
            unsigned pa[4];
            ldsm4(pa, q_lm + ks * 32);
#pragma unroll
            for (int p = 0; p < 4; p++) {
                unsigned vq[4];
                ldsm4t(vq, v_lm + ks * 16 * ASTRB + p * 32);
                mma_f16(o_acc[2 * p],     pa, vq[0], vq[2]);
                mma_f16(o_acc[2 * p + 1], pa, vq[1], vq[3]);
            }
        }
    }

    // ---- write O (half) ----
    float inv0 = 1.0f / l0, inv1 = 1.0f / l1;
#pragma unroll
    for (int nb = 0; nb < 8; nb++) {
        int col = h * HD + nb * 8 + lm4 * 2;
        __half2 v0 = __floats2half2_rn(o_acc[nb][0] * inv0, o_acc[nb][1] * inv0);
        __half2 v1 = __floats2half2_rn(o_acc[nb][2] * inv1, o_acc[nb][3] * inv1);
        *reinterpret_cast<__half2*>(op + (size_t)(b * TT + row0g) * EE + col) = v0;
        *reinterpret_cast<__half2*>(op + (size_t)(b * TT + row1g) * EE + col) = v1;
    }
}

// ---------------------------------------------------------------------------
// Fused residual-add + LayerNorm over E=768. One block per row, 256 threads.
// ---------------------------------------------------------------------------
template <bool HALF_OUT>
__global__ __launch_bounds__(256)
void ln_kernel(const float* __restrict__ a, const float* __restrict__ res,
               const float* __restrict__ g, const float* __restrict__ bt,
               float* __restrict__ out, __half* __restrict__ outh) {
    const int row = blockIdx.x;
    const float* pa = a + (size_t)row * EE;
    const float* pr = res + (size_t)row * EE;
    float vloc[3];
    float s = 0.0f, ss = 0.0f;
#pragma unroll
    for (int i = 0; i < 3; i++) {
        int c = threadIdx.x + i * 256;
        float vv = pa[c] + pr[c];
        vloc[i] = vv;
        s += vv;
        ss += vv * vv;
    }
#pragma unroll
    for (int off = 16; off > 0; off >>= 1) {
        s  += __shfl_xor_sync(0xffffffffu, s, off);
        ss += __shfl_xor_sync(0xffffffffu, ss, off);
    }
    __shared__ float sred[16];
    __shared__ float smu, srstd;
    int w = threadIdx.x >> 5, lane = threadIdx.x & 31;
    if (lane == 0) { sred[w] = s; sred[8 + w] = ss; }
    __syncthreads();
    if (threadIdx.x == 0) {
        float S = 0.0f, SS = 0.0f;
#pragma unroll
        for (int i = 0; i < 8; i++) { S += sred[i]; SS += sred[8 + i]; }
        float mu = S * (1.0f / EE);
        float var = SS * (1.0f / EE) - mu * mu;
        smu = mu;
        srstd = rsqrtf(var + LN_EPS);
    }
    __syncthreads();
    float mu = smu, rstd = srstd;
    float* po = out + (size_t)row * EE;
    __half* ph = HALF_OUT ? (outh + (size_t)row * EE) : nullptr;
#pragma unroll
    for (int i = 0; i < 3; i++) {
        int c = threadIdx.x + i * 256;
        float vv = (vloc[i] - mu) * rstd * g[c] + bt[c];
        po[c] = vv;
        if (HALF_OUT) ph[c] = __float2half_rn(vv);
    }
}

// ---------------------------------------------------------------------------
// Launch
// ---------------------------------------------------------------------------
extern "C" void kernel_launch(void* const* d_in, const int* in_sizes, int n_in,
                              void* d_out, int out_size) {
    const float* x      = (const float*)d_in[0];
    const float* Wq     = (const float*)d_in[1];
    const float* Wk     = (const float*)d_in[2];
    const float* Wv     = (const float*)d_in[3];
    const float* proj_w = (const float*)d_in[4];
    const float* proj_b = (const float*)d_in[5];
    const float* ln1_g  = (const float*)d_in[6];
    const float* ln1_b  = (const float*)d_in[7];
    const float* w1     = (const float*)d_in[8];
    const float* b1     = (const float*)d_in[9];
    const float* w2     = (const float*)d_in[10];
    const float* b2     = (const float*)d_in[11];
    const float* ln2_g  = (const float*)d_in[12];
    const float* ln2_b  = (const float*)d_in[13];
    float* out = (float*)d_out;

    __half *qh, *kh, *vh, *attnh, *x1h, *xh, *hh;
    __half *wqh, *wkh, *wvh, *projh, *w1h, *w2h;
    float *tmp, *x1;
    cudaGetSymbolAddress((void**)&qh,    g_qh);
    cudaGetSymbolAddress((void**)&kh,    g_kh);
    cudaGetSymbolAddress((void**)&vh,    g_vh);
    cudaGetSymbolAddress((void**)&attnh, g_attnh);
    cudaGetSymbolAddress((void**)&x1h,   g_x1h);
    cudaGetSymbolAddress((void**)&xh,    g_xh);
    cudaGetSymbolAddress((void**)&hh,    g_hh);
    cudaGetSymbolAddress((void**)&wqh,   g_wqh);
    cudaGetSymbolAddress((void**)&wkh,   g_wkh);
    cudaGetSymbolAddress((void**)&wvh,   g_wvh);
    cudaGetSymbolAddress((void**)&projh, g_projh);
    cudaGetSymbolAddress((void**)&w1h,   g_w1h);
    cudaGetSymbolAddress((void**)&w2h,   g_w2h);
    cudaGetSymbolAddress((void**)&tmp,   g_tmp);
    cudaGetSymbolAddress((void**)&x1,    g_x1);

    static bool attr_done = false;
    if (!attr_done) {
        cudaFuncSetAttribute((const void*)hgemm_kernel<false, false, 3, true, 128>,
                             cudaFuncAttributeMaxDynamicSharedMemorySize, GSMEM_OF(128));
        cudaFuncSetAttribute((const void*)hgemm_kernel<true, true, 1, true, 128>,
                             cudaFuncAttributeMaxDynamicSharedMemorySize, GSMEM_OF(128));
        cudaFuncSetAttribute((const void*)hgemm_kernel<true, false, 1, false, 64>,
                             cudaFuncAttributeMaxDynamicSharedMemorySize, GSMEM_OF(64));
        attr_done = true;
    }

    // ---- convert all GEMM operands to half (one launch) ----
    tohalf7_kernel<<<(CNTOT + 255) / 256, 256>>>(
        x, xh, Wq, wqh, Wk, wkh, Wv, wvh, proj_w, projh, w1, w1h, w2, w2h);

    dim3 gQKV(EE / 128, MROWS / 128, 3);    // (6, 32, 3)
    dim3 gE64(EE / 64, MROWS / 128, 1);     // (12, 32)
    dim3 gF(FFD / 128, MROWS / 128, 1);     // (24, 32)

    // Fused QKV projections
    hgemm_kernel<false, false, 3, true, 128><<<gQKV, 256, GSMEM_OF(128)>>>(
        xh, wqh, wkh, wvh, nullptr, qh, kh, vh, MROWS, EE, EE);

    // Causal attention (128-row Q tiles, reversed order)
    attn_h_kernel<<<dim3(TT / 128, BB * NH), 256>>>(qh, kh, vh, attnh);

    // Output projection + bias (BN=64 for balance)
    hgemm_kernel<true, false, 1, false, 64><<<gE64, 256, GSMEM_OF(64)>>>(
        attnh, projh, projh, projh, proj_b, tmp, tmp, tmp, MROWS, EE, EE);
    ln_kernel<true><<<MROWS, 256>>>(tmp, x, ln1_g, ln1_b, x1, x1h);

    // FFN
    hgemm_kernel<true, true, 1, true, 128><<<gF, 256, GSMEM_OF(128)>>>(
        x1h, w1h, w1h, w1h, b1, hh, hh, hh, MROWS, FFD, EE);
    hgemm_kernel<true, false, 1, false, 64><<<gE64, 256, GSMEM_OF(64)>>>(
        hh, w2h, w2h, w2h, b2, tmp, tmp, tmp, MROWS, EE, FFD);
    ln_kernel<false><<<MROWS, 256>>>(tmp, x1, ln2_g, ln2_b, out, nullptr);
}

// round 9
// speedup vs baseline: 6.4701x; 1.0176x over previous
#include <cuda_runtime.h>
#include <cuda_fp16.h>
#include <math.h>
#include <stdint.h>

// Problem constants
#define BB 2
#define TT 2048
#define EE 768
#define NH 12
#define HD 64
#define FFD 3072
#define MROWS (BB * TT)   // 4096
#define LN_EPS 1e-5f

// ---------------------------------------------------------------------------
// Scratch (no allocation allowed -> __device__ globals)
// ---------------------------------------------------------------------------
__device__ __half g_qh[MROWS * EE];
__device__ __half g_kh[MROWS * EE];
__device__ __half g_vh[MROWS * EE];
__device__ __half g_attnh[MROWS * EE];
__device__ __half g_x1h[MROWS * EE];
__device__ __half g_xh[MROWS * EE];
__device__ __half g_hh[MROWS * FFD];
__device__ __half g_wqh[NH * HD * EE];
__device__ __half g_wkh[NH * HD * EE];
__device__ __half g_wvh[NH * HD * EE];
__device__ __half g_projh[EE * EE];
__device__ __half g_w1h[FFD * EE];
__device__ __half g_w2h[EE * FFD];
__device__ float g_tmp[MROWS * EE];
__device__ float g_x1[MROWS * EE];

// ---------------------------------------------------------------------------
// Helpers
// ---------------------------------------------------------------------------
__device__ __forceinline__ void mma_f16(float* c, const unsigned* a,
                                        unsigned b0, unsigned b1) {
    asm volatile(
        "mma.sync.aligned.m16n8k16.row.col.f32.f16.f16.f32 "
        "{%0,%1,%2,%3}, {%4,%5,%6,%7}, {%8,%9}, {%0,%1,%2,%3};\n"
        : "+f"(c[0]), "+f"(c[1]), "+f"(c[2]), "+f"(c[3])
        : "r"(a[0]), "r"(a[1]), "r"(a[2]), "r"(a[3]), "r"(b0), "r"(b1));
}

__device__ __forceinline__ void ldsm4(unsigned* r, uint32_t addr) {
    asm volatile("ldmatrix.sync.aligned.m8n8.x4.shared.b16 {%0,%1,%2,%3}, [%4];"
                 : "=r"(r[0]), "=r"(r[1]), "=r"(r[2]), "=r"(r[3]) : "r"(addr));
}
__device__ __forceinline__ void ldsm4t(unsigned* r, uint32_t addr) {
    asm volatile("ldmatrix.sync.aligned.m8n8.x4.trans.shared.b16 {%0,%1,%2,%3}, [%4];"
                 : "=r"(r[0]), "=r"(r[1]), "=r"(r[2]), "=r"(r[3]) : "r"(addr));
}

__device__ __forceinline__ void cp16s(uint32_t s, const void* g) {
    asm volatile("cp.async.cg.shared.global [%0], [%1], 16;\n" :: "r"(s), "l"(g));
}
__device__ __forceinline__ void cp_commit() {
    asm volatile("cp.async.commit_group;\n");
}

__device__ __forceinline__ uint32_t smem_u32(const void* p) {
    return (uint32_t)__cvta_generic_to_shared(p);
}

// ---------------------------------------------------------------------------
// Fused float -> half conversion for all 7 operand tensors (one launch).
// ---------------------------------------------------------------------------
#define CN0 (MROWS * EE / 4)      // x
#define CN1 (NH * HD * EE / 4)    // Wq / Wk / Wv
#define CN2 (EE * EE / 4)         // proj_w
#define CN3 (FFD * EE / 4)        // w1 / w2
#define CNTOT (CN0 + 3 * CN1 + CN2 + 2 * CN3)

__global__ __launch_bounds__(256)
void tohalf7_kernel(const float* __restrict__ i0, __half* __restrict__ o0,
                    const float* __restrict__ i1, __half* __restrict__ o1,
                    const float* __restrict__ i2, __half* __restrict__ o2,
                    const float* __restrict__ i3, __half* __restrict__ o3,
                    const float* __restrict__ i4, __half* __restrict__ o4,
                    const float* __restrict__ i5, __half* __restrict__ o5,
                    const float* __restrict__ i6, __half* __restrict__ o6) {
    int i = blockIdx.x * 256 + threadIdx.x;
    const float* in;
    __half* out;
    if (i < CN0) { in = i0; out = o0; }
    else if ((i -= CN0) < CN1) { in = i1; out = o1; }
    else if ((i -= CN1) < CN1) { in = i2; out = o2; }
    else if ((i -= CN1) < CN1) { in = i3; out = o3; }
    else if ((i -= CN1) < CN2) { in = i4; out = o4; }
    else if ((i -= CN2) < CN3) { in = i5; out = o5; }
    else if ((i -= CN3) < CN3) { in = i6; out = o6; }
    else return;
    float4 v = reinterpret_cast<const float4*>(in)[i];
    reinterpret_cast<__half2*>(out)[2 * i]     = __floats2half2_rn(v.x, v.y);
    reinterpret_cast<__half2*>(out)[2 * i + 1] = __floats2half2_rn(v.z, v.w);
}

// ---------------------------------------------------------------------------
// FP16 tensor-core GEMM with ldmatrix: C[M,N] = A[M,K] @ B[N,K]^T
// BM=128, BN template (128 or 64), BK=32, 256 threads, 8 warps as 4x2.
// SINGLE-barrier 3-stage cp.async pipeline:
//   bar -> issue load(s+NS-1) -> compute(s) -> wait_group(NS-2)
// The end-of-iter wait makes chunk s+1 resident before the next barrier
// (visibility), and the barrier orders compute(s-1) before its stage is
// overwritten by load(s+NS-1) (WAR).
// ---------------------------------------------------------------------------
#define GROWB 80                       // bytes per smem row
#define GNS 3
#define GSMEM_OF(BN) (GNS * (128 + (BN)) * GROWB)

template <bool HAS_BIAS, bool RELU, int NZ, bool OUT_HALF, int BN>
__global__ __launch_bounds__(256)
void hgemm_kernel(const __half* __restrict__ A,
                  const __half* __restrict__ B0, const __half* __restrict__ B1,
                  const __half* __restrict__ B2,
                  const float* __restrict__ bias,
                  void* __restrict__ C0v, void* __restrict__ C1v, void* __restrict__ C2v,
                  int M, int N, int K) {
    constexpr int WN     = BN / 2;      // warp n extent
    constexpr int NGROUP = WN / 16;     // B ldsm groups per warp
    constexpr int ACCN   = WN / 8;      // acc n tiles per warp
    constexpr int GSTGA  = 128 * GROWB;
    constexpr int GSTGB  = BN * GROWB;

    const __half* B = B0;
    void* Cv = C0v;
    if (NZ == 3) {
        if (blockIdx.z == 1) { B = B1; Cv = C1v; }
        else if (blockIdx.z == 2) { B = B2; Cv = C2v; }
    }

    extern __shared__ char smraw[];
    const uint32_t smb = smem_u32(smraw);
    const int tid  = threadIdx.x;
    const int lane = tid & 31;
    const int warp = tid >> 5;
    const int wm   = warp >> 1;          // 0..3
    const int wn   = warp & 1;           // 0..1
    const int ln4  = lane >> 2;          // 0..7
    const int lm4  = lane & 3;           // 0..3
    const int brow = blockIdx.y * 128;
    const int bcol = blockIdx.x * BN;

    const uint32_t lm_off = (uint32_t)(lane & 15) * GROWB + ((lane >> 4) << 4);
    const uint32_t a_lm = (uint32_t)(wm * 32) * GROWB + lm_off;
    const uint32_t b_lm = (uint32_t)(wn * WN) * GROWB + lm_off;

    float acc[2][ACCN][4];
#pragma unroll
    for (int mt = 0; mt < 2; mt++)
#pragma unroll
        for (int nt = 0; nt < ACCN; nt++)
#pragma unroll
            for (int i = 0; i < 4; i++) acc[mt][nt][i] = 0.0f;

    const int nk = K >> 5;               // BK = 32 halfs

    const int lrA = tid >> 1;            // 0..127
    const int ljA = (tid & 1) * 2;       // chunk base 0 or 2
    const int lrB = tid >> 2;            // 0..63 (BN=64 path)
    const int ljB = tid & 3;             // 0..3

    auto gload = [&](int c) {
        const int st = c % GNS;
        const uint32_t sa = smb + st * GSTGA;
        const uint32_t sb = smb + GNS * GSTGA + st * GSTGB;
        const int kb = c * 32;
        const __half* gA = A + (size_t)(brow + lrA) * K + kb + ljA * 8;
        cp16s(sa + lrA * GROWB + ljA * 16, gA);
        cp16s(sa + lrA * GROWB + (ljA + 1) * 16, gA + 8);
        if (BN == 128) {
            const __half* gB = B + (size_t)(bcol + lrA) * K + kb + ljA * 8;
            cp16s(sb + lrA * GROWB + ljA * 16, gB);
            cp16s(sb + lrA * GROWB + (ljA + 1) * 16, gB + 8);
        } else {
            const __half* gB = B + (size_t)(bcol + lrB) * K + kb + ljB * 8;
            cp16s(sb + lrB * GROWB + ljB * 16, gB);
        }
        cp_commit();
    };

    // prologue: chunks 0..NS-2, then ensure chunk 0 resident
#pragma unroll
    for (int c = 0; c < GNS - 1; c++) gload(c);
    asm volatile("cp.async.wait_group %0;\n" :: "n"(GNS - 2));

    for (int s = 0; s < nk; s++) {
        __syncthreads();                 // chunk s visible; stage (s-1)%NS safe to overwrite
        const int t = s + GNS - 1;
        if (t < nk) gload(t);
        else cp_commit();

        const int st = s % GNS;
        const uint32_t sa = smb + st * GSTGA + a_lm;
        const uint32_t sb = smb + GNS * GSTGA + st * GSTGB + b_lm;
#pragma unroll
        for (int ks = 0; ks < 2; ks++) {  // two k16 chunks per BK32
            unsigned af[2][4];
            ldsm4(af[0], sa + ks * 32);
            ldsm4(af[1], sa + 16 * GROWB + ks * 32);
#pragma unroll
            for (int p = 0; p < NGROUP; p++) {
                unsigned bq[4];
                ldsm4(bq, sb + p * 16 * GROWB + ks * 32);
                mma_f16(acc[0][2 * p],     af[0], bq[0], bq[2]);
                mma_f16(acc[0][2 * p + 1], af[0], bq[1], bq[3]);
                mma_f16(acc[1][2 * p],     af[1], bq[0], bq[2]);
                mma_f16(acc[1][2 * p + 1], af[1], bq[1], bq[3]);
            }
        }
        asm volatile("cp.async.wait_group %0;\n" :: "n"(GNS - 2));  // chunk s+1 resident
    }

    // epilogue
#pragma unroll
    for (int mt = 0; mt < 2; mt++) {
        const int r = brow + wm * 32 + mt * 16 + ln4;
#pragma unroll
        for (int nt = 0; nt < ACCN; nt++) {
            const int col = bcol + wn * WN + nt * 8 + lm4 * 2;
            float2 v0 = make_float2(acc[mt][nt][0], acc[mt][nt][1]);
            float2 v1 = make_float2(acc[mt][nt][2], acc[mt][nt][3]);
            if (HAS_BIAS) {
                float bx = bias[col], by = bias[col + 1];
                v0.x += bx; v0.y += by;
                v1.x += bx; v1.y += by;
            }
            if (RELU) {
                v0.x = fmaxf(v0.x, 0.0f); v0.y = fmaxf(v0.y, 0.0f);
                v1.x = fmaxf(v1.x, 0.0f); v1.y = fmaxf(v1.y, 0.0f);
            }
            if (OUT_HALF) {
                __half* C = (__half*)Cv;
                *reinterpret_cast<__half2*>(C + (size_t)r * N + col) =
                    __floats2half2_rn(v0.x, v0.y);
                *reinterpret_cast<__half2*>(C + (size_t)(r + 8) * N + col) =
                    __floats2half2_rn(v1.x, v1.y);
            } else {
                float* C = (float*)Cv;
                *reinterpret_cast<float2*>(C + (size_t)r * N + col) = v0;
                *reinterpret_cast<float2*>(C + (size_t)(r + 8) * N + col) = v1;
            }
        }
    }
}

// ---------------------------------------------------------------------------
// FP16 causal flash attention (mma.m16n8k16, fp32 softmax), cp.async
// double-buffered K/V (same single-barrier schedule as the GEMM).
// Q tile = 128 rows (8 warps x 16 rows), K/V tiles of 64 keys.
// Grid (T/128, B*NH), 256 threads, qt order reversed (heavy CTAs first).
// Dynamic SMEM: Q/P (128 rows) + 2x K (64) + 2x V (64), stride 36 words.
// ---------------------------------------------------------------------------
#define ASTRW 36
#define ASTRB 144
#define AQW (128 * ASTRW)
#define AKVW (64 * ASTRW)
#define ATT_SMEM ((AQW + 4 * AKVW) * 4)   // 55296 bytes

__global__ __launch_bounds__(256)
void attn_h_kernel(const __half* __restrict__ qp, const __half* __restrict__ kp,
                   const __half* __restrict__ vp, __half* __restrict__ op) {
    extern __shared__ unsigned asm_[];
    unsigned* Qs = asm_;                     // Q, then P (per-warp private rows)
    unsigned* Ks = asm_ + AQW;               // 2 stages
    unsigned* Vs = asm_ + AQW + 2 * AKVW;    // 2 stages

    const int qt  = (gridDim.x - 1) - blockIdx.x;   // reversed: heavy first
    const int bh  = blockIdx.y;
    const int b   = bh / NH;
    const int h   = bh % NH;
    const int tid = threadIdx.x;
    const int lane = tid & 31;
    const int w    = tid >> 5;       // 0..7
    const int ln4  = lane >> 2;      // 0..7
    const int lm4  = lane & 3;       // 0..3
    const int rb   = w * 16;         // warp's query-row base (0..112)

    const uint32_t smQ = smem_u32(Qs);
    const uint32_t smK = smem_u32(Ks);
    const uint32_t smV = smem_u32(Vs);

    const uint32_t lm_off = (uint32_t)(lane & 15) * ASTRB + ((lane >> 4) << 4);
    const uint32_t q_lm = smQ + (uint32_t)rb * ASTRB + lm_off;
    const uint32_t k_lm = smK + lm_off;
    const uint32_t v_lm = smV + ((uint32_t)((lane & 7) + ((lane >> 4) << 3))) * ASTRB
                              + (((lane >> 3) & 1) << 4);

    // K/V tile loader: 64 rows x 64 halfs each via cp.async (one commit group)
    const int lrKV = tid >> 2;           // 0..63
    const int ljKV = tid & 3;            // 0..3 (2 chunks each of K and V)
    auto kvload = [&](int kt) {
        const int st = kt & 1;
        const uint32_t sk = smK + st * (AKVW * 4);
        const uint32_t sv = smV + st * (AKVW * 4);
        size_t g = ((size_t)(b * TT + kt * 64 + lrKV) * EE + h * HD + ljKV * 16);
        const uint32_t so = (uint32_t)lrKV * ASTRB + ljKV * 32;
        cp16s(sk + so,      kp + g);
        cp16s(sk + so + 16, kp + g + 8);
        cp16s(sv + so,      vp + g);
        cp16s(sv + so + 16, vp + g + 8);
        cp_commit();
    };

    const int nkt = 2 * qt + 2;          // 64-key tiles

    // ---- prologue: start K/V tile 0, then load Q (plain) ----
    kvload(0);
#pragma unroll
    for (int i = 0; i < 4; i++) {
        int idx = tid + i * 256;
        int row = idx >> 3;               // 0..127
        int c   = idx & 7;
        uint4 vq = *reinterpret_cast<const uint4*>(
            qp + ((size_t)(b * TT + qt * 128 + row) * EE + h * HD + c * 8));
        *reinterpret_cast<uint4*>(&Qs[row * ASTRW + c * 4]) = vq;
    }
    asm volatile("cp.async.wait_group 0;\n");   // tile 0 resident (this thread)
    __syncthreads();                            // Q + tile 0 visible block-wide

    // ---- Q a-fragments (4 k16 chunks x 4 regs) ----
    unsigned qa[4][4];
#pragma unroll
    for (int ks = 0; ks < 4; ks++) ldsm4(qa[ks], q_lm + ks * 32);

    float o_acc[8][4];
#pragma unroll
    for (int nb = 0; nb < 8; nb++)
#pragma unroll
        for (int i = 0; i < 4; i++) o_acc[nb][i] = 0.0f;
    float m0 = -1e30f, m1 = -1e30f, l0 = 0.0f, l1 = 0.0f;
    const float scale = 0.125f;
    const int row0g = qt * 128 + rb + ln4;
    const int row1g = row0g + 8;

    for (int kt = 0; kt < nkt; kt++) {
        if (kt) __syncthreads();         // tile kt visible; buf (kt+1)&1 safe to overwrite
        if (kt + 1 < nkt) kvload(kt + 1);
        else cp_commit();

        const uint32_t kb_ = k_lm + (kt & 1) * (AKVW * 4);
        const uint32_t vb_ = v_lm + (kt & 1) * (AKVW * 4);
        const int s0 = kt * 64;

        // ---- S = Q K^T : warp computes 16x64 ----
        float s[8][4];
#pragma unroll
        for (int nb = 0; nb < 8; nb++)
#pragma unroll
            for (int i = 0; i < 4; i++) s[nb][i] = 0.0f;
#pragma unroll
        for (int ks = 0; ks < 4; ks++) {
#pragma unroll
            for (int p = 0; p < 4; p++) {
                unsigned bq[4];
                ldsm4(bq, kb_ + p * 16 * ASTRB + ks * 32);
                mma_f16(s[2 * p],     qa[ks], bq[0], bq[2]);
                mma_f16(s[2 * p + 1], qa[ks], bq[1], bq[3]);
            }
        }

        // ---- scale + causal mask (warp-dependent) ----
        if (s0 + 63 > qt * 128 + rb) {
#pragma unroll
            for (int nb = 0; nb < 8; nb++) {
                int c0 = s0 + nb * 8 + lm4 * 2;
                s[nb][0] = (c0     > row0g) ? -1e30f : s[nb][0] * scale;
                s[nb][1] = (c0 + 1 > row0g) ? -1e30f : s[nb][1] * scale;
                s[nb][2] = (c0     > row1g) ? -1e30f : s[nb][2] * scale;
                s[nb][3] = (c0 + 1 > row1g) ? -1e30f : s[nb][3] * scale;
            }
        } else {
#pragma unroll
            for (int nb = 0; nb < 8; nb++)
#pragma unroll
                for (int i = 0; i < 4; i++) s[nb][i] *= scale;
        }

        // ---- online softmax (fp32) ----
        float mx0 = -1e30f, mx1 = -1e30f;
#pragma unroll
        for (int nb = 0; nb < 8; nb++) {
            mx0 = fmaxf(mx0, fmaxf(s[nb][0], s[nb][1]));
            mx1 = fmaxf(mx1, fmaxf(s[nb][2], s[nb][3]));
        }
        mx0 = fmaxf(mx0, __shfl_xor_sync(0xffffffffu, mx0, 1));
        mx0 = fmaxf(mx0, __shfl_xor_sync(0xffffffffu, mx0, 2));
        mx1 = fmaxf(mx1, __shfl_xor_sync(0xffffffffu, mx1, 1));
        mx1 = fmaxf(mx1, __shfl_xor_sync(0xffffffffu, mx1, 2));
        float mn0 = fmaxf(m0, mx0), mn1 = fmaxf(m1, mx1);
        float alpha0 = __expf(m0 - mn0), alpha1 = __expf(m1 - mn1);
        float sum0 = 0.0f, sum1 = 0.0f;
#pragma unroll
        for (int nb = 0; nb < 8; nb++) {
            float p00 = __expf(s[nb][0] - mn0);
            float p01 = __expf(s[nb][1] - mn0);
            float p10 = __expf(s[nb][2] - mn1);
            float p11 = __expf(s[nb][3] - mn1);
            sum0 += p00 + p01;
            sum1 += p10 + p11;
            __half2 hp0 = __floats2half2_rn(p00, p01);
            __half2 hp1 = __floats2half2_rn(p10, p11);
            Qs[(rb + ln4) * ASTRW + nb * 4 + lm4]     = *reinterpret_cast<unsigned*>(&hp0);
            Qs[(rb + ln4 + 8) * ASTRW + nb * 4 + lm4] = *reinterpret_cast<unsigned*>(&hp1);
        }
        sum0 += __shfl_xor_sync(0xffffffffu, sum0, 1);
        sum0 += __shfl_xor_sync(0xffffffffu, sum0, 2);
        sum1 += __shfl_xor_sync(0xffffffffu, sum1, 1);
        sum1 += __shfl_xor_sync(0xffffffffu, sum1, 2);
        l0 = l0 * alpha0 + sum0;
        l1 = l1 * alpha1 + sum1;
        m0 = mn0; m1 = mn1;
#pragma unroll
        for (int nb = 0; nb < 8; nb++) {
            o_acc[nb][0] *= alpha0; o_acc[nb][1] *= alpha0;
            o_acc[nb][2] *= alpha1; o_acc[nb][3] *= alpha1;
        }
        __syncwarp();

        // ---- O += P V : P a-frags via ldsm, V b-frags via ldsm.trans ----
#pragma unroll
        for (int ks = 0; ks < 4; ks++) {
            unsigned pa[4];
            ldsm4(pa, q_lm + ks * 32);
#pragma unroll
            for (int p = 0; p < 4; p++) {
                unsigned vq[4];
                ldsm4t(vq, vb_ + ks * 16 * ASTRB + p * 32);
                mma_f16(o_acc[2 * p],     pa, vq[0], vq[2]);
                mma_f16(o_acc[2 * p + 1], pa, vq[1], vq[3]);
            }
        }
        asm volatile("cp.async.wait_group 0;\n");   // tile kt+1 resident
    }

    // ---- write O (half) ----
    float inv0 = 1.0f / l0, inv1 = 1.0f / l1;
#pragma unroll
    for (int nb = 0; nb < 8; nb++) {
        int col = h * HD + nb * 8 + lm4 * 2;
        __half2 v0 = __floats2half2_rn(o_acc[nb][0] * inv0, o_acc[nb][1] * inv0);
        __half2 v1 = __floats2half2_rn(o_acc[nb][2] * inv1, o_acc[nb][3] * inv1);
        *reinterpret_cast<__half2*>(op + (size_t)(b * TT + row0g) * EE + col) = v0;
        *reinterpret_cast<__half2*>(op + (size_t)(b * TT + row1g) * EE + col) = v1;
    }
}

// ---------------------------------------------------------------------------
// Fused residual-add + LayerNorm over E=768. One block per row, 256 threads.
// ---------------------------------------------------------------------------
template <bool HALF_OUT>
__global__ __launch_bounds__(256)
void ln_kernel(const float* __restrict__ a, const float* __restrict__ res,
               const float* __restrict__ g, const float* __restrict__ bt,
               float* __restrict__ out, __half* __restrict__ outh) {
    const int row = blockIdx.x;
    const float* pa = a + (size_t)row * EE;
    const float* pr = res + (size_t)row * EE;
    float vloc[3];
    float s = 0.0f, ss = 0.0f;
#pragma unroll
    for (int i = 0; i < 3; i++) {
        int c = threadIdx.x + i * 256;
        float vv = pa[c] + pr[c];
        vloc[i] = vv;
        s += vv;
        ss += vv * vv;
    }
#pragma unroll
    for (int off = 16; off > 0; off >>= 1) {
        s  += __shfl_xor_sync(0xffffffffu, s, off);
        ss += __shfl_xor_sync(0xffffffffu, ss, off);
    }
    __shared__ float sred[16];
    __shared__ float smu, srstd;
    int w = threadIdx.x >> 5, lane = threadIdx.x & 31;
    if (lane == 0) { sred[w] = s; sred[8 + w] = ss; }
    __syncthreads();
    if (threadIdx.x == 0) {
        float S = 0.0f, SS = 0.0f;
#pragma unroll
        for (int i = 0; i < 8; i++) { S += sred[i]; SS += sred[8 + i]; }
        float mu = S * (1.0f / EE);
        float var = SS * (1.0f / EE) - mu * mu;
        smu = mu;
        srstd = rsqrtf(var + LN_EPS);
    }
    __syncthreads();
    float mu = smu, rstd = srstd;
    float* po = out + (size_t)row * EE;
    __half* ph = HALF_OUT ? (outh + (size_t)row * EE) : nullptr;
#pragma unroll
    for (int i = 0; i < 3; i++) {
        int c = threadIdx.x + i * 256;
        float vv = (vloc[i] - mu) * rstd * g[c] + bt[c];
        po[c] = vv;
        if (HALF_OUT) ph[c] = __float2half_rn(vv);
    }
}

// ---------------------------------------------------------------------------
// Launch
// ---------------------------------------------------------------------------
extern "C" void kernel_launch(void* const* d_in, const int* in_sizes, int n_in,
                              void* d_out, int out_size) {
    const float* x      = (const float*)d_in[0];
    const float* Wq     = (const float*)d_in[1];
    const float* Wk     = (const float*)d_in[2];
    const float* Wv     = (const float*)d_in[3];
    const float* proj_w = (const float*)d_in[4];
    const float* proj_b = (const float*)d_in[5];
    const float* ln1_g  = (const float*)d_in[6];
    const float* ln1_b  = (const float*)d_in[7];
    const float* w1     = (const float*)d_in[8];
    const float* b1     = (const float*)d_in[9];
    const float* w2     = (const float*)d_in[10];
    const float* b2     = (const float*)d_in[11];
    const float* ln2_g  = (const float*)d_in[12];
    const float* ln2_b  = (const float*)d_in[13];
    float* out = (float*)d_out;

    __half *qh, *kh, *vh, *attnh, *x1h, *xh, *hh;
    __half *wqh, *wkh, *wvh, *projh, *w1h, *w2h;
    float *tmp, *x1;
    cudaGetSymbolAddress((void**)&qh,    g_qh);
    cudaGetSymbolAddress((void**)&kh,    g_kh);
    cudaGetSymbolAddress((void**)&vh,    g_vh);
    cudaGetSymbolAddress((void**)&attnh, g_attnh);
    cudaGetSymbolAddress((void**)&x1h,   g_x1h);
    cudaGetSymbolAddress((void**)&xh,    g_xh);
    cudaGetSymbolAddress((void**)&hh,    g_hh);
    cudaGetSymbolAddress((void**)&wqh,   g_wqh);
    cudaGetSymbolAddress((void**)&wkh,   g_wkh);
    cudaGetSymbolAddress((void**)&wvh,   g_wvh);
    cudaGetSymbolAddress((void**)&projh, g_projh);
    cudaGetSymbolAddress((void**)&w1h,   g_w1h);
    cudaGetSymbolAddress((void**)&w2h,   g_w2h);
    cudaGetSymbolAddress((void**)&tmp,   g_tmp);
    cudaGetSymbolAddress((void**)&x1,    g_x1);

    static bool attr_done = false;
    if (!attr_done) {
        cudaFuncSetAttribute((const void*)hgemm_kernel<false, false, 3, true, 128>,
                             cudaFuncAttributeMaxDynamicSharedMemorySize, GSMEM_OF(128));
        cudaFuncSetAttribute((const void*)hgemm_kernel<true, true, 1, true, 128>,
                             cudaFuncAttributeMaxDynamicSharedMemorySize, GSMEM_OF(128));
        cudaFuncSetAttribute((const void*)hgemm_kernel<true, false, 1, false, 64>,
                             cudaFuncAttributeMaxDynamicSharedMemorySize, GSMEM_OF(64));
        cudaFuncSetAttribute((const void*)attn_h_kernel,
                             cudaFuncAttributeMaxDynamicSharedMemorySize, ATT_SMEM);
        attr_done = true;
    }

    // ---- convert all GEMM operands to half (one launch) ----
    tohalf7_kernel<<<(CNTOT + 255) / 256, 256>>>(
        x, xh, Wq, wqh, Wk, wkh, Wv, wvh, proj_w, projh, w1, w1h, w2, w2h);

    dim3 gQKV(EE / 128, MROWS / 128, 3);    // (6, 32, 3)
    dim3 gE64(EE / 64, MROWS / 128, 1);     // (12, 32)
    dim3 gF(FFD / 128, MROWS / 128, 1);     // (24, 32)

    // Fused QKV projections
    hgemm_kernel<false, false, 3, true, 128><<<gQKV, 256, GSMEM_OF(128)>>>(
        xh, wqh, wkh, wvh, nullptr, qh, kh, vh, MROWS, EE, EE);

    // Causal attention (128-row Q tiles, cp.async double-buffered K/V)
    attn_h_kernel<<<dim3(TT / 128, BB * NH), 256, ATT_SMEM>>>(qh, kh, vh, attnh);

    // Output projection + bias (BN=64 for balance)
    hgemm_kernel<true, false, 1, false, 64><<<gE64, 256, GSMEM_OF(64)>>>(
        attnh, projh, projh, projh, proj_b, tmp, tmp, tmp, MROWS, EE, EE);
    ln_kernel<true><<<MROWS, 256>>>(tmp, x, ln1_g, ln1_b, x1, x1h);

    // FFN
    hgemm_kernel<true, true, 1, true, 128><<<gF, 256, GSMEM_OF(128)>>>(
        x1h, w1h, w1h, w1h, b1, hh, hh, hh, MROWS, FFD, EE);
    hgemm_kernel<true, false, 1, false, 64><<<gE64, 256, GSMEM_OF(64)>>>(
        hh, w2h, w2h, w2h, b2, tmp, tmp, tmp, MROWS, EE, FFD);
    ln_kernel<false><<<MROWS, 256>>>(tmp, x1, ln2_g, ln2_b, out, nullptr);
}

// round 11
// speedup vs baseline: 6.5616x; 1.0141x over previous
#include <cuda_runtime.h>
#include <cuda_fp16.h>
#include <math.h>
#include <stdint.h>

// Problem constants
#define BB 2
#define TT 2048
#define EE 768
#define NH 12
#define HD 64
#define FFD 3072
#define MROWS (BB * TT)   // 4096
#define LN_EPS 1e-5f

// ---------------------------------------------------------------------------
// Scratch (no allocation allowed -> __device__ globals)
// ---------------------------------------------------------------------------
__device__ __half g_qh[MROWS * EE];
__device__ __half g_kh[MROWS * EE];
__device__ __half g_vh[MROWS * EE];
__device__ __half g_attnh[MROWS * EE];
__device__ __half g_x1h[MROWS * EE];
__device__ __half g_xh[MROWS * EE];
__device__ __half g_hh[MROWS * FFD];
__device__ __half g_wqh[NH * HD * EE];
__device__ __half g_wkh[NH * HD * EE];
__device__ __half g_wvh[NH * HD * EE];
__device__ __half g_projh[EE * EE];
__device__ __half g_w1h[FFD * EE];
__device__ __half g_w2h[EE * FFD];
__device__ float g_tmp[MROWS * EE];
__device__ float g_x1[MROWS * EE];

// ---------------------------------------------------------------------------
// Helpers
// ---------------------------------------------------------------------------
__device__ __forceinline__ void mma_f16(float* c, const unsigned* a,
                                        unsigned b0, unsigned b1) {
    asm volatile(
        "mma.sync.aligned.m16n8k16.row.col.f32.f16.f16.f32 "
        "{%0,%1,%2,%3}, {%4,%5,%6,%7}, {%8,%9}, {%0,%1,%2,%3};\n"
        : "+f"(c[0]), "+f"(c[1]), "+f"(c[2]), "+f"(c[3])
        : "r"(a[0]), "r"(a[1]), "r"(a[2]), "r"(a[3]), "r"(b0), "r"(b1));
}

__device__ __forceinline__ void ldsm4(unsigned* r, uint32_t addr) {
    asm volatile("ldmatrix.sync.aligned.m8n8.x4.shared.b16 {%0,%1,%2,%3}, [%4];"
                 : "=r"(r[0]), "=r"(r[1]), "=r"(r[2]), "=r"(r[3]) : "r"(addr));
}
__device__ __forceinline__ void ldsm4t(unsigned* r, uint32_t addr) {
    asm volatile("ldmatrix.sync.aligned.m8n8.x4.trans.shared.b16 {%0,%1,%2,%3}, [%4];"
                 : "=r"(r[0]), "=r"(r[1]), "=r"(r[2]), "=r"(r[3]) : "r"(addr));
}

__device__ __forceinline__ void cp16s(uint32_t s, const void* g) {
    asm volatile("cp.async.cg.shared.global [%0], [%1], 16;\n" :: "r"(s), "l"(g));
}
__device__ __forceinline__ void cp_commit() {
    asm volatile("cp.async.commit_group;\n");
}

__device__ __forceinline__ uint32_t smem_u32(const void* p) {
    return (uint32_t)__cvta_generic_to_shared(p);
}

// ---------------------------------------------------------------------------
// Fused float -> half conversion for all 7 operand tensors (one launch).
// ---------------------------------------------------------------------------
#define CN0 (MROWS * EE / 4)      // x
#define CN1 (NH * HD * EE / 4)    // Wq / Wk / Wv
#define CN2 (EE * EE / 4)         // proj_w
#define CN3 (FFD * EE / 4)        // w1 / w2
#define CNTOT (CN0 + 3 * CN1 + CN2 + 2 * CN3)

__global__ __launch_bounds__(256)
void tohalf7_kernel(const float* __restrict__ i0, __half* __restrict__ o0,
                    const float* __restrict__ i1, __half* __restrict__ o1,
                    const float* __restrict__ i2, __half* __restrict__ o2,
                    const float* __restrict__ i3, __half* __restrict__ o3,
                    const float* __restrict__ i4, __half* __restrict__ o4,
                    const float* __restrict__ i5, __half* __restrict__ o5,
                    const float* __restrict__ i6, __half* __restrict__ o6) {
    int i = blockIdx.x * 256 + threadIdx.x;
    const float* in;
    __half* out;
    if (i < CN0) { in = i0; out = o0; }
    else if ((i -= CN0) < CN1) { in = i1; out = o1; }
    else if ((i -= CN1) < CN1) { in = i2; out = o2; }
    else if ((i -= CN1) < CN1) { in = i3; out = o3; }
    else if ((i -= CN1) < CN2) { in = i4; out = o4; }
    else if ((i -= CN2) < CN3) { in = i5; out = o5; }
    else if ((i -= CN3) < CN3) { in = i6; out = o6; }
    else return;
    float4 v = reinterpret_cast<const float4*>(in)[i];
    reinterpret_cast<__half2*>(out)[2 * i]     = __floats2half2_rn(v.x, v.y);
    reinterpret_cast<__half2*>(out)[2 * i + 1] = __floats2half2_rn(v.z, v.w);
}

// ---------------------------------------------------------------------------
// FP16 tensor-core GEMM with ldmatrix: C[M,N] = A[M,K] @ B[N,K]^T
// BM=128, BN template (128 or 64), BK=32, 256 threads, 8 warps as 4x2.
// Single-barrier 3-stage cp.async pipeline.
// ---------------------------------------------------------------------------
#define GROWB 80                       // bytes per smem row
#define GNS 3
#define GSMEM_OF(BN) (GNS * (128 + (BN)) * GROWB)

template <bool HAS_BIAS, bool RELU, int NZ, bool OUT_HALF, int BN>
__global__ __launch_bounds__(256)
void hgemm_kernel(const __half* __restrict__ A,
                  const __half* __restrict__ B0, const __half* __restrict__ B1,
                  const __half* __restrict__ B2,
                  const float* __restrict__ bias,
                  void* __restrict__ C0v, void* __restrict__ C1v, void* __restrict__ C2v,
                  int M, int N, int K) {
    constexpr int WN     = BN / 2;
    constexpr int NGROUP = WN / 16;
    constexpr int ACCN   = WN / 8;
    constexpr int GSTGA  = 128 * GROWB;
    constexpr int GSTGB  = BN * GROWB;

    const __half* B = B0;
    void* Cv = C0v;
    if (NZ == 3) {
        if (blockIdx.z == 1) { B = B1; Cv = C1v; }
        else if (blockIdx.z == 2) { B = B2; Cv = C2v; }
    }

    extern __shared__ char smraw[];
    const uint32_t smb = smem_u32(smraw);
    const int tid  = threadIdx.x;
    const int lane = tid & 31;
    const int warp = tid >> 5;
    const int wm   = warp >> 1;
    const int wn   = warp & 1;
    const int ln4  = lane >> 2;
    const int lm4  = lane & 3;
    const int brow = blockIdx.y * 128;
    const int bcol = blockIdx.x * BN;

    const uint32_t lm_off = (uint32_t)(lane & 15) * GROWB + ((lane >> 4) << 4);
    const uint32_t a_lm = (uint32_t)(wm * 32) * GROWB + lm_off;
    const uint32_t b_lm = (uint32_t)(wn * WN) * GROWB + lm_off;

    float acc[2][ACCN][4];
#pragma unroll
    for (int mt = 0; mt < 2; mt++)
#pragma unroll
        for (int nt = 0; nt < ACCN; nt++)
#pragma unroll
            for (int i = 0; i < 4; i++) acc[mt][nt][i] = 0.0f;

    const int nk = K >> 5;

    const int lrA = tid >> 1;
    const int ljA = (tid & 1) * 2;
    const int lrB = tid >> 2;
    const int ljB = tid & 3;

    auto gload = [&](int c) {
        const int st = c % GNS;
        const uint32_t sa = smb + st * GSTGA;
        const uint32_t sb = smb + GNS * GSTGA + st * GSTGB;
        const int kb = c * 32;
        const __half* gA = A + (size_t)(brow + lrA) * K + kb + ljA * 8;
        cp16s(sa + lrA * GROWB + ljA * 16, gA);
        cp16s(sa + lrA * GROWB + (ljA + 1) * 16, gA + 8);
        if (BN == 128) {
            const __half* gB = B + (size_t)(bcol + lrA) * K + kb + ljA * 8;
            cp16s(sb + lrA * GROWB + ljA * 16, gB);
            cp16s(sb + lrA * GROWB + (ljA + 1) * 16, gB + 8);
        } else {
            const __half* gB = B + (size_t)(bcol + lrB) * K + kb + ljB * 8;
            cp16s(sb + lrB * GROWB + ljB * 16, gB);
        }
        cp_commit();
    };

#pragma unroll
    for (int c = 0; c < GNS - 1; c++) gload(c);
    asm volatile("cp.async.wait_group %0;\n" :: "n"(GNS - 2));

    for (int s = 0; s < nk; s++) {
        __syncthreads();
        const int t = s + GNS - 1;
        if (t < nk) gload(t);
        else cp_commit();

        const int st = s % GNS;
        const uint32_t sa = smb + st * GSTGA + a_lm;
        const uint32_t sb = smb + GNS * GSTGA + st * GSTGB + b_lm;
#pragma unroll
        for (int ks = 0; ks < 2; ks++) {
            unsigned af[2][4];
            ldsm4(af[0], sa + ks * 32);
            ldsm4(af[1], sa + 16 * GROWB + ks * 32);
#pragma unroll
            for (int p = 0; p < NGROUP; p++) {
                unsigned bq[4];
                ldsm4(bq, sb + p * 16 * GROWB + ks * 32);
                mma_f16(acc[0][2 * p],     af[0], bq[0], bq[2]);
                mma_f16(acc[0][2 * p + 1], af[0], bq[1], bq[3]);
                mma_f16(acc[1][2 * p],     af[1], bq[0], bq[2]);
                mma_f16(acc[1][2 * p + 1], af[1], bq[1], bq[3]);
            }
        }
        asm volatile("cp.async.wait_group %0;\n" :: "n"(GNS - 2));
    }

    // epilogue
#pragma unroll
    for (int mt = 0; mt < 2; mt++) {
        const int r = brow + wm * 32 + mt * 16 + ln4;
#pragma unroll
        for (int nt = 0; nt < ACCN; nt++) {
            const int col = bcol + wn * WN + nt * 8 + lm4 * 2;
            float2 v0 = make_float2(acc[mt][nt][0], acc[mt][nt][1]);
            float2 v1 = make_float2(acc[mt][nt][2], acc[mt][nt][3]);
            if (HAS_BIAS) {
                float bx = bias[col], by = bias[col + 1];
                v0.x += bx; v0.y += by;
                v1.x += bx; v1.y += by;
            }
            if (RELU) {
                v0.x = fmaxf(v0.x, 0.0f); v0.y = fmaxf(v0.y, 0.0f);
                v1.x = fmaxf(v1.x, 0.0f); v1.y = fmaxf(v1.y, 0.0f);
            }
            if (OUT_HALF) {
                __half* C = (__half*)Cv;
                *reinterpret_cast<__half2*>(C + (size_t)r * N + col) =
                    __floats2half2_rn(v0.x, v0.y);
                *reinterpret_cast<__half2*>(C + (size_t)(r + 8) * N + col) =
                    __floats2half2_rn(v1.x, v1.y);
            } else {
                float* C = (float*)Cv;
                *reinterpret_cast<float2*>(C + (size_t)r * N + col) = v0;
                *reinterpret_cast<float2*>(C + (size_t)(r + 8) * N + col) = v1;
            }
        }
    }
}

// ---------------------------------------------------------------------------
// FP16 causal flash attention (mma.m16n8k16, fp32 softmax), cp.async
// double-buffered K/V, and P PASSED IN REGISTERS:
// the S c-fragments of two adjacent n8 tiles are exactly the m16n8k16
// A-fragment of the corresponding P k16 chunk -> pack half2 in regs,
// no SMEM round-trip, no __syncwarp.
// Softmax tracked in log2 domain (scale folded with log2e, exp2f).
// ---------------------------------------------------------------------------
#define ASTRW 36
#define ASTRB 144
#define AQW (128 * ASTRW)
#define AKVW (64 * ASTRW)
#define ATT_SMEM ((AQW + 4 * AKVW) * 4)   // 55296 bytes

__global__ __launch_bounds__(256)
void attn_h_kernel(const __half* __restrict__ qp, const __half* __restrict__ kp,
                   const __half* __restrict__ vp, __half* __restrict__ op) {
    extern __shared__ unsigned asm_[];
    unsigned* Qs = asm_;                     // Q staging (prologue only)
    unsigned* Ks = asm_ + AQW;               // 2 stages
    unsigned* Vs = asm_ + AQW + 2 * AKVW;    // 2 stages

    const int qt  = (gridDim.x - 1) - blockIdx.x;   // reversed: heavy first
    const int bh  = blockIdx.y;
    const int b   = bh / NH;
    const int h   = bh % NH;
    const int tid = threadIdx.x;
    const int lane = tid & 31;
    const int w    = tid >> 5;       // 0..7
    const int ln4  = lane >> 2;      // 0..7
    const int lm4  = lane & 3;       // 0..3
    const int rb   = w * 16;         // warp's query-row base (0..112)

    const uint32_t smQ = smem_u32(Qs);
    const uint32_t smK = smem_u32(Ks);
    const uint32_t smV = smem_u32(Vs);

    const uint32_t lm_off = (uint32_t)(lane & 15) * ASTRB + ((lane >> 4) << 4);
    const uint32_t q_lm = smQ + (uint32_t)rb * ASTRB + lm_off;
    const uint32_t k_lm = smK + lm_off;
    const uint32_t v_lm = smV + ((uint32_t)((lane & 7) + ((lane >> 4) << 3))) * ASTRB
                              + (((lane >> 3) & 1) << 4);

    // K/V tile loader: 64 rows x 64 halfs each via cp.async (one commit group)
    const int lrKV = tid >> 2;           // 0..63
    const int ljKV = tid & 3;            // 0..3
    auto kvload = [&](int kt) {
        const int st = kt & 1;
        const uint32_t sk = smK + st * (AKVW * 4);
        const uint32_t sv = smV + st * (AKVW * 4);
        size_t g = ((size_t)(b * TT + kt * 64 + lrKV) * EE + h * HD + ljKV * 16);
        const uint32_t so = (uint32_t)lrKV * ASTRB + ljKV * 32;
        cp16s(sk + so,      kp + g);
        cp16s(sk + so + 16, kp + g + 8);
        cp16s(sv + so,      vp + g);
        cp16s(sv + so + 16, vp + g + 8);
        cp_commit();
    };

    const int nkt = 2 * qt + 2;          // 64-key tiles

    // ---- prologue: start K/V tile 0, then load Q (plain) ----
    kvload(0);
#pragma unroll
    for (int i = 0; i < 4; i++) {
        int idx = tid + i * 256;
        int row = idx >> 3;               // 0..127
        int c   = idx & 7;
        uint4 vq = *reinterpret_cast<const uint4*>(
            qp + ((size_t)(b * TT + qt * 128 + row) * EE + h * HD + c * 8));
        *reinterpret_cast<uint4*>(&Qs[row * ASTRW + c * 4]) = vq;
    }
    asm volatile("cp.async.wait_group 0;\n");
    __syncthreads();

    // ---- Q a-fragments (4 k16 chunks x 4 regs), held in registers ----
    unsigned qa[4][4];
#pragma unroll
    for (int ks = 0; ks < 4; ks++) ldsm4(qa[ks], q_lm + ks * 32);

    float o_acc[8][4];
#pragma unroll
    for (int nb = 0; nb < 8; nb++)
#pragma unroll
        for (int i = 0; i < 4; i++) o_acc[nb][i] = 0.0f;
    float m0 = -1e30f, m1 = -1e30f, l0 = 0.0f, l1 = 0.0f;
    const float scale2 = 0.125f * 1.44269504088896f;   // 1/sqrt(64) * log2(e)
    const int row0g = qt * 128 + rb + ln4;
    const int row1g = row0g + 8;

    for (int kt = 0; kt < nkt; kt++) {
        if (kt) __syncthreads();
        if (kt + 1 < nkt) kvload(kt + 1);
        else cp_commit();

        const uint32_t kb_ = k_lm + (kt & 1) * (AKVW * 4);
        const uint32_t vb_ = v_lm + (kt & 1) * (AKVW * 4);
        const int s0 = kt * 64;

        // ---- S = Q K^T : warp computes 16x64 ----
        float s[8][4];
#pragma unroll
        for (int nb = 0; nb < 8; nb++)
#pragma unroll
            for (int i = 0; i < 4; i++) s[nb][i] = 0.0f;
#pragma unroll
        for (int ks = 0; ks < 4; ks++) {
#pragma unroll
            for (int p = 0; p < 4; p++) {
                unsigned bq[4];
                ldsm4(bq, kb_ + p * 16 * ASTRB + ks * 32);
                mma_f16(s[2 * p],     qa[ks], bq[0], bq[2]);
                mma_f16(s[2 * p + 1], qa[ks], bq[1], bq[3]);
            }
        }

        // ---- scale (log2 domain) + causal mask ----
        if (s0 + 63 > qt * 128 + rb) {
#pragma unroll
            for (int nb = 0; nb < 8; nb++) {
                int c0 = s0 + nb * 8 + lm4 * 2;
                s[nb][0] = (c0     > row0g) ? -1e30f : s[nb][0] * scale2;
                s[nb][1] = (c0 + 1 > row0g) ? -1e30f : s[nb][1] * scale2;
                s[nb][2] = (c0     > row1g) ? -1e30f : s[nb][2] * scale2;
                s[nb][3] = (c0 + 1 > row1g) ? -1e30f : s[nb][3] * scale2;
            }
        } else {
#pragma unroll
            for (int nb = 0; nb < 8; nb++)
#pragma unroll
                for (int i = 0; i < 4; i++) s[nb][i] *= scale2;
        }

        // ---- online softmax (fp32, base 2); P packed into registers ----
        float mx0 = -1e30f, mx1 = -1e30f;
#pragma unroll
        for (int nb = 0; nb < 8; nb++) {
            mx0 = fmaxf(mx0, fmaxf(s[nb][0], s[nb][1]));
            mx1 = fmaxf(mx1, fmaxf(s[nb][2], s[nb][3]));
        }
        mx0 = fmaxf(mx0, __shfl_xor_sync(0xffffffffu, mx0, 1));
        mx0 = fmaxf(mx0, __shfl_xor_sync(0xffffffffu, mx0, 2));
        mx1 = fmaxf(mx1, __shfl_xor_sync(0xffffffffu, mx1, 1));
        mx1 = fmaxf(mx1, __shfl_xor_sync(0xffffffffu, mx1, 2));
        float mn0 = fmaxf(m0, mx0), mn1 = fmaxf(m1, mx1);
        float alpha0 = exp2f(m0 - mn0), alpha1 = exp2f(m1 - mn1);
        float sum0 = 0.0f, sum1 = 0.0f;
        unsigned plo[8], phi[8];          // P a-fragment halves (row, row+8)
#pragma unroll
        for (int nb = 0; nb < 8; nb++) {
            float p00 = exp2f(s[nb][0] - mn0);
            float p01 = exp2f(s[nb][1] - mn0);
            float p10 = exp2f(s[nb][2] - mn1);
            float p11 = exp2f(s[nb][3] - mn1);
            sum0 += p00 + p01;
            sum1 += p10 + p11;
            __half2 hl = __floats2half2_rn(p00, p01);
            __half2 hh2 = __floats2half2_rn(p10, p11);
            plo[nb] = *reinterpret_cast<unsigned*>(&hl);
            phi[nb] = *reinterpret_cast<unsigned*>(&hh2);
        }
        sum0 += __shfl_xor_sync(0xffffffffu, sum0, 1);
        sum0 += __shfl_xor_sync(0xffffffffu, sum0, 2);
        sum1 += __shfl_xor_sync(0xffffffffu, sum1, 1);
        sum1 += __shfl_xor_sync(0xffffffffu, sum1, 2);
        l0 = l0 * alpha0 + sum0;
        l1 = l1 * alpha1 + sum1;
        m0 = mn0; m1 = mn1;
#pragma unroll
        for (int nb = 0; nb < 8; nb++) {
            o_acc[nb][0] *= alpha0; o_acc[nb][1] *= alpha0;
            o_acc[nb][2] *= alpha1; o_acc[nb][3] *= alpha1;
        }

        // ---- O += P V : P a-frags from registers, V b-frags via ldsm.trans ----
#pragma unroll
        for (int ks = 0; ks < 4; ks++) {
            unsigned pa[4];
            pa[0] = plo[2 * ks];
            pa[1] = phi[2 * ks];
            pa[2] = plo[2 * ks + 1];
            pa[3] = phi[2 * ks + 1];
#pragma unroll
            for (int p = 0; p < 4; p++) {
                unsigned vq[4];
                ldsm4t(vq, vb_ + ks * 16 * ASTRB + p * 32);
                mma_f16(o_acc[2 * p],     pa, vq[0], vq[2]);
                mma_f16(o_acc[2 * p + 1], pa, vq[1], vq[3]);
            }
        }
        asm volatile("cp.async.wait_group 0;\n");
    }

    // ---- write O (half) ----
    float inv0 = 1.0f / l0, inv1 = 1.0f / l1;
#pragma unroll
    for (int nb = 0; nb < 8; nb++) {
        int col = h * HD + nb * 8 + lm4 * 2;
        __half2 v0 = __floats2half2_rn(o_acc[nb][0] * inv0, o_acc[nb][1] * inv0);
        __half2 v1 = __floats2half2_rn(o_acc[nb][2] * inv1, o_acc[nb][3] * inv1);
        *reinterpret_cast<__half2*>(op + (size_t)(b * TT + row0g) * EE + col) = v0;
        *reinterpret_cast<__half2*>(op + (size_t)(b * TT + row1g) * EE + col) = v1;
    }
}

// ---------------------------------------------------------------------------
// Fused residual-add + LayerNorm over E=768. One block per row, 256 threads.
// ---------------------------------------------------------------------------
template <bool HALF_OUT>
__global__ __launch_bounds__(256)
void ln_kernel(const float* __restrict__ a, const float* __restrict__ res,
               const float* __restrict__ g, const float* __restrict__ bt,
               float* __restrict__ out, __half* __restrict__ outh) {
    const int row = blockIdx.x;
    const float* pa = a + (size_t)row * EE;
    const float* pr = res + (size_t)row * EE;
    float vloc[3];
    float s = 0.0f, ss = 0.0f;
#pragma unroll
    for (int i = 0; i < 3; i++) {
        int c = threadIdx.x + i * 256;
        float vv = pa[c] + pr[c];
        vloc[i] = vv;
        s += vv;
        ss += vv * vv;
    }
#pragma unroll
    for (int off = 16; off > 0; off >>= 1) {
        s  += __shfl_xor_sync(0xffffffffu, s, off);
        ss += __shfl_xor_sync(0xffffffffu, ss, off);
    }
    __shared__ float sred[16];
    __shared__ float smu, srstd;
    int w = threadIdx.x >> 5, lane = threadIdx.x & 31;
    if (lane == 0) { sred[w] = s; sred[8 + w] = ss; }
    __syncthreads();
    if (threadIdx.x == 0) {
        float S = 0.0f, SS = 0.0f;
#pragma unroll
        for (int i = 0; i < 8; i++) { S += sred[i]; SS += sred[8 + i]; }
        float mu = S * (1.0f / EE);
        float var = SS * (1.0f / EE) - mu * mu;
        smu = mu;
        srstd = rsqrtf(var + LN_EPS);
    }
    __syncthreads();
    float mu = smu, rstd = srstd;
    float* po = out + (size_t)row * EE;
    __half* ph = HALF_OUT ? (outh + (size_t)row * EE) : nullptr;
#pragma unroll
    for (int i = 0; i < 3; i++) {
        int c = threadIdx.x + i * 256;
        float vv = (vloc[i] - mu) * rstd * g[c] + bt[c];
        po[c] = vv;
        if (HALF_OUT) ph[c] = __float2half_rn(vv);
    }
}

// ---------------------------------------------------------------------------
// Launch
// ---------------------------------------------------------------------------
extern "C" void kernel_launch(void* const* d_in, const int* in_sizes, int n_in,
                              void* d_out, int out_size) {
    const float* x      = (const float*)d_in[0];
    const float* Wq     = (const float*)d_in[1];
    const float* Wk     = (const float*)d_in[2];
    const float* Wv     = (const float*)d_in[3];
    const float* proj_w = (const float*)d_in[4];
    const float* proj_b = (const float*)d_in[5];
    const float* ln1_g  = (const float*)d_in[6];
    const float* ln1_b  = (const float*)d_in[7];
    const float* w1     = (const float*)d_in[8];
    const float* b1     = (const float*)d_in[9];
    const float* w2     = (const float*)d_in[10];
    const float* b2     = (const float*)d_in[11];
    const float* ln2_g  = (const float*)d_in[12];
    const float* ln2_b  = (const float*)d_in[13];
    float* out = (float*)d_out;

    __half *qh, *kh, *vh, *attnh, *x1h, *xh, *hh;
    __half *wqh, *wkh, *wvh, *projh, *w1h, *w2h;
    float *tmp, *x1;
    cudaGetSymbolAddress((void**)&qh,    g_qh);
    cudaGetSymbolAddress((void**)&kh,    g_kh);
    cudaGetSymbolAddress((void**)&vh,    g_vh);
    cudaGetSymbolAddress((void**)&attnh, g_attnh);
    cudaGetSymbolAddress((void**)&x1h,   g_x1h);
    cudaGetSymbolAddress((void**)&xh,    g_xh);
    cudaGetSymbolAddress((void**)&hh,    g_hh);
    cudaGetSymbolAddress((void**)&wqh,   g_wqh);
    cudaGetSymbolAddress((void**)&wkh,   g_wkh);
    cudaGetSymbolAddress((void**)&wvh,   g_wvh);
    cudaGetSymbolAddress((void**)&projh, g_projh);
    cudaGetSymbolAddress((void**)&w1h,   g_w1h);
    cudaGetSymbolAddress((void**)&w2h,   g_w2h);
    cudaGetSymbolAddress((void**)&tmp,   g_tmp);
    cudaGetSymbolAddress((void**)&x1,    g_x1);

    static bool attr_done = false;
    if (!attr_done) {
        cudaFuncSetAttribute((const void*)hgemm_kernel<false, false, 3, true, 128>,
                             cudaFuncAttributeMaxDynamicSharedMemorySize, GSMEM_OF(128));
        cudaFuncSetAttribute((const void*)hgemm_kernel<true, true, 1, true, 128>,
                             cudaFuncAttributeMaxDynamicSharedMemorySize, GSMEM_OF(128));
        cudaFuncSetAttribute((const void*)hgemm_kernel<true, false, 1, false, 64>,
                             cudaFuncAttributeMaxDynamicSharedMemorySize, GSMEM_OF(64));
        cudaFuncSetAttribute((const void*)attn_h_kernel,
                             cudaFuncAttributeMaxDynamicSharedMemorySize, ATT_SMEM);
        attr_done = true;
    }

    // ---- convert all GEMM operands to half (one launch) ----
    tohalf7_kernel<<<(CNTOT + 255) / 256, 256>>>(
        x, xh, Wq, wqh, Wk, wkh, Wv, wvh, proj_w, projh, w1, w1h, w2, w2h);

    dim3 gQKV(EE / 128, MROWS / 128, 3);    // (6, 32, 3)
    dim3 gE64(EE / 64, MROWS / 128, 1);     // (12, 32)
    dim3 gF(FFD / 128, MROWS / 128, 1);     // (24, 32)

    // Fused QKV projections
    hgemm_kernel<false, false, 3, true, 128><<<gQKV, 256, GSMEM_OF(128)>>>(
        xh, wqh, wkh, wvh, nullptr, qh, kh, vh, MROWS, EE, EE);

    // Causal attention (register-resident P)
    attn_h_kernel<<<dim3(TT / 128, BB * NH), 256, ATT_SMEM>>>(qh, kh, vh, attnh);

    // Output projection + bias (BN=64 for balance)
    hgemm_kernel<true, false, 1, false, 64><<<gE64, 256, GSMEM_OF(64)>>>(
        attnh, projh, projh, projh, proj_b, tmp, tmp, tmp, MROWS, EE, EE);
    ln_kernel<true><<<MROWS, 256>>>(tmp, x, ln1_g, ln1_b, x1, x1h);

    // FFN
    hgemm_kernel<true, true, 1, true, 128><<<gF, 256, GSMEM_OF(128)>>>(
        x1h, w1h, w1h, w1h, b1, hh, hh, hh, MROWS, FFD, EE);
    hgemm_kernel<true, false, 1, false, 64><<<gE64, 256, GSMEM_OF(64)>>>(
        hh, w2h, w2h, w2h, b2, tmp, tmp, tmp, MROWS, EE, FFD);
    ln_kernel<false><<<MROWS, 256>>>(tmp, x1, ln2_g, ln2_b, out, nullptr);
}

// round 12
// speedup vs baseline: 6.7526x; 1.0291x over previous
#include <cuda_runtime.h>
#include <cuda_fp16.h>
#include <math.h>
#include <stdint.h>

// Problem constants
#define BB 2
#define TT 2048
#define EE 768
#define NH 12
#define HD 64
#define FFD 3072
#define MROWS (BB * TT)   // 4096
#define LN_EPS 1e-5f

// ---------------------------------------------------------------------------
// Scratch (no allocation allowed -> __device__ globals)
// ---------------------------------------------------------------------------
__device__ __half g_qh[MROWS * EE];
__device__ __half g_kh[MROWS * EE];
__device__ __half g_vh[MROWS * EE];
__device__ __half g_attnh[MROWS * EE];
__device__ __half g_x1h[MROWS * EE];
__device__ __half g_xh[MROWS * EE];
__device__ __half g_hh[MROWS * FFD];
__device__ __half g_wqh[NH * HD * EE];
__device__ __half g_wkh[NH * HD * EE];
__device__ __half g_wvh[NH * HD * EE];
__device__ __half g_projh[EE * EE];
__device__ __half g_w1h[FFD * EE];
__device__ __half g_w2h[EE * FFD];
__device__ float g_tmp[MROWS * EE];
__device__ float g_x1[MROWS * EE];
__device__ float g_po[2 * MROWS * EE];          // split-K partial O (unnormalized)
__device__ float g_ml[2 * MROWS * NH * 2];      // split-K partial (m, l)

// ---------------------------------------------------------------------------
// Helpers
// ---------------------------------------------------------------------------
__device__ __forceinline__ void mma_f16(float* c, const unsigned* a,
                                        unsigned b0, unsigned b1) {
    asm volatile(
        "mma.sync.aligned.m16n8k16.row.col.f32.f16.f16.f32 "
        "{%0,%1,%2,%3}, {%4,%5,%6,%7}, {%8,%9}, {%0,%1,%2,%3};\n"
        : "+f"(c[0]), "+f"(c[1]), "+f"(c[2]), "+f"(c[3])
        : "r"(a[0]), "r"(a[1]), "r"(a[2]), "r"(a[3]), "r"(b0), "r"(b1));
}

__device__ __forceinline__ void ldsm4(unsigned* r, uint32_t addr) {
    asm volatile("ldmatrix.sync.aligned.m8n8.x4.shared.b16 {%0,%1,%2,%3}, [%4];"
                 : "=r"(r[0]), "=r"(r[1]), "=r"(r[2]), "=r"(r[3]) : "r"(addr));
}
__device__ __forceinline__ void ldsm4t(unsigned* r, uint32_t addr) {
    asm volatile("ldmatrix.sync.aligned.m8n8.x4.trans.shared.b16 {%0,%1,%2,%3}, [%4];"
                 : "=r"(r[0]), "=r"(r[1]), "=r"(r[2]), "=r"(r[3]) : "r"(addr));
}

__device__ __forceinline__ void cp16s(uint32_t s, const void* g) {
    asm volatile("cp.async.cg.shared.global [%0], [%1], 16;\n" :: "r"(s), "l"(g));
}
__device__ __forceinline__ void cp_commit() {
    asm volatile("cp.async.commit_group;\n");
}

__device__ __forceinline__ uint32_t smem_u32(const void* p) {
    return (uint32_t)__cvta_generic_to_shared(p);
}

// Fast exp2 (single MUFU op; avoids the slow accurate exp2f software path)
__device__ __forceinline__ float ex2(float x) {
    float r;
    asm("ex2.approx.ftz.f32 %0, %1;" : "=f"(r) : "f"(x));
    return r;
}

// ---------------------------------------------------------------------------
// Fused float -> half conversion for all 7 operand tensors (one launch).
// ---------------------------------------------------------------------------
#define CN0 (MROWS * EE / 4)      // x
#define CN1 (NH * HD * EE / 4)    // Wq / Wk / Wv
#define CN2 (EE * EE / 4)         // proj_w
#define CN3 (FFD * EE / 4)        // w1 / w2
#define CNTOT (CN0 + 3 * CN1 + CN2 + 2 * CN3)

__global__ __launch_bounds__(256)
void tohalf7_kernel(const float* __restrict__ i0, __half* __restrict__ o0,
                    const float* __restrict__ i1, __half* __restrict__ o1,
                    const float* __restrict__ i2, __half* __restrict__ o2,
                    const float* __restrict__ i3, __half* __restrict__ o3,
                    const float* __restrict__ i4, __half* __restrict__ o4,
                    const float* __restrict__ i5, __half* __restrict__ o5,
                    const float* __restrict__ i6, __half* __restrict__ o6) {
    int i = blockIdx.x * 256 + threadIdx.x;
    const float* in;
    __half* out;
    if (i < CN0) { in = i0; out = o0; }
    else if ((i -= CN0) < CN1) { in = i1; out = o1; }
    else if ((i -= CN1) < CN1) { in = i2; out = o2; }
    else if ((i -= CN1) < CN1) { in = i3; out = o3; }
    else if ((i -= CN1) < CN2) { in = i4; out = o4; }
    else if ((i -= CN2) < CN3) { in = i5; out = o5; }
    else if ((i -= CN3) < CN3) { in = i6; out = o6; }
    else return;
    float4 v = reinterpret_cast<const float4*>(in)[i];
    reinterpret_cast<__half2*>(out)[2 * i]     = __floats2half2_rn(v.x, v.y);
    reinterpret_cast<__half2*>(out)[2 * i + 1] = __floats2half2_rn(v.z, v.w);
}

// ---------------------------------------------------------------------------
// FP16 tensor-core GEMM with ldmatrix: C[M,N] = A[M,K] @ B[N,K]^T
// BM=128, BN template (128 or 64), BK=32, 256 threads, 8 warps as 4x2.
// Single-barrier 3-stage cp.async pipeline.
// ---------------------------------------------------------------------------
#define GROWB 80                       // bytes per smem row
#define GNS 3
#define GSMEM_OF(BN) (GNS * (128 + (BN)) * GROWB)

template <bool HAS_BIAS, bool RELU, int NZ, bool OUT_HALF, int BN>
__global__ __launch_bounds__(256)
void hgemm_kernel(const __half* __restrict__ A,
                  const __half* __restrict__ B0, const __half* __restrict__ B1,
                  const __half* __restrict__ B2,
                  const float* __restrict__ bias,
                  void* __restrict__ C0v, void* __restrict__ C1v, void* __restrict__ C2v,
                  int M, int N, int K) {
    constexpr int WN     = BN / 2;
    constexpr int NGROUP = WN / 16;
    constexpr int ACCN   = WN / 8;
    constexpr int GSTGA  = 128 * GROWB;
    constexpr int GSTGB  = BN * GROWB;

    const __half* B = B0;
    void* Cv = C0v;
    if (NZ == 3) {
        if (blockIdx.z == 1) { B = B1; Cv = C1v; }
        else if (blockIdx.z == 2) { B = B2; Cv = C2v; }
    }

    extern __shared__ char smraw[];
    const uint32_t smb = smem_u32(smraw);
    const int tid  = threadIdx.x;
    const int lane = tid & 31;
    const int warp = tid >> 5;
    const int wm   = warp >> 1;
    const int wn   = warp & 1;
    const int ln4  = lane >> 2;
    const int lm4  = lane & 3;
    const int brow = blockIdx.y * 128;
    const int bcol = blockIdx.x * BN;

    const uint32_t lm_off = (uint32_t)(lane & 15) * GROWB + ((lane >> 4) << 4);
    const uint32_t a_lm = (uint32_t)(wm * 32) * GROWB + lm_off;
    const uint32_t b_lm = (uint32_t)(wn * WN) * GROWB + lm_off;

    float acc[2][ACCN][4];
#pragma unroll
    for (int mt = 0; mt < 2; mt++)
#pragma unroll
        for (int nt = 0; nt < ACCN; nt++)
#pragma unroll
            for (int i = 0; i < 4; i++) acc[mt][nt][i] = 0.0f;

    const int nk = K >> 5;

    const int lrA = tid >> 1;
    const int ljA = (tid & 1) * 2;
    const int lrB = tid >> 2;
    const int ljB = tid & 3;

    auto gload = [&](int c) {
        const int st = c % GNS;
        const uint32_t sa = smb + st * GSTGA;
        const uint32_t sb = smb + GNS * GSTGA + st * GSTGB;
        const int kb = c * 32;
        const __half* gA = A + (size_t)(brow + lrA) * K + kb + ljA * 8;
        cp16s(sa + lrA * GROWB + ljA * 16, gA);
        cp16s(sa + lrA * GROWB + (ljA + 1) * 16, gA + 8);
        if (BN == 128) {
            const __half* gB = B + (size_t)(bcol + lrA) * K + kb + ljA * 8;
            cp16s(sb + lrA * GROWB + ljA * 16, gB);
            cp16s(sb + lrA * GROWB + (ljA + 1) * 16, gB + 8);
        } else {
            const __half* gB = B + (size_t)(bcol + lrB) * K + kb + ljB * 8;
            cp16s(sb + lrB * GROWB + ljB * 16, gB);
        }
        cp_commit();
    };

#pragma unroll
    for (int c = 0; c < GNS - 1; c++) gload(c);
    asm volatile("cp.async.wait_group %0;\n" :: "n"(GNS - 2));

    for (int s = 0; s < nk; s++) {
        __syncthreads();
        const int t = s + GNS - 1;
        if (t < nk) gload(t);
        else cp_commit();

        const int st = s % GNS;
        const uint32_t sa = smb + st * GSTGA + a_lm;
        const uint32_t sb = smb + GNS * GSTGA + st * GSTGB + b_lm;
#pragma unroll
        for (int ks = 0; ks < 2; ks++) {
            unsigned af[2][4];
            ldsm4(af[0], sa + ks * 32);
            ldsm4(af[1], sa + 16 * GROWB + ks * 32);
#pragma unroll
            for (int p = 0; p < NGROUP; p++) {
                unsigned bq[4];
                ldsm4(bq, sb + p * 16 * GROWB + ks * 32);
                mma_f16(acc[0][2 * p],     af[0], bq[0], bq[2]);
                mma_f16(acc[0][2 * p + 1], af[0], bq[1], bq[3]);
                mma_f16(acc[1][2 * p],     af[1], bq[0], bq[2]);
                mma_f16(acc[1][2 * p + 1], af[1], bq[1], bq[3]);
            }
        }
        asm volatile("cp.async.wait_group %0;\n" :: "n"(GNS - 2));
    }

    // epilogue
#pragma unroll
    for (int mt = 0; mt < 2; mt++) {
        const int r = brow + wm * 32 + mt * 16 + ln4;
#pragma unroll
        for (int nt = 0; nt < ACCN; nt++) {
            const int col = bcol + wn * WN + nt * 8 + lm4 * 2;
            float2 v0 = make_float2(acc[mt][nt][0], acc[mt][nt][1]);
            float2 v1 = make_float2(acc[mt][nt][2], acc[mt][nt][3]);
            if (HAS_BIAS) {
                float bx = bias[col], by = bias[col + 1];
                v0.x += bx; v0.y += by;
                v1.x += bx; v1.y += by;
            }
            if (RELU) {
                v0.x = fmaxf(v0.x, 0.0f); v0.y = fmaxf(v0.y, 0.0f);
                v1.x = fmaxf(v1.x, 0.0f); v1.y = fmaxf(v1.y, 0.0f);
            }
            if (OUT_HALF) {
                __half* C = (__half*)Cv;
                *reinterpret_cast<__half2*>(C + (size_t)r * N + col) =
                    __floats2half2_rn(v0.x, v0.y);
                *reinterpret_cast<__half2*>(C + (size_t)(r + 8) * N + col) =
                    __floats2half2_rn(v1.x, v1.y);
            } else {
                float* C = (float*)Cv;
                *reinterpret_cast<float2*>(C + (size_t)r * N + col) = v0;
                *reinterpret_cast<float2*>(C + (size_t)(r + 8) * N + col) = v1;
            }
        }
    }
}

// ---------------------------------------------------------------------------
// Split-K FP16 causal flash attention (flash-decoding style).
// Grid (T/128, B*NH, 2): z = key-range split. Split sp covers key tiles
// [sp*(qt+1), (sp+1)*(qt+1)) of the 2qt+2 total -> equal halves, max 16
// serial tiles per CTA, 768 CTAs. Each split writes UNNORMALIZED O (fp32)
// plus per-row (m, l); a combine kernel merges the two splits.
// P stays in registers (c-frag == a-frag identity); softmax in log2 domain
// with single-MUFU ex2.approx.
// ---------------------------------------------------------------------------
#define ASTRW 36
#define ASTRB 144
#define AQW (128 * ASTRW)
#define AKVW (64 * ASTRW)
#define ATT_SMEM ((AQW + 4 * AKVW) * 4)   // 55296 bytes

__global__ __launch_bounds__(256)
void attn_split_kernel(const __half* __restrict__ qp, const __half* __restrict__ kp,
                       const __half* __restrict__ vp,
                       float* __restrict__ opart, float* __restrict__ mlpart) {
    extern __shared__ unsigned asm_[];
    unsigned* Qs = asm_;                     // Q staging (prologue only)
    unsigned* Ks = asm_ + AQW;               // 2 stages
    unsigned* Vs = asm_ + AQW + 2 * AKVW;    // 2 stages

    const int qt  = (gridDim.x - 1) - blockIdx.x;   // reversed: heavy first
    const int bh  = blockIdx.y;
    const int sp  = blockIdx.z;              // split 0 / 1
    const int b   = bh / NH;
    const int h   = bh % NH;
    const int tid = threadIdx.x;
    const int lane = tid & 31;
    const int w    = tid >> 5;       // 0..7
    const int ln4  = lane >> 2;      // 0..7
    const int lm4  = lane & 3;       // 0..3
    const int rb   = w * 16;         // warp's query-row base (0..112)

    const int ntl = qt + 1;          // tiles in this split
    const int kt0 = sp * ntl;        // first global key tile

    const uint32_t smQ = smem_u32(Qs);
    const uint32_t smK = smem_u32(Ks);
    const uint32_t smV = smem_u32(Vs);

    const uint32_t lm_off = (uint32_t)(lane & 15) * ASTRB + ((lane >> 4) << 4);
    const uint32_t q_lm = smQ + (uint32_t)rb * ASTRB + lm_off;
    const uint32_t k_lm = smK + lm_off;
    const uint32_t v_lm = smV + ((uint32_t)((lane & 7) + ((lane >> 4) << 3))) * ASTRB
                              + (((lane >> 3) & 1) << 4);

    // K/V tile loader (local tile index lt; global tile = kt0 + lt)
    const int lrKV = tid >> 2;           // 0..63
    const int ljKV = tid & 3;            // 0..3
    auto kvload = [&](int lt) {
        const int st = lt & 1;
        const uint32_t sk = smK + st * (AKVW * 4);
        const uint32_t sv = smV + st * (AKVW * 4);
        size_t g = ((size_t)(b * TT + (kt0 + lt) * 64 + lrKV) * EE + h * HD + ljKV * 16);
        const uint32_t so = (uint32_t)lrKV * ASTRB + ljKV * 32;
        cp16s(sk + so,      kp + g);
        cp16s(sk + so + 16, kp + g + 8);
        cp16s(sv + so,      vp + g);
        cp16s(sv + so + 16, vp + g + 8);
        cp_commit();
    };

    // ---- prologue: start K/V tile 0, then load Q (plain) ----
    kvload(0);
#pragma unroll
    for (int i = 0; i < 4; i++) {
        int idx = tid + i * 256;
        int row = idx >> 3;               // 0..127
        int c   = idx & 7;
        uint4 vq = *reinterpret_cast<const uint4*>(
            qp + ((size_t)(b * TT + qt * 128 + row) * EE + h * HD + c * 8));
        *reinterpret_cast<uint4*>(&Qs[row * ASTRW + c * 4]) = vq;
    }
    asm volatile("cp.async.wait_group 0;\n");
    __syncthreads();

    // ---- Q a-fragments (4 k16 chunks x 4 regs), held in registers ----
    unsigned qa[4][4];
#pragma unroll
    for (int ks = 0; ks < 4; ks++) ldsm4(qa[ks], q_lm + ks * 32);

    float o_acc[8][4];
#pragma unroll
    for (int nb = 0; nb < 8; nb++)
#pragma unroll
        for (int i = 0; i < 4; i++) o_acc[nb][i] = 0.0f;
    float m0 = -1e30f, m1 = -1e30f, l0 = 0.0f, l1 = 0.0f;
    const float scale2 = 0.125f * 1.44269504088896f;   // 1/sqrt(64) * log2(e)
    const int row0g = qt * 128 + rb + ln4;
    const int row1g = row0g + 8;

    for (int lt = 0; lt < ntl; lt++) {
        if (lt) __syncthreads();
        if (lt + 1 < ntl) kvload(lt + 1);
        else cp_commit();

        const uint32_t kb_ = k_lm + (lt & 1) * (AKVW * 4);
        const uint32_t vb_ = v_lm + (lt & 1) * (AKVW * 4);
        const int s0 = (kt0 + lt) * 64;

        // ---- S = Q K^T : warp computes 16x64 ----
        float s[8][4];
#pragma unroll
        for (int nb = 0; nb < 8; nb++)
#pragma unroll
            for (int i = 0; i < 4; i++) s[nb][i] = 0.0f;
#pragma unroll
        for (int ks = 0; ks < 4; ks++) {
#pragma unroll
            for (int p = 0; p < 4; p++) {
                unsigned bq[4];
                ldsm4(bq, kb_ + p * 16 * ASTRB + ks * 32);
                mma_f16(s[2 * p],     qa[ks], bq[0], bq[2]);
                mma_f16(s[2 * p + 1], qa[ks], bq[1], bq[3]);
            }
        }

        // ---- scale (log2 domain) + causal mask ----
        if (s0 + 63 > qt * 128 + rb) {
#pragma unroll
            for (int nb = 0; nb < 8; nb++) {
                int c0 = s0 + nb * 8 + lm4 * 2;
                s[nb][0] = (c0     > row0g) ? -1e30f : s[nb][0] * scale2;
                s[nb][1] = (c0 + 1 > row0g) ? -1e30f : s[nb][1] * scale2;
                s[nb][2] = (c0     > row1g) ? -1e30f : s[nb][2] * scale2;
                s[nb][3] = (c0 + 1 > row1g) ? -1e30f : s[nb][3] * scale2;
            }
        } else {
#pragma unroll
            for (int nb = 0; nb < 8; nb++)
#pragma unroll
                for (int i = 0; i < 4; i++) s[nb][i] *= scale2;
        }

        // ---- online softmax (fp32, base 2); P packed into registers ----
        float mx0 = -1e30f, mx1 = -1e30f;
#pragma unroll
        for (int nb = 0; nb < 8; nb++) {
            mx0 = fmaxf(mx0, fmaxf(s[nb][0], s[nb][1]));
            mx1 = fmaxf(mx1, fmaxf(s[nb][2], s[nb][3]));
        }
        mx0 = fmaxf(mx0, __shfl_xor_sync(0xffffffffu, mx0, 1));
        mx0 = fmaxf(mx0, __shfl_xor_sync(0xffffffffu, mx0, 2));
        mx1 = fmaxf(mx1, __shfl_xor_sync(0xffffffffu, mx1, 1));
        mx1 = fmaxf(mx1, __shfl_xor_sync(0xffffffffu, mx1, 2));
        float mn0 = fmaxf(m0, mx0), mn1 = fmaxf(m1, mx1);
        float alpha0 = ex2(m0 - mn0), alpha1 = ex2(m1 - mn1);
        float sum0 = 0.0f, sum1 = 0.0f;
        unsigned plo[8], phi[8];          // P a-fragment halves (row, row+8)
#pragma unroll
        for (int nb = 0; nb < 8; nb++) {
            float p00 = ex2(s[nb][0] - mn0);
            float p01 = ex2(s[nb][1] - mn0);
            float p10 = ex2(s[nb][2] - mn1);
            float p11 = ex2(s[nb][3] - mn1);
            sum0 += p00 + p01;
            sum1 += p10 + p11;
            __half2 hl = __floats2half2_rn(p00, p01);
            __half2 hh2 = __floats2half2_rn(p10, p11);
            plo[nb] = *reinterpret_cast<unsigned*>(&hl);
            phi[nb] = *reinterpret_cast<unsigned*>(&hh2);
        }
        sum0 += __shfl_xor_sync(0xffffffffu, sum0, 1);
        sum0 += __shfl_xor_sync(0xffffffffu, sum0, 2);
        sum1 += __shfl_xor_sync(0xffffffffu, sum1, 1);
        sum1 += __shfl_xor_sync(0xffffffffu, sum1, 2);
        l0 = l0 * alpha0 + sum0;
        l1 = l1 * alpha1 + sum1;
        m0 = mn0; m1 = mn1;
#pragma unroll
        for (int nb = 0; nb < 8; nb++) {
            o_acc[nb][0] *= alpha0; o_acc[nb][1] *= alpha0;
            o_acc[nb][2] *= alpha1; o_acc[nb][3] *= alpha1;
        }

        // ---- O += P V : P a-frags from registers, V b-frags via ldsm.trans ----
#pragma unroll
        for (int ks = 0; ks < 4; ks++) {
            unsigned pa[4];
            pa[0] = plo[2 * ks];
            pa[1] = phi[2 * ks];
            pa[2] = plo[2 * ks + 1];
            pa[3] = phi[2 * ks + 1];
#pragma unroll
            for (int p = 0; p < 4; p++) {
                unsigned vq[4];
                ldsm4t(vq, vb_ + ks * 16 * ASTRB + p * 32);
                mma_f16(o_acc[2 * p],     pa, vq[0], vq[2]);
                mma_f16(o_acc[2 * p + 1], pa, vq[1], vq[3]);
            }
        }
        asm volatile("cp.async.wait_group 0;\n");
    }

    // ---- write partial O (fp32, unnormalized) + (m, l) ----
    float* po = opart + (size_t)sp * MROWS * EE;
    const size_t grow0 = (size_t)(b * TT + row0g);
    const size_t grow1 = (size_t)(b * TT + row1g);
#pragma unroll
    for (int nb = 0; nb < 8; nb++) {
        int col = h * HD + nb * 8 + lm4 * 2;
        *reinterpret_cast<float2*>(po + grow0 * EE + col) =
            make_float2(o_acc[nb][0], o_acc[nb][1]);
        *reinterpret_cast<float2*>(po + grow1 * EE + col) =
            make_float2(o_acc[nb][2], o_acc[nb][3]);
    }
    if (lm4 == 0) {
        float* ml = mlpart + (size_t)sp * MROWS * NH * 2;
        ml[(grow0 * NH + h) * 2 + 0] = m0;
        ml[(grow0 * NH + h) * 2 + 1] = l0;
        ml[(grow1 * NH + h) * 2 + 0] = m1;
        ml[(grow1 * NH + h) * 2 + 1] = l1;
    }
}

// ---------------------------------------------------------------------------
// Split-K combine: attnh = (w0*O0 + w1*O1) / (w0*l0 + w1*l1), w = 2^(m - M).
// One block per row, 256 threads x 3 elements.
// ---------------------------------------------------------------------------
__global__ __launch_bounds__(256)
void attn_combine_kernel(const float* __restrict__ opart,
                         const float* __restrict__ mlpart,
                         __half* __restrict__ attnh) {
    const int row = blockIdx.x;
    const float* O0 = opart + (size_t)row * EE;
    const float* O1 = opart + (size_t)MROWS * EE + (size_t)row * EE;
    const float* ml0 = mlpart + (size_t)row * NH * 2;
    const float* ml1 = mlpart + (size_t)MROWS * NH * 2 + (size_t)row * NH * 2;
    __half* out = attnh + (size_t)row * EE;
#pragma unroll
    for (int i = 0; i < 3; i++) {
        int c = threadIdx.x + i * 256;
        int h = c >> 6;
        float m0 = ml0[h * 2], l0 = ml0[h * 2 + 1];
        float m1 = ml1[h * 2], l1 = ml1[h * 2 + 1];
        float M = fmaxf(m0, m1);
        float w0 = ex2(m0 - M), w1 = ex2(m1 - M);
        float d = w0 * l0 + w1 * l1;
        float v = (w0 * O0[c] + w1 * O1[c]) / d;
        out[c] = __float2half_rn(v);
    }
}

// ---------------------------------------------------------------------------
// Fused residual-add + LayerNorm over E=768. One block per row, 256 threads.
// ---------------------------------------------------------------------------
template <bool HALF_OUT>
__global__ __launch_bounds__(256)
void ln_kernel(const float* __restrict__ a, const float* __restrict__ res,
               const float* __restrict__ g, const float* __restrict__ bt,
               float* __restrict__ out, __half* __restrict__ outh) {
    const int row = blockIdx.x;
    const float* pa = a + (size_t)row * EE;
    const float* pr = res + (size_t)row * EE;
    float vloc[3];
    float s = 0.0f, ss = 0.0f;
#pragma unroll
    for (int i = 0; i < 3; i++) {
        int c = threadIdx.x + i * 256;
        float vv = pa[c] + pr[c];
        vloc[i] = vv;
        s += vv;
        ss += vv * vv;
    }
#pragma unroll
    for (int off = 16; off > 0; off >>= 1) {
        s  += __shfl_xor_sync(0xffffffffu, s, off);
        ss += __shfl_xor_sync(0xffffffffu, ss, off);
    }
    __shared__ float sred[16];
    __shared__ float smu, srstd;
    int w = threadIdx.x >> 5, lane = threadIdx.x & 31;
    if (lane == 0) { sred[w] = s; sred[8 + w] = ss; }
    __syncthreads();
    if (threadIdx.x == 0) {
        float S = 0.0f, SS = 0.0f;
#pragma unroll
        for (int i = 0; i < 8; i++) { S += sred[i]; SS += sred[8 + i]; }
        float mu = S * (1.0f / EE);
        float var = SS * (1.0f / EE) - mu * mu;
        smu = mu;
        srstd = rsqrtf(var + LN_EPS);
    }
    __syncthreads();
    float mu = smu, rstd = srstd;
    float* po = out + (size_t)row * EE;
    __half* ph = HALF_OUT ? (outh + (size_t)row * EE) : nullptr;
#pragma unroll
    for (int i = 0; i < 3; i++) {
        int c = threadIdx.x + i * 256;
        float vv = (vloc[i] - mu) * rstd * g[c] + bt[c];
        po[c] = vv;
        if (HALF_OUT) ph[c] = __float2half_rn(vv);
    }
}

// ---------------------------------------------------------------------------
// Launch
// ---------------------------------------------------------------------------
extern "C" void kernel_launch(void* const* d_in, const int* in_sizes, int n_in,
                              void* d_out, int out_size) {
    const float* x      = (const float*)d_in[0];
    const float* Wq     = (const float*)d_in[1];
    const float* Wk     = (const float*)d_in[2];
    const float* Wv     = (const float*)d_in[3];
    const float* proj_w = (const float*)d_in[4];
    const float* proj_b = (const float*)d_in[5];
    const float* ln1_g  = (const float*)d_in[6];
    const float* ln1_b  = (const float*)d_in[7];
    const float* w1     = (const float*)d_in[8];
    const float* b1     = (const float*)d_in[9];
    const float* w2     = (const float*)d_in[10];
    const float* b2     = (const float*)d_in[11];
    const float* ln2_g  = (const float*)d_in[12];
    const float* ln2_b  = (const float*)d_in[13];
    float* out = (float*)d_out;

    __half *qh, *kh, *vh, *attnh, *x1h, *xh, *hh;
    __half *wqh, *wkh, *wvh, *projh, *w1h, *w2h;
    float *tmp, *x1, *po, *ml;
    cudaGetSymbolAddress((void**)&qh,    g_qh);
    cudaGetSymbolAddress((void**)&kh,    g_kh);
    cudaGetSymbolAddress((void**)&vh,    g_vh);
    cudaGetSymbolAddress((void**)&attnh, g_attnh);
    cudaGetSymbolAddress((void**)&x1h,   g_x1h);
    cudaGetSymbolAddress((void**)&xh,    g_xh);
    cudaGetSymbolAddress((void**)&hh,    g_hh);
    cudaGetSymbolAddress((void**)&wqh,   g_wqh);
    cudaGetSymbolAddress((void**)&wkh,   g_wkh);
    cudaGetSymbolAddress((void**)&wvh,   g_wvh);
    cudaGetSymbolAddress((void**)&projh, g_projh);
    cudaGetSymbolAddress((void**)&w1h,   g_w1h);
    cudaGetSymbolAddress((void**)&w2h,   g_w2h);
    cudaGetSymbolAddress((void**)&tmp,   g_tmp);
    cudaGetSymbolAddress((void**)&x1,    g_x1);
    cudaGetSymbolAddress((void**)&po,    g_po);
    cudaGetSymbolAddress((void**)&ml,    g_ml);

    static bool attr_done = false;
    if (!attr_done) {
        cudaFuncSetAttribute((const void*)hgemm_kernel<false, false, 3, true, 128>,
                             cudaFuncAttributeMaxDynamicSharedMemorySize, GSMEM_OF(128));
        cudaFuncSetAttribute((const void*)hgemm_kernel<true, true, 1, true, 128>,
                             cudaFuncAttributeMaxDynamicSharedMemorySize, GSMEM_OF(128));
        cudaFuncSetAttribute((const void*)hgemm_kernel<true, false, 1, false, 64>,
                             cudaFuncAttributeMaxDynamicSharedMemorySize, GSMEM_OF(64));
        cudaFuncSetAttribute((const void*)attn_split_kernel,
                             cudaFuncAttributeMaxDynamicSharedMemorySize, ATT_SMEM);
        attr_done = true;
    }

    // ---- convert all GEMM operands to half (one launch) ----
    tohalf7_kernel<<<(CNTOT + 255) / 256, 256>>>(
        x, xh, Wq, wqh, Wk, wkh, Wv, wvh, proj_w, projh, w1, w1h, w2, w2h);

    dim3 gQKV(EE / 128, MROWS / 128, 3);    // (6, 32, 3)
    dim3 gE64(EE / 64, MROWS / 128, 1);     // (12, 32)
    dim3 gF(FFD / 128, MROWS / 128, 1);     // (24, 32)

    // Fused QKV projections
    hgemm_kernel<false, false, 3, true, 128><<<gQKV, 256, GSMEM_OF(128)>>>(
        xh, wqh, wkh, wvh, nullptr, qh, kh, vh, MROWS, EE, EE);

    // Causal attention: split-K halves + combine
    attn_split_kernel<<<dim3(TT / 128, BB * NH, 2), 256, ATT_SMEM>>>(
        qh, kh, vh, po, ml);
    attn_combine_kernel<<<MROWS, 256>>>(po, ml, attnh);

    // Output projection + bias (BN=64 for balance)
    hgemm_kernel<true, false, 1, false, 64><<<gE64, 256, GSMEM_OF(64)>>>(
        attnh, projh, projh, projh, proj_b, tmp, tmp, tmp, MROWS, EE, EE);
    ln_kernel<true><<<MROWS, 256>>>(tmp, x, ln1_g, ln1_b, x1, x1h);

    // FFN
    hgemm_kernel<true, true, 1, true, 128><<<gF, 256, GSMEM_OF(128)>>>(
        x1h, w1h, w1h, w1h, b1, hh, hh, hh, MROWS, FFD, EE);
    hgemm_kernel<true, false, 1, false, 64><<<gE64, 256, GSMEM_OF(64)>>>(
        hh, w2h, w2h, w2h, b2, tmp, tmp, tmp, MROWS, EE, FFD);
    ln_kernel<false><<<MROWS, 256>>>(tmp, x1, ln2_g, ln2_b, out, nullptr);
}